// round 5
// baseline (speedup 1.0000x reference)
#include <cuda_runtime.h>
#include <cuda_bf16.h>
#include <cstdint>

#define N_TOK 2048
#define NN (8LL * 2048 * 2048)

typedef __nv_bfloat16 bf16;

__device__ __forceinline__ uint32_t smem_to_u32(const void* p) {
    uint32_t a;
    asm("{ .reg .u64 t; cvta.to.shared.u64 t, %1; cvt.u32.u64 %0, t; }" : "=r"(a) : "l"(p));
    return a;
}

__device__ __forceinline__ void ldmatrix_x4(uint32_t& r0, uint32_t& r1, uint32_t& r2,
                                            uint32_t& r3, uint32_t addr) {
    asm volatile("ldmatrix.sync.aligned.m8n8.x4.shared.b16 {%0,%1,%2,%3}, [%4];"
                 : "=r"(r0), "=r"(r1), "=r"(r2), "=r"(r3) : "r"(addr));
}

__device__ __forceinline__ void mma16816(float c[4], const uint32_t a[4], const uint32_t b[2]) {
    asm volatile(
        "mma.sync.aligned.m16n8k16.row.col.f32.bf16.bf16.f32 "
        "{%0,%1,%2,%3}, {%4,%5,%6,%7}, {%8,%9}, {%0,%1,%2,%3};"
        : "+f"(c[0]), "+f"(c[1]), "+f"(c[2]), "+f"(c[3])
        : "r"(a[0]), "r"(a[1]), "r"(a[2]), "r"(a[3]), "r"(b[0]), "r"(b[1]));
}

#define CP_ASYNC_CG(smem_addr, gmem_ptr) \
    asm volatile("cp.async.cg.shared.global [%0], [%1], 16;" \
                 :: "r"(smem_addr), "l"(gmem_ptr))
#define CP_ASYNC_COMMIT() asm volatile("cp.async.commit_group;" ::: "memory")
#define CP_ASYNC_WAIT(n)  asm volatile("cp.async.wait_group %0;" :: "n"(n) : "memory")

// ============================ device scratch ============================
__device__ __align__(16) bf16 g_Xh[2048 * 1024];
__device__ __align__(16) bf16 g_Xl[2048 * 1024];
__device__ __align__(16) bf16 g_WTh[5242880];   // q1,k1,q2,k2 (1M each) + v1,v2 (512K each), [N,K]
__device__ __align__(16) bf16 g_WTl[5242880];
__device__ __align__(16) bf16 g_QKh[4][2048 * 1024];  // 0:q1 1:k1 2:q2 3:k2
__device__ __align__(16) bf16 g_QKl[4][2048 * 1024];
__device__ __align__(16) bf16 g_VTh[1024 * 2048];     // rows: mat*512 + vcol, cols: token
__device__ __align__(16) bf16 g_VTl[1024 * 2048];
__device__ __align__(16) float g_S1[NN];   // fp32 scores; after softmax: [hi bf16 x2048 | lo bf16 x2048] per row
__device__ __align__(16) float g_S2[NN];
__device__ __align__(16) float g_M1[2048LL * 2048];
__device__ __align__(16) float g_M2[2048LL * 2048];

// ============================ conversion kernels ============================
__global__ __launch_bounds__(256) void convx_kernel(const float* __restrict__ x) {
    int i = (blockIdx.x * 256 + threadIdx.x) * 4;
    float4 v = *(const float4*)(x + i);
    float vv[4] = {v.x, v.y, v.z, v.w};
    bf16 h[4], l[4];
#pragma unroll
    for (int j = 0; j < 4; j++) {
        h[j] = __float2bfloat16(vv[j]);
        l[j] = __float2bfloat16(vv[j] - __bfloat162float(h[j]));
    }
    *(uint2*)&g_Xh[i] = *(uint2*)h;
    *(uint2*)&g_Xl[i] = *(uint2*)l;
}

__global__ __launch_bounds__(256)
void convw_kernel(const float* __restrict__ w0, const float* __restrict__ w1,
                  const float* __restrict__ w2, const float* __restrict__ w3,
                  const float* __restrict__ w4, const float* __restrict__ w5) {
    int z = blockIdx.z;
    const float* W;
    int Ncols;
    long long base;
    switch (z) {
        case 0: W = w0; Ncols = 1024; base = 0; break;
        case 1: W = w1; Ncols = 1024; base = 1048576; break;
        case 2: W = w2; Ncols = 1024; base = 2097152; break;
        case 3: W = w3; Ncols = 1024; base = 3145728; break;
        case 4: W = w4; Ncols = 512;  base = 4194304; break;
        default:W = w5; Ncols = 512;  base = 4718592; break;
    }
    int bn = blockIdx.x * 32, bk = blockIdx.y * 32;
    if (bn >= Ncols) return;
    __shared__ float t[32][33];
#pragma unroll
    for (int i = threadIdx.y; i < 32; i += 8)
        t[i][threadIdx.x] = W[(long long)(bk + i) * Ncols + bn + threadIdx.x];
    __syncthreads();
#pragma unroll
    for (int i = threadIdx.y; i < 32; i += 8) {
        float v = t[threadIdx.x][i];
        bf16 hh = __float2bfloat16(v);
        long long o = base + (long long)(bn + i) * 1024 + bk + threadIdx.x;
        g_WTh[o] = hh;
        g_WTl[o] = __float2bfloat16(v - __bfloat162float(hh));
    }
}

__global__ void mask_transpose_kernel(const float* __restrict__ G1,
                                      const float* __restrict__ G2) {
    __shared__ float t1[32][33];
    __shared__ float t2[32][33];
    int bx = blockIdx.x * 32;
    int by = blockIdx.y * 32;
    int x = bx + threadIdx.x;
#pragma unroll
    for (int i = threadIdx.y; i < 32; i += 8) {
        t1[i][threadIdx.x] = G1[(long long)(by + i) * N_TOK + x];
        t2[i][threadIdx.x] = G2[(long long)(by + i) * N_TOK + x];
    }
    __syncthreads();
    int ox = by + threadIdx.x;
#pragma unroll
    for (int i = threadIdx.y; i < 32; i += 8) {
        g_M1[(long long)(bx + i) * N_TOK + ox] = (t1[threadIdx.x][i] - 1.f) * 10000.f;
        g_M2[(long long)(bx + i) * N_TOK + ox] = (t2[threadIdx.x][i] - 1.f) * 10000.f;
    }
}

// ============================ pipelined mma.sync GEMM body ============================
template <int BN, int WM, int WN>
__device__ __forceinline__ void gemm_mma(
    const bf16* __restrict__ aH, const bf16* __restrict__ aL, int lda,
    const bf16* __restrict__ bH, const bf16* __restrict__ bL, int ldb,
    int K, float acc[128 / (WM * 16)][4][4])
{
    constexpr int MI = 128 / (WM * 16);
    constexpr int OFF_AL = 10240;
    constexpr int OFF_BH = 20480;
    constexpr int OFF_BL = 20480 + BN * 80;
    constexpr int STG = 20480 + BN * 160;
    extern __shared__ __align__(16) char sm[];
    const uint32_t smb = smem_to_u32(sm);
    const int tid = threadIdx.x;
    const int wid = tid >> 5, lane = tid & 31;
    const int wm = (wid / WN) * (MI * 16);
    const int wn = (wid % WN) * 32;
    const int a_row = wm + (lane & 7) + ((lane >> 3) & 1) * 8;
    const int a_cofs = (lane >> 4) * 8;
    const int b_row = wn + (lane & 7) + ((lane >> 4) & 1) * 8;
    const int b_cofs = ((lane >> 3) & 1) * 8;

    const int r_cp = tid >> 2;          // 0..63
    const int c_cp = (tid & 3) * 8;     // 0,8,16,24
    const int NC = K >> 5;

    auto issue_stage = [&](int ic) {
        const uint32_t sb = smb + (uint32_t)(ic & 1) * STG;
        const int k0 = ic * 32;
#pragma unroll
        for (int i = 0; i < 2; i++) {
            int r = r_cp + i * 64;
            uint32_t so = (uint32_t)(r * 80 + c_cp * 2);
            CP_ASYNC_CG(sb + so, aH + r * lda + k0 + c_cp);
            CP_ASYNC_CG(sb + OFF_AL + so, aL + r * lda + k0 + c_cp);
        }
#pragma unroll
        for (int i = 0; i < BN / 64; i++) {
            int r = r_cp + i * 64;
            uint32_t so = (uint32_t)(r * 80 + c_cp * 2);
            CP_ASYNC_CG(sb + OFF_BH + so, bH + r * ldb + k0 + c_cp);
            CP_ASYNC_CG(sb + OFF_BL + so, bL + r * ldb + k0 + c_cp);
        }
        CP_ASYNC_COMMIT();
    };

    issue_stage(0);
    for (int ic = 0; ic < NC; ic++) {
        if (ic + 1 < NC) { issue_stage(ic + 1); CP_ASYNC_WAIT(1); }
        else             { CP_ASYNC_WAIT(0); }
        __syncthreads();
        const uint32_t sb = smb + (uint32_t)(ic & 1) * STG;
#pragma unroll
        for (int ks = 0; ks < 32; ks += 16) {
            uint32_t ah[MI][4], al[MI][4], bh[4][2], bl[4][2];
#pragma unroll
            for (int mi = 0; mi < MI; mi++) {
                uint32_t off = (uint32_t)(((a_row + mi * 16) * 40 + ks + a_cofs) * 2);
                ldmatrix_x4(ah[mi][0], ah[mi][1], ah[mi][2], ah[mi][3], sb + off);
                ldmatrix_x4(al[mi][0], al[mi][1], al[mi][2], al[mi][3], sb + OFF_AL + off);
            }
#pragma unroll
            for (int nj = 0; nj < 2; nj++) {
                uint32_t off = (uint32_t)(((b_row + nj * 16) * 40 + ks + b_cofs) * 2);
                ldmatrix_x4(bh[nj * 2][0], bh[nj * 2][1], bh[nj * 2 + 1][0], bh[nj * 2 + 1][1],
                            sb + OFF_BH + off);
                ldmatrix_x4(bl[nj * 2][0], bl[nj * 2][1], bl[nj * 2 + 1][0], bl[nj * 2 + 1][1],
                            sb + OFF_BL + off);
            }
#pragma unroll
            for (int mi = 0; mi < MI; mi++)
#pragma unroll
                for (int ni = 0; ni < 4; ni++) {
                    mma16816(acc[mi][ni], ah[mi], bh[ni]);
                    mma16816(acc[mi][ni], ah[mi], bl[ni]);
                    mma16816(acc[mi][ni], al[mi], bh[ni]);
                }
        }
        __syncthreads();
    }
}

// ============================ stage 1: projections ============================
__global__ __launch_bounds__(256, 2)
void proj_mma_kernel(const float* __restrict__ bq1, const float* __restrict__ bk1,
                     const float* __restrict__ bv1, const float* __restrict__ bq2,
                     const float* __restrict__ bk2, const float* __restrict__ bv2)
{
    const int cb = blockIdx.x;
    const int bm = blockIdx.y * 128;
    const bf16 *bH, *bL;
    const float* bias;
    int r, bnl;
    if (cb < 32) {
        r = cb >> 3; bnl = (cb & 7) * 128;
        long long wo = (long long)r * 1048576 + (long long)bnl * 1024;
        bH = g_WTh + wo; bL = g_WTl + wo;
        bias = (r == 0) ? bq1 : (r == 1) ? bk1 : (r == 2) ? bq2 : bk2;
    } else {
        r = (cb - 32) >> 2; bnl = ((cb - 32) & 3) * 128;
        long long wo = 4194304LL + (long long)r * 524288 + (long long)bnl * 1024;
        bH = g_WTh + wo; bL = g_WTl + wo;
        bias = r ? bv2 : bv1;
    }
    float acc[4][4][4];
#pragma unroll
    for (int a = 0; a < 4; a++)
#pragma unroll
        for (int b = 0; b < 4; b++)
#pragma unroll
            for (int c = 0; c < 4; c++) acc[a][b][c] = 0.f;

    gemm_mma<128, 2, 4>(g_Xh + (long long)bm * 1024, g_Xl + (long long)bm * 1024, 1024,
                        bH, bL, 1024, 1024, acc);

    const int wid = threadIdx.x >> 5, lane = threadIdx.x & 31;
    const int g = lane >> 2, t = lane & 3;
    const int wm = (wid >> 2) * 64, wn = (wid & 3) * 32;
#pragma unroll
    for (int mi = 0; mi < 4; mi++) {
        int m0 = bm + wm + mi * 16 + g;
#pragma unroll
        for (int ni = 0; ni < 4; ni++) {
            int col = bnl + wn + ni * 8 + 2 * t;
            float b0 = bias[col], b1 = bias[col + 1];
            float v00 = acc[mi][ni][0] + b0, v01 = acc[mi][ni][1] + b1;
            float v10 = acc[mi][ni][2] + b0, v11 = acc[mi][ni][3] + b1;
            bf16 h00 = __float2bfloat16(v00), h01 = __float2bfloat16(v01);
            bf16 h10 = __float2bfloat16(v10), h11 = __float2bfloat16(v11);
            bf16 l00 = __float2bfloat16(v00 - __bfloat162float(h00));
            bf16 l01 = __float2bfloat16(v01 - __bfloat162float(h01));
            bf16 l10 = __float2bfloat16(v10 - __bfloat162float(h10));
            bf16 l11 = __float2bfloat16(v11 - __bfloat162float(h11));
            if (cb < 32) {
                long long o0 = (long long)m0 * 1024 + col;
                long long o1 = (long long)(m0 + 8) * 1024 + col;
                *(__nv_bfloat162*)&g_QKh[r][o0] = __nv_bfloat162(h00, h01);
                *(__nv_bfloat162*)&g_QKl[r][o0] = __nv_bfloat162(l00, l01);
                *(__nv_bfloat162*)&g_QKh[r][o1] = __nv_bfloat162(h10, h11);
                *(__nv_bfloat162*)&g_QKl[r][o1] = __nv_bfloat162(l10, l11);
            } else {
                int c0 = r * 512 + col, c1 = c0 + 1;
                g_VTh[(long long)c0 * 2048 + m0] = h00;
                g_VTh[(long long)c1 * 2048 + m0] = h01;
                g_VTh[(long long)c0 * 2048 + m0 + 8] = h10;
                g_VTh[(long long)c1 * 2048 + m0 + 8] = h11;
                g_VTl[(long long)c0 * 2048 + m0] = l00;
                g_VTl[(long long)c1 * 2048 + m0] = l01;
                g_VTl[(long long)c0 * 2048 + m0 + 8] = l10;
                g_VTl[(long long)c1 * 2048 + m0 + 8] = l11;
            }
        }
    }
}

// ============================ stage 2: scores ============================
__global__ __launch_bounds__(256, 2)
void score_mma_kernel(float scale)
{
    const int z = blockIdx.z, mat = z >> 3, h = z & 7;
    const int bm = blockIdx.y * 128, bn = blockIdx.x * 128;
    const bf16* qh = g_QKh[mat * 2] + (long long)bm * 1024 + h * 128;
    const bf16* ql = g_QKl[mat * 2] + (long long)bm * 1024 + h * 128;
    const bf16* kh = g_QKh[mat * 2 + 1] + (long long)bn * 1024 + h * 128;
    const bf16* kl = g_QKl[mat * 2 + 1] + (long long)bn * 1024 + h * 128;

    float acc[4][4][4];
#pragma unroll
    for (int a = 0; a < 4; a++)
#pragma unroll
        for (int b = 0; b < 4; b++)
#pragma unroll
            for (int c = 0; c < 4; c++) acc[a][b][c] = 0.f;

    gemm_mma<128, 2, 4>(qh, ql, 1024, kh, kl, 1024, 128, acc);

    float* S = (mat ? g_S2 : g_S1) + (long long)h * N_TOK * N_TOK;
    const int wid = threadIdx.x >> 5, lane = threadIdx.x & 31;
    const int g = lane >> 2, t = lane & 3;
    const int wm = (wid >> 2) * 64, wn = (wid & 3) * 32;
#pragma unroll
    for (int mi = 0; mi < 4; mi++) {
        int m0 = bm + wm + mi * 16 + g;
#pragma unroll
        for (int ni = 0; ni < 4; ni++) {
            int n0 = bn + wn + ni * 8 + 2 * t;
            float2 r0 = make_float2(acc[mi][ni][0] * scale, acc[mi][ni][1] * scale);
            float2 r1 = make_float2(acc[mi][ni][2] * scale, acc[mi][ni][3] * scale);
            *(float2*)(S + (long long)m0 * N_TOK + n0) = r0;
            *(float2*)(S + (long long)(m0 + 8) * N_TOK + n0) = r1;
        }
    }
}

// ============================ stage 3: dual gathered softmax (all heads per CTA) ============================
__device__ __forceinline__ float warpRedMax(float v) {
#pragma unroll
    for (int o = 16; o > 0; o >>= 1) v = fmaxf(v, __shfl_xor_sync(0xffffffffu, v, o));
    return v;
}
__device__ __forceinline__ float warpRedSum(float v) {
#pragma unroll
    for (int o = 16; o > 0; o >>= 1) v += __shfl_xor_sync(0xffffffffu, v, o);
    return v;
}

// dynamic smem layout (floats/ints, 2048 each):
// sh1[0:2048] sh2[2048:4096] m1[4096:6144] m2[6144:8192] c2n[8192:10240] n2c[10240:12288]
// red: 32 floats at [12288:12320]
__global__ __launch_bounds__(256)
void softmax_gather_kernel(const int* __restrict__ n2c, const int* __restrict__ c2n)
{
    extern __shared__ __align__(16) float smf[];
    float* sh1 = smf;
    float* sh2 = smf + 2048;
    float* sm1 = smf + 4096;
    float* sm2 = smf + 6144;
    int*   si1 = (int*)(smf + 8192);    // c2n row
    int*   si2 = (int*)(smf + 10240);   // n2c row
    float* red = smf + 12288;

    const int n = blockIdx.x;
    const int tid = threadIdx.x;
    const int lane = tid & 31, wid = tid >> 5;
    const int mb = tid * 8;   // this thread owns columns [mb, mb+8)

    // one-time loads: masks + indices for row n (head-invariant)
    {
        const float4* m1g = (const float4*)(g_M1 + (long long)n * N_TOK);
        const float4* m2g = (const float4*)(g_M2 + (long long)n * N_TOK);
        const int4* c2ng = (const int4*)(c2n + (long long)n * N_TOK);
        const int4* n2cg = (const int4*)(n2c + (long long)n * N_TOK);
#pragma unroll
        for (int i = 0; i < 2; i++) {
            int v4 = tid + i * 256;
            *(float4*)&sm1[v4 * 4] = m1g[v4];
            *(float4*)&sm2[v4 * 4] = m2g[v4];
            *(int4*)&si1[v4 * 4] = c2ng[v4];
            *(int4*)&si2[v4 * 4] = n2cg[v4];
        }
    }

    for (int h = 0; h < 8; h++) {
        float* s1row = g_S1 + ((long long)h * N_TOK + n) * N_TOK;
        float* s2row = g_S2 + ((long long)h * N_TOK + n) * N_TOK;
        __syncthreads();   // smem rows free to overwrite (and masks ready on h=0)
        {
            const float4* s1g = (const float4*)s1row;
            const float4* s2g = (const float4*)s2row;
#pragma unroll
            for (int i = 0; i < 2; i++) {
                int v4 = tid + i * 256;
                *(float4*)&sh1[v4 * 4] = s1g[v4];
                *(float4*)&sh2[v4 * 4] = s2g[v4];
            }
        }
        __syncthreads();

        float z1[8], z2[8];
        float mx1 = -1e30f, mx2 = -1e30f;
#pragma unroll
        for (int i = 0; i < 8; i++) {
            int m = mb + i;
            z1[i] = sh1[m] + sh2[si1[m]] + sm1[m];
            z2[i] = sh2[m] + sh1[si2[m]] + sm2[m];
            mx1 = fmaxf(mx1, z1[i]);
            mx2 = fmaxf(mx2, z2[i]);
        }
        mx1 = warpRedMax(mx1);
        mx2 = warpRedMax(mx2);
        if (lane == 0) { red[wid] = mx1; red[wid + 8] = mx2; }
        __syncthreads();
        if (wid == 0) {
            float a = (lane < 8) ? red[lane] : -1e30f;
            float b = (lane < 8) ? red[lane + 8] : -1e30f;
            a = warpRedMax(a);
            b = warpRedMax(b);
            if (lane == 0) { red[16] = a; red[17] = b; }
        }
        __syncthreads();
        mx1 = red[16];
        mx2 = red[17];

        float sum1 = 0.f, sum2 = 0.f;
#pragma unroll
        for (int i = 0; i < 8; i++) {
            z1[i] = __expf(z1[i] - mx1);
            z2[i] = __expf(z2[i] - mx2);
            sum1 += z1[i];
            sum2 += z2[i];
        }
        sum1 = warpRedSum(sum1);
        sum2 = warpRedSum(sum2);
        if (lane == 0) { red[wid] = sum1; red[wid + 8] = sum2; }
        __syncthreads();
        if (wid == 0) {
            float a = (lane < 8) ? red[lane] : 0.f;
            float b = (lane < 8) ? red[lane + 8] : 0.f;
            a = warpRedSum(a);
            b = warpRedSum(b);
            if (lane == 0) { red[16] = a; red[17] = b; }
        }
        __syncthreads();
        const float inv1 = 1.f / red[16];
        const float inv2 = 1.f / red[17];

        bf16 h1[8], l1[8], h2[8], l2[8];
#pragma unroll
        for (int i = 0; i < 8; i++) {
            float p1 = z1[i] * inv1;
            float p2 = z2[i] * inv2;
            h1[i] = __float2bfloat16(p1);
            l1[i] = __float2bfloat16(p1 - __bfloat162float(h1[i]));
            h2[i] = __float2bfloat16(p2);
            l2[i] = __float2bfloat16(p2 - __bfloat162float(h2[i]));
        }
        bf16* a1 = reinterpret_cast<bf16*>(s1row);
        bf16* a2 = reinterpret_cast<bf16*>(s2row);
        *(uint4*)&a1[mb]        = *(uint4*)h1;
        *(uint4*)&a1[2048 + mb] = *(uint4*)l1;
        *(uint4*)&a2[mb]        = *(uint4*)h2;
        *(uint4*)&a2[2048 + mb] = *(uint4*)l2;
    }
}

// ============================ stage 4: AV + concat ============================
__global__ __launch_bounds__(256, 2)
void av_mma_kernel(float* __restrict__ out)
{
    const int z = blockIdx.z, mat = z >> 3, h = z & 7;
    const int bm = blockIdx.y * 128;
    const bf16* Ab = reinterpret_cast<const bf16*>(mat ? g_S2 : g_S1);
    const bf16* aH = Ab + ((long long)h * N_TOK + bm) * 4096;
    const bf16* aL = aH + 2048;
    const bf16* bH = g_VTh + (long long)(mat * 512 + h * 64) * 2048;
    const bf16* bL = g_VTl + (long long)(mat * 512 + h * 64) * 2048;

    float acc[2][4][4];
#pragma unroll
    for (int a = 0; a < 2; a++)
#pragma unroll
        for (int b = 0; b < 4; b++)
#pragma unroll
            for (int c = 0; c < 4; c++) acc[a][b][c] = 0.f;

    gemm_mma<64, 4, 2>(aH, aL, 4096, bH, bL, 2048, 2048, acc);

    const int wid = threadIdx.x >> 5, lane = threadIdx.x & 31;
    const int g = lane >> 2, t = lane & 3;
    const int wm = (wid >> 1) * 32, wn = (wid & 1) * 32;
    const int cbase = mat * 512 + h * 64;
#pragma unroll
    for (int mi = 0; mi < 2; mi++) {
        int m0 = bm + wm + mi * 16 + g;
#pragma unroll
        for (int ni = 0; ni < 4; ni++) {
            int col = cbase + wn + ni * 8 + 2 * t;
            *(float2*)(out + (long long)m0 * 1024 + col) =
                make_float2(acc[mi][ni][0], acc[mi][ni][1]);
            *(float2*)(out + (long long)(m0 + 8) * 1024 + col) =
                make_float2(acc[mi][ni][2], acc[mi][ni][3]);
        }
    }
}

// ============================ launch ============================
extern "C" void kernel_launch(void* const* d_in, const int* in_sizes, int n_in,
                              void* d_out, int out_size)
{
    const float* x   = (const float*)d_in[0];
    const float* fst = (const float*)d_in[1];
    const float* sec = (const float*)d_in[2];
    const int*   n2c = (const int*)d_in[3];
    const int*   c2n = (const int*)d_in[4];
    const float* Wq1 = (const float*)d_in[5];
    const float* bq1 = (const float*)d_in[6];
    const float* Wk1 = (const float*)d_in[7];
    const float* bk1 = (const float*)d_in[8];
    const float* Wv1 = (const float*)d_in[9];
    const float* bv1 = (const float*)d_in[10];
    const float* Wq2 = (const float*)d_in[11];
    const float* bq2 = (const float*)d_in[12];
    const float* Wk2 = (const float*)d_in[13];
    const float* bk2 = (const float*)d_in[14];
    const float* Wv2 = (const float*)d_in[15];
    const float* bv2 = (const float*)d_in[16];
    float* out = (float*)d_out;

    static bool attr_set = false;
    if (!attr_set) {
        cudaFuncSetAttribute(proj_mma_kernel, cudaFuncAttributeMaxDynamicSharedMemorySize, 81920);
        cudaFuncSetAttribute(score_mma_kernel, cudaFuncAttributeMaxDynamicSharedMemorySize, 81920);
        cudaFuncSetAttribute(av_mma_kernel, cudaFuncAttributeMaxDynamicSharedMemorySize, 61440);
        cudaFuncSetAttribute(softmax_gather_kernel, cudaFuncAttributeMaxDynamicSharedMemorySize, 49408);
        attr_set = true;
    }

    // stage 0: transposed masks + bf16 split conversions
    mask_transpose_kernel<<<dim3(64, 64), dim3(32, 8)>>>(fst, sec);
    convx_kernel<<<2048, 256>>>(x);
    convw_kernel<<<dim3(32, 32, 6), dim3(32, 8)>>>(Wq1, Wk1, Wq2, Wk2, Wv1, Wv2);

    // stage 1: projections (640 CTAs, pipelined mma.sync)
    proj_mma_kernel<<<dim3(40, 16), 256, 81920>>>(bq1, bk1, bv1, bq2, bk2, bv2);

    // stage 2: scores (4096 CTAs)
    const float scale = 0.08838834764831845f;  // 1/sqrt(128)
    score_mma_kernel<<<dim3(16, 16, 16), 256, 81920>>>(scale);

    // stage 3: gathered dual softmax, all 8 heads per CTA -> bf16-split attention, in place
    softmax_gather_kernel<<<2048, 256, 49408>>>(n2c, c2n);

    // stage 4: AV + concat (256 CTAs)
    av_mma_kernel<<<dim3(1, 16, 16), 256, 61440>>>(out);
}

// round 6
// speedup vs baseline: 1.5448x; 1.5448x over previous
#include <cuda_runtime.h>
#include <cuda_bf16.h>
#include <cstdint>

#define N_TOK 2048
#define NN (8LL * 2048 * 2048)

typedef __nv_bfloat16 bf16;

__device__ __forceinline__ uint32_t smem_to_u32(const void* p) {
    uint32_t a;
    asm("{ .reg .u64 t; cvta.to.shared.u64 t, %1; cvt.u32.u64 %0, t; }" : "=r"(a) : "l"(p));
    return a;
}

__device__ __forceinline__ void ldmatrix_x4(uint32_t& r0, uint32_t& r1, uint32_t& r2,
                                            uint32_t& r3, uint32_t addr) {
    asm volatile("ldmatrix.sync.aligned.m8n8.x4.shared.b16 {%0,%1,%2,%3}, [%4];"
                 : "=r"(r0), "=r"(r1), "=r"(r2), "=r"(r3) : "r"(addr));
}

__device__ __forceinline__ void mma16816(float c[4], const uint32_t a[4], const uint32_t b[2]) {
    asm volatile(
        "mma.sync.aligned.m16n8k16.row.col.f32.bf16.bf16.f32 "
        "{%0,%1,%2,%3}, {%4,%5,%6,%7}, {%8,%9}, {%0,%1,%2,%3};"
        : "+f"(c[0]), "+f"(c[1]), "+f"(c[2]), "+f"(c[3])
        : "r"(a[0]), "r"(a[1]), "r"(a[2]), "r"(a[3]), "r"(b[0]), "r"(b[1]));
}

#define CP_ASYNC_CG(smem_addr, gmem_ptr) \
    asm volatile("cp.async.cg.shared.global [%0], [%1], 16;" \
                 :: "r"(smem_addr), "l"(gmem_ptr))
#define CP_ASYNC_COMMIT() asm volatile("cp.async.commit_group;" ::: "memory")
#define CP_ASYNC_WAIT(n)  asm volatile("cp.async.wait_group %0;" :: "n"(n) : "memory")

// ============================ device scratch ============================
__device__ __align__(16) bf16 g_Xh[2048 * 1024];
__device__ __align__(16) bf16 g_Xl[2048 * 1024];
__device__ __align__(16) bf16 g_WTh[5242880];   // q1,k1,q2,k2 (1M each) + v1,v2 (512K each), [N,K]
__device__ __align__(16) bf16 g_WTl[5242880];
__device__ __align__(16) bf16 g_QKh[4][2048 * 1024];  // 0:q1 1:k1 2:q2 3:k2
__device__ __align__(16) bf16 g_QKl[4][2048 * 1024];
__device__ __align__(16) bf16 g_VTh[1024 * 2048];     // rows: mat*512 + vcol, cols: token
__device__ __align__(16) bf16 g_VTl[1024 * 2048];
__device__ __align__(16) float g_S1[NN];   // fp32 scores; after softmax: [hi bf16 x2048 | lo bf16 x2048] per row
__device__ __align__(16) float g_S2[NN];
__device__ __align__(16) bf16 g_M1[2048LL * 2048];           // transposed masks, bf16 (exact: {0,-1e4})
__device__ __align__(16) bf16 g_M2[2048LL * 2048];
__device__ __align__(16) unsigned short g_I1[2048LL * 2048]; // c2n as u16
__device__ __align__(16) unsigned short g_I2[2048LL * 2048]; // n2c as u16

// ============================ conversion kernels ============================
__global__ __launch_bounds__(256) void convx_kernel(const float* __restrict__ x) {
    int i = (blockIdx.x * 256 + threadIdx.x) * 4;
    float4 v = *(const float4*)(x + i);
    float vv[4] = {v.x, v.y, v.z, v.w};
    bf16 h[4], l[4];
#pragma unroll
    for (int j = 0; j < 4; j++) {
        h[j] = __float2bfloat16(vv[j]);
        l[j] = __float2bfloat16(vv[j] - __bfloat162float(h[j]));
    }
    *(uint2*)&g_Xh[i] = *(uint2*)h;
    *(uint2*)&g_Xl[i] = *(uint2*)l;
}

__global__ __launch_bounds__(256)
void convw_kernel(const float* __restrict__ w0, const float* __restrict__ w1,
                  const float* __restrict__ w2, const float* __restrict__ w3,
                  const float* __restrict__ w4, const float* __restrict__ w5) {
    int z = blockIdx.z;
    const float* W;
    int Ncols;
    long long base;
    switch (z) {
        case 0: W = w0; Ncols = 1024; base = 0; break;
        case 1: W = w1; Ncols = 1024; base = 1048576; break;
        case 2: W = w2; Ncols = 1024; base = 2097152; break;
        case 3: W = w3; Ncols = 1024; base = 3145728; break;
        case 4: W = w4; Ncols = 512;  base = 4194304; break;
        default:W = w5; Ncols = 512;  base = 4718592; break;
    }
    int bn = blockIdx.x * 32, bk = blockIdx.y * 32;
    if (bn >= Ncols) return;
    __shared__ float t[32][33];
#pragma unroll
    for (int i = threadIdx.y; i < 32; i += 8)
        t[i][threadIdx.x] = W[(long long)(bk + i) * Ncols + bn + threadIdx.x];
    __syncthreads();
#pragma unroll
    for (int i = threadIdx.y; i < 32; i += 8) {
        float v = t[threadIdx.x][i];
        bf16 hh = __float2bfloat16(v);
        long long o = base + (long long)(bn + i) * 1024 + bk + threadIdx.x;
        g_WTh[o] = hh;
        g_WTl[o] = __float2bfloat16(v - __bfloat162float(hh));
    }
}

// masks transposed -> bf16 (values {0,-1e4} exact)
__global__ void mask_transpose_kernel(const float* __restrict__ G1,
                                      const float* __restrict__ G2) {
    __shared__ float t1[32][33];
    __shared__ float t2[32][33];
    int bx = blockIdx.x * 32;
    int by = blockIdx.y * 32;
    int x = bx + threadIdx.x;
#pragma unroll
    for (int i = threadIdx.y; i < 32; i += 8) {
        t1[i][threadIdx.x] = G1[(long long)(by + i) * N_TOK + x];
        t2[i][threadIdx.x] = G2[(long long)(by + i) * N_TOK + x];
    }
    __syncthreads();
    int ox = by + threadIdx.x;
#pragma unroll
    for (int i = threadIdx.y; i < 32; i += 8) {
        g_M1[(long long)(bx + i) * N_TOK + ox] =
            __float2bfloat16((t1[threadIdx.x][i] - 1.f) * 10000.f);
        g_M2[(long long)(bx + i) * N_TOK + ox] =
            __float2bfloat16((t2[threadIdx.x][i] - 1.f) * 10000.f);
    }
}

// indices int32 -> uint16
__global__ __launch_bounds__(256)
void convidx_kernel(const int* __restrict__ c2n, const int* __restrict__ n2c) {
    long long i = ((long long)blockIdx.x * 256 + threadIdx.x) * 4;
    int4 a = *(const int4*)(c2n + i);
    int4 b = *(const int4*)(n2c + i);
    ushort4 ua = make_ushort4((unsigned short)a.x, (unsigned short)a.y,
                              (unsigned short)a.z, (unsigned short)a.w);
    ushort4 ub = make_ushort4((unsigned short)b.x, (unsigned short)b.y,
                              (unsigned short)b.z, (unsigned short)b.w);
    *(ushort4*)&g_I1[i] = ua;
    *(ushort4*)&g_I2[i] = ub;
}

// ============================ pipelined mma.sync GEMM body ============================
template <int BN, int WM, int WN>
__device__ __forceinline__ void gemm_mma(
    const bf16* __restrict__ aH, const bf16* __restrict__ aL, int lda,
    const bf16* __restrict__ bH, const bf16* __restrict__ bL, int ldb,
    int K, float acc[128 / (WM * 16)][4][4])
{
    constexpr int MI = 128 / (WM * 16);
    constexpr int OFF_AL = 10240;
    constexpr int OFF_BH = 20480;
    constexpr int OFF_BL = 20480 + BN * 80;
    constexpr int STG = 20480 + BN * 160;
    extern __shared__ __align__(16) char sm[];
    const uint32_t smb = smem_to_u32(sm);
    const int tid = threadIdx.x;
    const int wid = tid >> 5, lane = tid & 31;
    const int wm = (wid / WN) * (MI * 16);
    const int wn = (wid % WN) * 32;
    const int a_row = wm + (lane & 7) + ((lane >> 3) & 1) * 8;
    const int a_cofs = (lane >> 4) * 8;
    const int b_row = wn + (lane & 7) + ((lane >> 4) & 1) * 8;
    const int b_cofs = ((lane >> 3) & 1) * 8;

    const int r_cp = tid >> 2;          // 0..63
    const int c_cp = (tid & 3) * 8;     // 0,8,16,24
    const int NC = K >> 5;

    auto issue_stage = [&](int ic) {
        const uint32_t sb = smb + (uint32_t)(ic & 1) * STG;
        const int k0 = ic * 32;
#pragma unroll
        for (int i = 0; i < 2; i++) {
            int r = r_cp + i * 64;
            uint32_t so = (uint32_t)(r * 80 + c_cp * 2);
            CP_ASYNC_CG(sb + so, aH + r * lda + k0 + c_cp);
            CP_ASYNC_CG(sb + OFF_AL + so, aL + r * lda + k0 + c_cp);
        }
#pragma unroll
        for (int i = 0; i < BN / 64; i++) {
            int r = r_cp + i * 64;
            uint32_t so = (uint32_t)(r * 80 + c_cp * 2);
            CP_ASYNC_CG(sb + OFF_BH + so, bH + r * ldb + k0 + c_cp);
            CP_ASYNC_CG(sb + OFF_BL + so, bL + r * ldb + k0 + c_cp);
        }
        CP_ASYNC_COMMIT();
    };

    issue_stage(0);
    for (int ic = 0; ic < NC; ic++) {
        if (ic + 1 < NC) { issue_stage(ic + 1); CP_ASYNC_WAIT(1); }
        else             { CP_ASYNC_WAIT(0); }
        __syncthreads();
        const uint32_t sb = smb + (uint32_t)(ic & 1) * STG;
#pragma unroll
        for (int ks = 0; ks < 32; ks += 16) {
            uint32_t ah[MI][4], al[MI][4], bh[4][2], bl[4][2];
#pragma unroll
            for (int mi = 0; mi < MI; mi++) {
                uint32_t off = (uint32_t)(((a_row + mi * 16) * 40 + ks + a_cofs) * 2);
                ldmatrix_x4(ah[mi][0], ah[mi][1], ah[mi][2], ah[mi][3], sb + off);
                ldmatrix_x4(al[mi][0], al[mi][1], al[mi][2], al[mi][3], sb + OFF_AL + off);
            }
#pragma unroll
            for (int nj = 0; nj < 2; nj++) {
                uint32_t off = (uint32_t)(((b_row + nj * 16) * 40 + ks + b_cofs) * 2);
                ldmatrix_x4(bh[nj * 2][0], bh[nj * 2][1], bh[nj * 2 + 1][0], bh[nj * 2 + 1][1],
                            sb + OFF_BH + off);
                ldmatrix_x4(bl[nj * 2][0], bl[nj * 2][1], bl[nj * 2 + 1][0], bl[nj * 2 + 1][1],
                            sb + OFF_BL + off);
            }
#pragma unroll
            for (int mi = 0; mi < MI; mi++)
#pragma unroll
                for (int ni = 0; ni < 4; ni++) {
                    mma16816(acc[mi][ni], ah[mi], bh[ni]);
                    mma16816(acc[mi][ni], ah[mi], bl[ni]);
                    mma16816(acc[mi][ni], al[mi], bh[ni]);
                }
        }
        __syncthreads();
    }
}

// ============================ stage 1: projections ============================
__global__ __launch_bounds__(256, 2)
void proj_mma_kernel(const float* __restrict__ bq1, const float* __restrict__ bk1,
                     const float* __restrict__ bv1, const float* __restrict__ bq2,
                     const float* __restrict__ bk2, const float* __restrict__ bv2)
{
    const int cb = blockIdx.x;
    const int bm = blockIdx.y * 128;
    const bf16 *bH, *bL;
    const float* bias;
    int r, bnl;
    if (cb < 32) {
        r = cb >> 3; bnl = (cb & 7) * 128;
        long long wo = (long long)r * 1048576 + (long long)bnl * 1024;
        bH = g_WTh + wo; bL = g_WTl + wo;
        bias = (r == 0) ? bq1 : (r == 1) ? bk1 : (r == 2) ? bq2 : bk2;
    } else {
        r = (cb - 32) >> 2; bnl = ((cb - 32) & 3) * 128;
        long long wo = 4194304LL + (long long)r * 524288 + (long long)bnl * 1024;
        bH = g_WTh + wo; bL = g_WTl + wo;
        bias = r ? bv2 : bv1;
    }
    float acc[4][4][4];
#pragma unroll
    for (int a = 0; a < 4; a++)
#pragma unroll
        for (int b = 0; b < 4; b++)
#pragma unroll
            for (int c = 0; c < 4; c++) acc[a][b][c] = 0.f;

    gemm_mma<128, 2, 4>(g_Xh + (long long)bm * 1024, g_Xl + (long long)bm * 1024, 1024,
                        bH, bL, 1024, 1024, acc);

    const int wid = threadIdx.x >> 5, lane = threadIdx.x & 31;
    const int g = lane >> 2, t = lane & 3;
    const int wm = (wid >> 2) * 64, wn = (wid & 3) * 32;
#pragma unroll
    for (int mi = 0; mi < 4; mi++) {
        int m0 = bm + wm + mi * 16 + g;
#pragma unroll
        for (int ni = 0; ni < 4; ni++) {
            int col = bnl + wn + ni * 8 + 2 * t;
            float b0 = bias[col], b1 = bias[col + 1];
            float v00 = acc[mi][ni][0] + b0, v01 = acc[mi][ni][1] + b1;
            float v10 = acc[mi][ni][2] + b0, v11 = acc[mi][ni][3] + b1;
            bf16 h00 = __float2bfloat16(v00), h01 = __float2bfloat16(v01);
            bf16 h10 = __float2bfloat16(v10), h11 = __float2bfloat16(v11);
            bf16 l00 = __float2bfloat16(v00 - __bfloat162float(h00));
            bf16 l01 = __float2bfloat16(v01 - __bfloat162float(h01));
            bf16 l10 = __float2bfloat16(v10 - __bfloat162float(h10));
            bf16 l11 = __float2bfloat16(v11 - __bfloat162float(h11));
            if (cb < 32) {
                long long o0 = (long long)m0 * 1024 + col;
                long long o1 = (long long)(m0 + 8) * 1024 + col;
                *(__nv_bfloat162*)&g_QKh[r][o0] = __nv_bfloat162(h00, h01);
                *(__nv_bfloat162*)&g_QKl[r][o0] = __nv_bfloat162(l00, l01);
                *(__nv_bfloat162*)&g_QKh[r][o1] = __nv_bfloat162(h10, h11);
                *(__nv_bfloat162*)&g_QKl[r][o1] = __nv_bfloat162(l10, l11);
            } else {
                int c0 = r * 512 + col, c1 = c0 + 1;
                g_VTh[(long long)c0 * 2048 + m0] = h00;
                g_VTh[(long long)c1 * 2048 + m0] = h01;
                g_VTh[(long long)c0 * 2048 + m0 + 8] = h10;
                g_VTh[(long long)c1 * 2048 + m0 + 8] = h11;
                g_VTl[(long long)c0 * 2048 + m0] = l00;
                g_VTl[(long long)c1 * 2048 + m0] = l01;
                g_VTl[(long long)c0 * 2048 + m0 + 8] = l10;
                g_VTl[(long long)c1 * 2048 + m0 + 8] = l11;
            }
        }
    }
}

// ============================ stage 2: scores ============================
__global__ __launch_bounds__(256, 2)
void score_mma_kernel(float scale)
{
    const int z = blockIdx.z, mat = z >> 3, h = z & 7;
    const int bm = blockIdx.y * 128, bn = blockIdx.x * 128;
    const bf16* qh = g_QKh[mat * 2] + (long long)bm * 1024 + h * 128;
    const bf16* ql = g_QKl[mat * 2] + (long long)bm * 1024 + h * 128;
    const bf16* kh = g_QKh[mat * 2 + 1] + (long long)bn * 1024 + h * 128;
    const bf16* kl = g_QKl[mat * 2 + 1] + (long long)bn * 1024 + h * 128;

    float acc[4][4][4];
#pragma unroll
    for (int a = 0; a < 4; a++)
#pragma unroll
        for (int b = 0; b < 4; b++)
#pragma unroll
            for (int c = 0; c < 4; c++) acc[a][b][c] = 0.f;

    gemm_mma<128, 2, 4>(qh, ql, 1024, kh, kl, 1024, 128, acc);

    float* S = (mat ? g_S2 : g_S1) + (long long)h * N_TOK * N_TOK;
    const int wid = threadIdx.x >> 5, lane = threadIdx.x & 31;
    const int g = lane >> 2, t = lane & 3;
    const int wm = (wid >> 2) * 64, wn = (wid & 3) * 32;
#pragma unroll
    for (int mi = 0; mi < 4; mi++) {
        int m0 = bm + wm + mi * 16 + g;
#pragma unroll
        for (int ni = 0; ni < 4; ni++) {
            int n0 = bn + wn + ni * 8 + 2 * t;
            float2 r0 = make_float2(acc[mi][ni][0] * scale, acc[mi][ni][1] * scale);
            float2 r1 = make_float2(acc[mi][ni][2] * scale, acc[mi][ni][3] * scale);
            *(float2*)(S + (long long)m0 * N_TOK + n0) = r0;
            *(float2*)(S + (long long)(m0 + 8) * N_TOK + n0) = r1;
        }
    }
}

// ============================ stage 3: dual gathered softmax ============================
__device__ __forceinline__ float warpRedMax(float v) {
#pragma unroll
    for (int o = 16; o > 0; o >>= 1) v = fmaxf(v, __shfl_xor_sync(0xffffffffu, v, o));
    return v;
}
__device__ __forceinline__ float warpRedSum(float v) {
#pragma unroll
    for (int o = 16; o > 0; o >>= 1) v += __shfl_xor_sync(0xffffffffu, v, o);
    return v;
}

__global__ __launch_bounds__(256)
void softmax_gather_kernel()
{
    const int n = blockIdx.x;
    const int h = blockIdx.y;
    float* s1row = g_S1 + ((long long)h * N_TOK + n) * N_TOK;
    float* s2row = g_S2 + ((long long)h * N_TOK + n) * N_TOK;
    __shared__ float sh1[N_TOK];
    __shared__ float sh2[N_TOK];
    __shared__ float red[32];
    const int tid = threadIdx.x;
    const int lane = tid & 31, wid = tid >> 5;

#pragma unroll
    for (int i = 0; i < 8; i++) {
        int m = tid + i * 256;
        sh1[m] = s1row[m];
        sh2[m] = s2row[m];
    }
    __syncthreads();

    const unsigned short* c2nrow = g_I1 + (long long)n * N_TOK;
    const unsigned short* n2crow = g_I2 + (long long)n * N_TOK;
    const bf16* m1row = g_M1 + (long long)n * N_TOK;
    const bf16* m2row = g_M2 + (long long)n * N_TOK;

    float z1[8], z2[8];
    float mx1 = -1e30f, mx2 = -1e30f;
#pragma unroll
    for (int i = 0; i < 8; i++) {
        int m = tid + i * 256;
        z1[i] = sh1[m] + sh2[c2nrow[m]] + __bfloat162float(m1row[m]);
        z2[i] = sh2[m] + sh1[n2crow[m]] + __bfloat162float(m2row[m]);
        mx1 = fmaxf(mx1, z1[i]);
        mx2 = fmaxf(mx2, z2[i]);
    }
    mx1 = warpRedMax(mx1);
    mx2 = warpRedMax(mx2);
    if (lane == 0) { red[wid] = mx1; red[wid + 8] = mx2; }
    __syncthreads();
    if (wid == 0) {
        float a = (lane < 8) ? red[lane] : -1e30f;
        float b = (lane < 8) ? red[lane + 8] : -1e30f;
        a = warpRedMax(a);
        b = warpRedMax(b);
        if (lane == 0) { red[16] = a; red[17] = b; }
    }
    __syncthreads();
    mx1 = red[16];
    mx2 = red[17];

    float sum1 = 0.f, sum2 = 0.f;
#pragma unroll
    for (int i = 0; i < 8; i++) {
        z1[i] = __expf(z1[i] - mx1);
        z2[i] = __expf(z2[i] - mx2);
        sum1 += z1[i];
        sum2 += z2[i];
    }
    sum1 = warpRedSum(sum1);
    sum2 = warpRedSum(sum2);
    __syncthreads();
    if (lane == 0) { red[wid] = sum1; red[wid + 8] = sum2; }
    __syncthreads();
    if (wid == 0) {
        float a = (lane < 8) ? red[lane] : 0.f;
        float b = (lane < 8) ? red[lane + 8] : 0.f;
        a = warpRedSum(a);
        b = warpRedSum(b);
        if (lane == 0) { red[16] = a; red[17] = b; }
    }
    __syncthreads();
    float inv1 = 1.f / red[16];
    float inv2 = 1.f / red[17];
    bf16* a1 = reinterpret_cast<bf16*>(s1row);
    bf16* a2 = reinterpret_cast<bf16*>(s2row);
#pragma unroll
    for (int i = 0; i < 8; i++) {
        int m = tid + i * 256;
        float p1 = z1[i] * inv1;
        float p2 = z2[i] * inv2;
        bf16 h1 = __float2bfloat16(p1);
        bf16 h2 = __float2bfloat16(p2);
        a1[m] = h1; a1[2048 + m] = __float2bfloat16(p1 - __bfloat162float(h1));
        a2[m] = h2; a2[2048 + m] = __float2bfloat16(p2 - __bfloat162float(h2));
    }
}

// ============================ stage 4: AV + concat ============================
__global__ __launch_bounds__(256, 2)
void av_mma_kernel(float* __restrict__ out)
{
    const int z = blockIdx.z, mat = z >> 3, h = z & 7;
    const int bm = blockIdx.y * 128;
    const bf16* Ab = reinterpret_cast<const bf16*>(mat ? g_S2 : g_S1);
    const bf16* aH = Ab + ((long long)h * N_TOK + bm) * 4096;
    const bf16* aL = aH + 2048;
    const bf16* bH = g_VTh + (long long)(mat * 512 + h * 64) * 2048;
    const bf16* bL = g_VTl + (long long)(mat * 512 + h * 64) * 2048;

    float acc[2][4][4];
#pragma unroll
    for (int a = 0; a < 2; a++)
#pragma unroll
        for (int b = 0; b < 4; b++)
#pragma unroll
            for (int c = 0; c < 4; c++) acc[a][b][c] = 0.f;

    gemm_mma<64, 4, 2>(aH, aL, 4096, bH, bL, 2048, 2048, acc);

    const int wid = threadIdx.x >> 5, lane = threadIdx.x & 31;
    const int g = lane >> 2, t = lane & 3;
    const int wm = (wid >> 1) * 32, wn = (wid & 1) * 32;
    const int cbase = mat * 512 + h * 64;
#pragma unroll
    for (int mi = 0; mi < 2; mi++) {
        int m0 = bm + wm + mi * 16 + g;
#pragma unroll
        for (int ni = 0; ni < 4; ni++) {
            int col = cbase + wn + ni * 8 + 2 * t;
            *(float2*)(out + (long long)m0 * 1024 + col) =
                make_float2(acc[mi][ni][0], acc[mi][ni][1]);
            *(float2*)(out + (long long)(m0 + 8) * 1024 + col) =
                make_float2(acc[mi][ni][2], acc[mi][ni][3]);
        }
    }
}

// ============================ launch ============================
extern "C" void kernel_launch(void* const* d_in, const int* in_sizes, int n_in,
                              void* d_out, int out_size)
{
    const float* x   = (const float*)d_in[0];
    const float* fst = (const float*)d_in[1];
    const float* sec = (const float*)d_in[2];
    const int*   n2c = (const int*)d_in[3];
    const int*   c2n = (const int*)d_in[4];
    const float* Wq1 = (const float*)d_in[5];
    const float* bq1 = (const float*)d_in[6];
    const float* Wk1 = (const float*)d_in[7];
    const float* bk1 = (const float*)d_in[8];
    const float* Wv1 = (const float*)d_in[9];
    const float* bv1 = (const float*)d_in[10];
    const float* Wq2 = (const float*)d_in[11];
    const float* bq2 = (const float*)d_in[12];
    const float* Wk2 = (const float*)d_in[13];
    const float* bk2 = (const float*)d_in[14];
    const float* Wv2 = (const float*)d_in[15];
    const float* bv2 = (const float*)d_in[16];
    float* out = (float*)d_out;

    static bool attr_set = false;
    if (!attr_set) {
        cudaFuncSetAttribute(proj_mma_kernel, cudaFuncAttributeMaxDynamicSharedMemorySize, 81920);
        cudaFuncSetAttribute(score_mma_kernel, cudaFuncAttributeMaxDynamicSharedMemorySize, 81920);
        cudaFuncSetAttribute(av_mma_kernel, cudaFuncAttributeMaxDynamicSharedMemorySize, 61440);
        attr_set = true;
    }

    // stage 0: transposed bf16 masks + u16 indices + bf16 split conversions
    mask_transpose_kernel<<<dim3(64, 64), dim3(32, 8)>>>(fst, sec);
    convidx_kernel<<<4096, 256>>>(c2n, n2c);
    convx_kernel<<<2048, 256>>>(x);
    convw_kernel<<<dim3(32, 32, 6), dim3(32, 8)>>>(Wq1, Wk1, Wq2, Wk2, Wv1, Wv2);

    // stage 1: projections (640 CTAs, pipelined mma.sync)
    proj_mma_kernel<<<dim3(40, 16), 256, 81920>>>(bq1, bk1, bv1, bq2, bk2, bv2);

    // stage 2: scores (4096 CTAs)
    const float scale = 0.08838834764831845f;  // 1/sqrt(128)
    score_mma_kernel<<<dim3(16, 16, 16), 256, 81920>>>(scale);

    // stage 3: gathered dual softmax -> bf16-split attention, in place
    softmax_gather_kernel<<<dim3(2048, 8), 256>>>();

    // stage 4: AV + concat (256 CTAs)
    av_mma_kernel<<<dim3(1, 16, 16), 256, 61440>>>(out);
}

// round 7
// speedup vs baseline: 1.6889x; 1.0933x over previous
#include <cuda_runtime.h>
#include <cuda_bf16.h>
#include <cuda_fp16.h>
#include <cstdint>

#define N_TOK 2048
#define NN (8LL * 2048 * 2048)

typedef __nv_bfloat16 bf16;

__device__ __forceinline__ uint32_t smem_to_u32(const void* p) {
    uint32_t a;
    asm("{ .reg .u64 t; cvta.to.shared.u64 t, %1; cvt.u32.u64 %0, t; }" : "=r"(a) : "l"(p));
    return a;
}

__device__ __forceinline__ void ldmatrix_x4(uint32_t& r0, uint32_t& r1, uint32_t& r2,
                                            uint32_t& r3, uint32_t addr) {
    asm volatile("ldmatrix.sync.aligned.m8n8.x4.shared.b16 {%0,%1,%2,%3}, [%4];"
                 : "=r"(r0), "=r"(r1), "=r"(r2), "=r"(r3) : "r"(addr));
}

__device__ __forceinline__ void mma16816(float c[4], const uint32_t a[4], const uint32_t b[2]) {
    asm volatile(
        "mma.sync.aligned.m16n8k16.row.col.f32.bf16.bf16.f32 "
        "{%0,%1,%2,%3}, {%4,%5,%6,%7}, {%8,%9}, {%0,%1,%2,%3};"
        : "+f"(c[0]), "+f"(c[1]), "+f"(c[2]), "+f"(c[3])
        : "r"(a[0]), "r"(a[1]), "r"(a[2]), "r"(a[3]), "r"(b[0]), "r"(b[1]));
}

__device__ __forceinline__ void mma16816h(float c[4], const uint32_t a[4], const uint32_t b[2]) {
    asm volatile(
        "mma.sync.aligned.m16n8k16.row.col.f32.f16.f16.f32 "
        "{%0,%1,%2,%3}, {%4,%5,%6,%7}, {%8,%9}, {%0,%1,%2,%3};"
        : "+f"(c[0]), "+f"(c[1]), "+f"(c[2]), "+f"(c[3])
        : "r"(a[0]), "r"(a[1]), "r"(a[2]), "r"(a[3]), "r"(b[0]), "r"(b[1]));
}

#define CP_ASYNC_CG(smem_addr, gmem_ptr) \
    asm volatile("cp.async.cg.shared.global [%0], [%1], 16;" \
                 :: "r"(smem_addr), "l"(gmem_ptr))
#define CP_ASYNC_COMMIT() asm volatile("cp.async.commit_group;" ::: "memory")
#define CP_ASYNC_WAIT(n)  asm volatile("cp.async.wait_group %0;" :: "n"(n) : "memory")

// ============================ device scratch ============================
__device__ __align__(16) bf16 g_Xh[2048 * 1024];
__device__ __align__(16) bf16 g_Xl[2048 * 1024];
__device__ __align__(16) bf16 g_WTh[5242880];   // q1,k1,q2,k2 (1M each) + v1,v2 (512K each), [N,K]
__device__ __align__(16) bf16 g_WTl[5242880];
__device__ __align__(16) bf16 g_QKh[4][2048 * 1024];  // 0:q1 1:k1 2:q2 3:k2
__device__ __align__(16) bf16 g_QKl[4][2048 * 1024];
__device__ __align__(16) __half g_VTh[1024 * 2048];   // fp16 V hi, rows: mat*512 + vcol, cols: token
__device__ __align__(16) __half g_VTl[1024 * 2048];   // fp16 V lo
__device__ __align__(16) float g_S1[NN];   // fp32 scores; after softmax: fp16 probs x2048 in first half of row
__device__ __align__(16) float g_S2[NN];
__device__ __align__(16) bf16 g_M1[2048LL * 2048];           // transposed masks, bf16 (exact: {0,-1e4})
__device__ __align__(16) bf16 g_M2[2048LL * 2048];
__device__ __align__(16) unsigned short g_I1[2048LL * 2048]; // c2n as u16
__device__ __align__(16) unsigned short g_I2[2048LL * 2048]; // n2c as u16

// ============================ conversion kernels ============================
__global__ __launch_bounds__(256) void convx_kernel(const float* __restrict__ x) {
    int i = (blockIdx.x * 256 + threadIdx.x) * 4;
    float4 v = *(const float4*)(x + i);
    float vv[4] = {v.x, v.y, v.z, v.w};
    bf16 h[4], l[4];
#pragma unroll
    for (int j = 0; j < 4; j++) {
        h[j] = __float2bfloat16(vv[j]);
        l[j] = __float2bfloat16(vv[j] - __bfloat162float(h[j]));
    }
    *(uint2*)&g_Xh[i] = *(uint2*)h;
    *(uint2*)&g_Xl[i] = *(uint2*)l;
}

__global__ __launch_bounds__(256)
void convw_kernel(const float* __restrict__ w0, const float* __restrict__ w1,
                  const float* __restrict__ w2, const float* __restrict__ w3,
                  const float* __restrict__ w4, const float* __restrict__ w5) {
    int z = blockIdx.z;
    const float* W;
    int Ncols;
    long long base;
    switch (z) {
        case 0: W = w0; Ncols = 1024; base = 0; break;
        case 1: W = w1; Ncols = 1024; base = 1048576; break;
        case 2: W = w2; Ncols = 1024; base = 2097152; break;
        case 3: W = w3; Ncols = 1024; base = 3145728; break;
        case 4: W = w4; Ncols = 512;  base = 4194304; break;
        default:W = w5; Ncols = 512;  base = 4718592; break;
    }
    int bn = blockIdx.x * 32, bk = blockIdx.y * 32;
    if (bn >= Ncols) return;
    __shared__ float t[32][33];
#pragma unroll
    for (int i = threadIdx.y; i < 32; i += 8)
        t[i][threadIdx.x] = W[(long long)(bk + i) * Ncols + bn + threadIdx.x];
    __syncthreads();
#pragma unroll
    for (int i = threadIdx.y; i < 32; i += 8) {
        float v = t[threadIdx.x][i];
        bf16 hh = __float2bfloat16(v);
        long long o = base + (long long)(bn + i) * 1024 + bk + threadIdx.x;
        g_WTh[o] = hh;
        g_WTl[o] = __float2bfloat16(v - __bfloat162float(hh));
    }
}

// masks transposed -> bf16 (values {0,-1e4} exact)
__global__ void mask_transpose_kernel(const float* __restrict__ G1,
                                      const float* __restrict__ G2) {
    __shared__ float t1[32][33];
    __shared__ float t2[32][33];
    int bx = blockIdx.x * 32;
    int by = blockIdx.y * 32;
    int x = bx + threadIdx.x;
#pragma unroll
    for (int i = threadIdx.y; i < 32; i += 8) {
        t1[i][threadIdx.x] = G1[(long long)(by + i) * N_TOK + x];
        t2[i][threadIdx.x] = G2[(long long)(by + i) * N_TOK + x];
    }
    __syncthreads();
    int ox = by + threadIdx.x;
#pragma unroll
    for (int i = threadIdx.y; i < 32; i += 8) {
        g_M1[(long long)(bx + i) * N_TOK + ox] =
            __float2bfloat16((t1[threadIdx.x][i] - 1.f) * 10000.f);
        g_M2[(long long)(bx + i) * N_TOK + ox] =
            __float2bfloat16((t2[threadIdx.x][i] - 1.f) * 10000.f);
    }
}

// indices int32 -> uint16
__global__ __launch_bounds__(256)
void convidx_kernel(const int* __restrict__ c2n, const int* __restrict__ n2c) {
    long long i = ((long long)blockIdx.x * 256 + threadIdx.x) * 4;
    int4 a = *(const int4*)(c2n + i);
    int4 b = *(const int4*)(n2c + i);
    ushort4 ua = make_ushort4((unsigned short)a.x, (unsigned short)a.y,
                              (unsigned short)a.z, (unsigned short)a.w);
    ushort4 ub = make_ushort4((unsigned short)b.x, (unsigned short)b.y,
                              (unsigned short)b.z, (unsigned short)b.w);
    *(ushort4*)&g_I1[i] = ua;
    *(ushort4*)&g_I2[i] = ub;
}

// ============================ pipelined 3-term bf16 GEMM body (proj/score) ============================
template <int BN, int WM, int WN>
__device__ __forceinline__ void gemm_mma(
    const bf16* __restrict__ aH, const bf16* __restrict__ aL, int lda,
    const bf16* __restrict__ bH, const bf16* __restrict__ bL, int ldb,
    int K, float acc[128 / (WM * 16)][4][4])
{
    constexpr int MI = 128 / (WM * 16);
    constexpr int OFF_AL = 10240;
    constexpr int OFF_BH = 20480;
    constexpr int OFF_BL = 20480 + BN * 80;
    constexpr int STG = 20480 + BN * 160;
    extern __shared__ __align__(16) char sm[];
    const uint32_t smb = smem_to_u32(sm);
    const int tid = threadIdx.x;
    const int wid = tid >> 5, lane = tid & 31;
    const int wm = (wid / WN) * (MI * 16);
    const int wn = (wid % WN) * 32;
    const int a_row = wm + (lane & 7) + ((lane >> 3) & 1) * 8;
    const int a_cofs = (lane >> 4) * 8;
    const int b_row = wn + (lane & 7) + ((lane >> 4) & 1) * 8;
    const int b_cofs = ((lane >> 3) & 1) * 8;

    const int r_cp = tid >> 2;          // 0..63
    const int c_cp = (tid & 3) * 8;     // 0,8,16,24
    const int NC = K >> 5;

    auto issue_stage = [&](int ic) {
        const uint32_t sb = smb + (uint32_t)(ic & 1) * STG;
        const int k0 = ic * 32;
#pragma unroll
        for (int i = 0; i < 2; i++) {
            int r = r_cp + i * 64;
            uint32_t so = (uint32_t)(r * 80 + c_cp * 2);
            CP_ASYNC_CG(sb + so, aH + r * lda + k0 + c_cp);
            CP_ASYNC_CG(sb + OFF_AL + so, aL + r * lda + k0 + c_cp);
        }
#pragma unroll
        for (int i = 0; i < BN / 64; i++) {
            int r = r_cp + i * 64;
            uint32_t so = (uint32_t)(r * 80 + c_cp * 2);
            CP_ASYNC_CG(sb + OFF_BH + so, bH + r * ldb + k0 + c_cp);
            CP_ASYNC_CG(sb + OFF_BL + so, bL + r * ldb + k0 + c_cp);
        }
        CP_ASYNC_COMMIT();
    };

    issue_stage(0);
    for (int ic = 0; ic < NC; ic++) {
        if (ic + 1 < NC) { issue_stage(ic + 1); CP_ASYNC_WAIT(1); }
        else             { CP_ASYNC_WAIT(0); }
        __syncthreads();
        const uint32_t sb = smb + (uint32_t)(ic & 1) * STG;
#pragma unroll
        for (int ks = 0; ks < 32; ks += 16) {
            uint32_t ah[MI][4], al[MI][4], bh[4][2], bl[4][2];
#pragma unroll
            for (int mi = 0; mi < MI; mi++) {
                uint32_t off = (uint32_t)(((a_row + mi * 16) * 40 + ks + a_cofs) * 2);
                ldmatrix_x4(ah[mi][0], ah[mi][1], ah[mi][2], ah[mi][3], sb + off);
                ldmatrix_x4(al[mi][0], al[mi][1], al[mi][2], al[mi][3], sb + OFF_AL + off);
            }
#pragma unroll
            for (int nj = 0; nj < 2; nj++) {
                uint32_t off = (uint32_t)(((b_row + nj * 16) * 40 + ks + b_cofs) * 2);
                ldmatrix_x4(bh[nj * 2][0], bh[nj * 2][1], bh[nj * 2 + 1][0], bh[nj * 2 + 1][1],
                            sb + OFF_BH + off);
                ldmatrix_x4(bl[nj * 2][0], bl[nj * 2][1], bl[nj * 2 + 1][0], bl[nj * 2 + 1][1],
                            sb + OFF_BL + off);
            }
#pragma unroll
            for (int mi = 0; mi < MI; mi++)
#pragma unroll
                for (int ni = 0; ni < 4; ni++) {
                    mma16816(acc[mi][ni], ah[mi], bh[ni]);
                    mma16816(acc[mi][ni], ah[mi], bl[ni]);
                    mma16816(acc[mi][ni], al[mi], bh[ni]);
                }
        }
        __syncthreads();
    }
}

// ============================ 2-term fp16 GEMM body (AV) ============================
// acc[2][4][4] += P(128,K) * (Vh+Vl)(64,K)^T. P single fp16, V fp16 hi/lo.
// Warp grid 4x2. Stage layout: [A 10240 | Bh 5120 | Bl 5120], STG=20480.
__device__ __forceinline__ void gemm_av(
    const __half* __restrict__ aP, int lda,
    const __half* __restrict__ bH, const __half* __restrict__ bL, int ldb,
    int K, float acc[2][4][4])
{
    constexpr int OFF_BH = 10240;
    constexpr int OFF_BL = 15360;
    constexpr int STG = 20480;
    extern __shared__ __align__(16) char sm[];
    const uint32_t smb = smem_to_u32(sm);
    const int tid = threadIdx.x;
    const int wid = tid >> 5, lane = tid & 31;
    const int wm = (wid >> 1) * 32;
    const int wn = (wid & 1) * 32;
    const int a_row = wm + (lane & 7) + ((lane >> 3) & 1) * 8;
    const int a_cofs = (lane >> 4) * 8;
    const int b_row = wn + (lane & 7) + ((lane >> 4) & 1) * 8;
    const int b_cofs = ((lane >> 3) & 1) * 8;

    const int r_cp = tid >> 2;
    const int c_cp = (tid & 3) * 8;
    const int NC = K >> 5;

    auto issue_stage = [&](int ic) {
        const uint32_t sb = smb + (uint32_t)(ic & 1) * STG;
        const int k0 = ic * 32;
#pragma unroll
        for (int i = 0; i < 2; i++) {
            int r = r_cp + i * 64;
            uint32_t so = (uint32_t)(r * 80 + c_cp * 2);
            CP_ASYNC_CG(sb + so, aP + (long long)r * lda + k0 + c_cp);
        }
        {
            int r = r_cp;   // 0..63 covers all 64 V rows
            uint32_t so = (uint32_t)(r * 80 + c_cp * 2);
            CP_ASYNC_CG(sb + OFF_BH + so, bH + (long long)r * ldb + k0 + c_cp);
            CP_ASYNC_CG(sb + OFF_BL + so, bL + (long long)r * ldb + k0 + c_cp);
        }
        CP_ASYNC_COMMIT();
    };

    issue_stage(0);
    for (int ic = 0; ic < NC; ic++) {
        if (ic + 1 < NC) { issue_stage(ic + 1); CP_ASYNC_WAIT(1); }
        else             { CP_ASYNC_WAIT(0); }
        __syncthreads();
        const uint32_t sb = smb + (uint32_t)(ic & 1) * STG;
#pragma unroll
        for (int ks = 0; ks < 32; ks += 16) {
            uint32_t ap[2][4], bh[4][2], bl[4][2];
#pragma unroll
            for (int mi = 0; mi < 2; mi++) {
                uint32_t off = (uint32_t)(((a_row + mi * 16) * 40 + ks + a_cofs) * 2);
                ldmatrix_x4(ap[mi][0], ap[mi][1], ap[mi][2], ap[mi][3], sb + off);
            }
#pragma unroll
            for (int nj = 0; nj < 2; nj++) {
                uint32_t off = (uint32_t)(((b_row + nj * 16) * 40 + ks + b_cofs) * 2);
                ldmatrix_x4(bh[nj * 2][0], bh[nj * 2][1], bh[nj * 2 + 1][0], bh[nj * 2 + 1][1],
                            sb + OFF_BH + off);
                ldmatrix_x4(bl[nj * 2][0], bl[nj * 2][1], bl[nj * 2 + 1][0], bl[nj * 2 + 1][1],
                            sb + OFF_BL + off);
            }
#pragma unroll
            for (int mi = 0; mi < 2; mi++)
#pragma unroll
                for (int ni = 0; ni < 4; ni++) {
                    mma16816h(acc[mi][ni], ap[mi], bh[ni]);
                    mma16816h(acc[mi][ni], ap[mi], bl[ni]);
                }
        }
        __syncthreads();
    }
}

// ============================ stage 1: projections ============================
__global__ __launch_bounds__(256, 2)
void proj_mma_kernel(const float* __restrict__ bq1, const float* __restrict__ bk1,
                     const float* __restrict__ bv1, const float* __restrict__ bq2,
                     const float* __restrict__ bk2, const float* __restrict__ bv2)
{
    const int cb = blockIdx.x;
    const int bm = blockIdx.y * 128;
    const bf16 *bH, *bL;
    const float* bias;
    int r, bnl;
    if (cb < 32) {
        r = cb >> 3; bnl = (cb & 7) * 128;
        long long wo = (long long)r * 1048576 + (long long)bnl * 1024;
        bH = g_WTh + wo; bL = g_WTl + wo;
        bias = (r == 0) ? bq1 : (r == 1) ? bk1 : (r == 2) ? bq2 : bk2;
    } else {
        r = (cb - 32) >> 2; bnl = ((cb - 32) & 3) * 128;
        long long wo = 4194304LL + (long long)r * 524288 + (long long)bnl * 1024;
        bH = g_WTh + wo; bL = g_WTl + wo;
        bias = r ? bv2 : bv1;
    }
    float acc[4][4][4];
#pragma unroll
    for (int a = 0; a < 4; a++)
#pragma unroll
        for (int b = 0; b < 4; b++)
#pragma unroll
            for (int c = 0; c < 4; c++) acc[a][b][c] = 0.f;

    gemm_mma<128, 2, 4>(g_Xh + (long long)bm * 1024, g_Xl + (long long)bm * 1024, 1024,
                        bH, bL, 1024, 1024, acc);

    const int wid = threadIdx.x >> 5, lane = threadIdx.x & 31;
    const int g = lane >> 2, t = lane & 3;
    const int wm = (wid >> 2) * 64, wn = (wid & 3) * 32;
#pragma unroll
    for (int mi = 0; mi < 4; mi++) {
        int m0 = bm + wm + mi * 16 + g;
#pragma unroll
        for (int ni = 0; ni < 4; ni++) {
            int col = bnl + wn + ni * 8 + 2 * t;
            float b0 = bias[col], b1 = bias[col + 1];
            float v00 = acc[mi][ni][0] + b0, v01 = acc[mi][ni][1] + b1;
            float v10 = acc[mi][ni][2] + b0, v11 = acc[mi][ni][3] + b1;
            if (cb < 32) {
                bf16 h00 = __float2bfloat16(v00), h01 = __float2bfloat16(v01);
                bf16 h10 = __float2bfloat16(v10), h11 = __float2bfloat16(v11);
                bf16 l00 = __float2bfloat16(v00 - __bfloat162float(h00));
                bf16 l01 = __float2bfloat16(v01 - __bfloat162float(h01));
                bf16 l10 = __float2bfloat16(v10 - __bfloat162float(h10));
                bf16 l11 = __float2bfloat16(v11 - __bfloat162float(h11));
                long long o0 = (long long)m0 * 1024 + col;
                long long o1 = (long long)(m0 + 8) * 1024 + col;
                *(__nv_bfloat162*)&g_QKh[r][o0] = __nv_bfloat162(h00, h01);
                *(__nv_bfloat162*)&g_QKl[r][o0] = __nv_bfloat162(l00, l01);
                *(__nv_bfloat162*)&g_QKh[r][o1] = __nv_bfloat162(h10, h11);
                *(__nv_bfloat162*)&g_QKl[r][o1] = __nv_bfloat162(l10, l11);
            } else {
                __half h00 = __float2half_rn(v00), h01 = __float2half_rn(v01);
                __half h10 = __float2half_rn(v10), h11 = __float2half_rn(v11);
                __half l00 = __float2half_rn(v00 - __half2float(h00));
                __half l01 = __float2half_rn(v01 - __half2float(h01));
                __half l10 = __float2half_rn(v10 - __half2float(h10));
                __half l11 = __float2half_rn(v11 - __half2float(h11));
                int c0 = r * 512 + col, c1 = c0 + 1;
                g_VTh[(long long)c0 * 2048 + m0] = h00;
                g_VTh[(long long)c1 * 2048 + m0] = h01;
                g_VTh[(long long)c0 * 2048 + m0 + 8] = h10;
                g_VTh[(long long)c1 * 2048 + m0 + 8] = h11;
                g_VTl[(long long)c0 * 2048 + m0] = l00;
                g_VTl[(long long)c1 * 2048 + m0] = l01;
                g_VTl[(long long)c0 * 2048 + m0 + 8] = l10;
                g_VTl[(long long)c1 * 2048 + m0 + 8] = l11;
            }
        }
    }
}

// ============================ stage 2: scores ============================
__global__ __launch_bounds__(256, 2)
void score_mma_kernel(float scale)
{
    const int z = blockIdx.z, mat = z >> 3, h = z & 7;
    const int bm = blockIdx.y * 128, bn = blockIdx.x * 128;
    const bf16* qh = g_QKh[mat * 2] + (long long)bm * 1024 + h * 128;
    const bf16* ql = g_QKl[mat * 2] + (long long)bm * 1024 + h * 128;
    const bf16* kh = g_QKh[mat * 2 + 1] + (long long)bn * 1024 + h * 128;
    const bf16* kl = g_QKl[mat * 2 + 1] + (long long)bn * 1024 + h * 128;

    float acc[4][4][4];
#pragma unroll
    for (int a = 0; a < 4; a++)
#pragma unroll
        for (int b = 0; b < 4; b++)
#pragma unroll
            for (int c = 0; c < 4; c++) acc[a][b][c] = 0.f;

    gemm_mma<128, 2, 4>(qh, ql, 1024, kh, kl, 1024, 128, acc);

    float* S = (mat ? g_S2 : g_S1) + (long long)h * N_TOK * N_TOK;
    const int wid = threadIdx.x >> 5, lane = threadIdx.x & 31;
    const int g = lane >> 2, t = lane & 3;
    const int wm = (wid >> 2) * 64, wn = (wid & 3) * 32;
#pragma unroll
    for (int mi = 0; mi < 4; mi++) {
        int m0 = bm + wm + mi * 16 + g;
#pragma unroll
        for (int ni = 0; ni < 4; ni++) {
            int n0 = bn + wn + ni * 8 + 2 * t;
            float2 r0 = make_float2(acc[mi][ni][0] * scale, acc[mi][ni][1] * scale);
            float2 r1 = make_float2(acc[mi][ni][2] * scale, acc[mi][ni][3] * scale);
            *(float2*)(S + (long long)m0 * N_TOK + n0) = r0;
            *(float2*)(S + (long long)(m0 + 8) * N_TOK + n0) = r1;
        }
    }
}

// ============================ stage 3: dual gathered softmax ============================
__device__ __forceinline__ float warpRedMax(float v) {
#pragma unroll
    for (int o = 16; o > 0; o >>= 1) v = fmaxf(v, __shfl_xor_sync(0xffffffffu, v, o));
    return v;
}
__device__ __forceinline__ float warpRedSum(float v) {
#pragma unroll
    for (int o = 16; o > 0; o >>= 1) v += __shfl_xor_sync(0xffffffffu, v, o);
    return v;
}

__global__ __launch_bounds__(256)
void softmax_gather_kernel()
{
    const int n = blockIdx.x;
    const int h = blockIdx.y;
    float* s1row = g_S1 + ((long long)h * N_TOK + n) * N_TOK;
    float* s2row = g_S2 + ((long long)h * N_TOK + n) * N_TOK;
    __shared__ float sh1[N_TOK];
    __shared__ float sh2[N_TOK];
    __shared__ float red[32];
    const int tid = threadIdx.x;
    const int lane = tid & 31, wid = tid >> 5;

#pragma unroll
    for (int i = 0; i < 8; i++) {
        int m = tid + i * 256;
        sh1[m] = s1row[m];
        sh2[m] = s2row[m];
    }
    __syncthreads();

    const unsigned short* c2nrow = g_I1 + (long long)n * N_TOK;
    const unsigned short* n2crow = g_I2 + (long long)n * N_TOK;
    const bf16* m1row = g_M1 + (long long)n * N_TOK;
    const bf16* m2row = g_M2 + (long long)n * N_TOK;

    float z1[8], z2[8];
    float mx1 = -1e30f, mx2 = -1e30f;
#pragma unroll
    for (int i = 0; i < 8; i++) {
        int m = tid + i * 256;
        z1[i] = sh1[m] + sh2[c2nrow[m]] + __bfloat162float(m1row[m]);
        z2[i] = sh2[m] + sh1[n2crow[m]] + __bfloat162float(m2row[m]);
        mx1 = fmaxf(mx1, z1[i]);
        mx2 = fmaxf(mx2, z2[i]);
    }
    mx1 = warpRedMax(mx1);
    mx2 = warpRedMax(mx2);
    if (lane == 0) { red[wid] = mx1; red[wid + 8] = mx2; }
    __syncthreads();
    if (wid == 0) {
        float a = (lane < 8) ? red[lane] : -1e30f;
        float b = (lane < 8) ? red[lane + 8] : -1e30f;
        a = warpRedMax(a);
        b = warpRedMax(b);
        if (lane == 0) { red[16] = a; red[17] = b; }
    }
    __syncthreads();
    mx1 = red[16];
    mx2 = red[17];

    float sum1 = 0.f, sum2 = 0.f;
#pragma unroll
    for (int i = 0; i < 8; i++) {
        z1[i] = __expf(z1[i] - mx1);
        z2[i] = __expf(z2[i] - mx2);
        sum1 += z1[i];
        sum2 += z2[i];
    }
    sum1 = warpRedSum(sum1);
    sum2 = warpRedSum(sum2);
    __syncthreads();
    if (lane == 0) { red[wid] = sum1; red[wid + 8] = sum2; }
    __syncthreads();
    if (wid == 0) {
        float a = (lane < 8) ? red[lane] : 0.f;
        float b = (lane < 8) ? red[lane + 8] : 0.f;
        a = warpRedSum(a);
        b = warpRedSum(b);
        if (lane == 0) { red[16] = a; red[17] = b; }
    }
    __syncthreads();
    float inv1 = 1.f / red[16];
    float inv2 = 1.f / red[17];
    // write probs as single fp16 into the first half of each row
    __half* a1 = reinterpret_cast<__half*>(s1row);
    __half* a2 = reinterpret_cast<__half*>(s2row);
#pragma unroll
    for (int i = 0; i < 8; i++) {
        int m = tid + i * 256;
        a1[m] = __float2half_rn(z1[i] * inv1);
        a2[m] = __float2half_rn(z2[i] * inv2);
    }
}

// ============================ stage 4: AV + concat (2-term fp16) ============================
__global__ __launch_bounds__(256, 2)
void av_mma_kernel(float* __restrict__ out)
{
    const int z = blockIdx.z, mat = z >> 3, h = z & 7;
    const int bm = blockIdx.y * 128;
    const __half* Ab = reinterpret_cast<const __half*>(mat ? g_S2 : g_S1);
    const __half* aP = Ab + ((long long)h * N_TOK + bm) * 4096;
    const __half* bH = g_VTh + (long long)(mat * 512 + h * 64) * 2048;
    const __half* bL = g_VTl + (long long)(mat * 512 + h * 64) * 2048;

    float acc[2][4][4];
#pragma unroll
    for (int a = 0; a < 2; a++)
#pragma unroll
        for (int b = 0; b < 4; b++)
#pragma unroll
            for (int c = 0; c < 4; c++) acc[a][b][c] = 0.f;

    gemm_av(aP, 4096, bH, bL, 2048, 2048, acc);

    const int wid = threadIdx.x >> 5, lane = threadIdx.x & 31;
    const int g = lane >> 2, t = lane & 3;
    const int wm = (wid >> 1) * 32, wn = (wid & 1) * 32;
    const int cbase = mat * 512 + h * 64;
#pragma unroll
    for (int mi = 0; mi < 2; mi++) {
        int m0 = bm + wm + mi * 16 + g;
#pragma unroll
        for (int ni = 0; ni < 4; ni++) {
            int col = cbase + wn + ni * 8 + 2 * t;
            *(float2*)(out + (long long)m0 * 1024 + col) =
                make_float2(acc[mi][ni][0], acc[mi][ni][1]);
            *(float2*)(out + (long long)(m0 + 8) * 1024 + col) =
                make_float2(acc[mi][ni][2], acc[mi][ni][3]);
        }
    }
}

// ============================ launch ============================
extern "C" void kernel_launch(void* const* d_in, const int* in_sizes, int n_in,
                              void* d_out, int out_size)
{
    const float* x   = (const float*)d_in[0];
    const float* fst = (const float*)d_in[1];
    const float* sec = (const float*)d_in[2];
    const int*   n2c = (const int*)d_in[3];
    const int*   c2n = (const int*)d_in[4];
    const float* Wq1 = (const float*)d_in[5];
    const float* bq1 = (const float*)d_in[6];
    const float* Wk1 = (const float*)d_in[7];
    const float* bk1 = (const float*)d_in[8];
    const float* Wv1 = (const float*)d_in[9];
    const float* bv1 = (const float*)d_in[10];
    const float* Wq2 = (const float*)d_in[11];
    const float* bq2 = (const float*)d_in[12];
    const float* Wk2 = (const float*)d_in[13];
    const float* bk2 = (const float*)d_in[14];
    const float* Wv2 = (const float*)d_in[15];
    const float* bv2 = (const float*)d_in[16];
    float* out = (float*)d_out;

    static bool attr_set = false;
    if (!attr_set) {
        cudaFuncSetAttribute(proj_mma_kernel, cudaFuncAttributeMaxDynamicSharedMemorySize, 81920);
        cudaFuncSetAttribute(score_mma_kernel, cudaFuncAttributeMaxDynamicSharedMemorySize, 81920);
        cudaFuncSetAttribute(av_mma_kernel, cudaFuncAttributeMaxDynamicSharedMemorySize, 40960);
        attr_set = true;
    }

    // stage 0: transposed bf16 masks + u16 indices + bf16 split conversions
    mask_transpose_kernel<<<dim3(64, 64), dim3(32, 8)>>>(fst, sec);
    convidx_kernel<<<4096, 256>>>(c2n, n2c);
    convx_kernel<<<2048, 256>>>(x);
    convw_kernel<<<dim3(32, 32, 6), dim3(32, 8)>>>(Wq1, Wk1, Wq2, Wk2, Wv1, Wv2);

    // stage 1: projections (640 CTAs, pipelined mma.sync)
    proj_mma_kernel<<<dim3(40, 16), 256, 81920>>>(bq1, bk1, bv1, bq2, bk2, bv2);

    // stage 2: scores (4096 CTAs)
    const float scale = 0.08838834764831845f;  // 1/sqrt(128)
    score_mma_kernel<<<dim3(16, 16, 16), 256, 81920>>>(scale);

    // stage 3: gathered dual softmax -> fp16 probs, in place
    softmax_gather_kernel<<<dim3(2048, 8), 256>>>();

    // stage 4: AV + concat (256 CTAs, 2-term fp16)
    av_mma_kernel<<<dim3(1, 16, 16), 256, 40960>>>(out);
}

// round 8
// speedup vs baseline: 1.8045x; 1.0685x over previous
#include <cuda_runtime.h>
#include <cuda_bf16.h>
#include <cuda_fp16.h>
#include <cstdint>

#define N_TOK 2048
#define NN (8LL * 2048 * 2048)

typedef __nv_bfloat16 bf16;

__device__ __forceinline__ uint32_t smem_to_u32(const void* p) {
    uint32_t a;
    asm("{ .reg .u64 t; cvta.to.shared.u64 t, %1; cvt.u32.u64 %0, t; }" : "=r"(a) : "l"(p));
    return a;
}

__device__ __forceinline__ void ldmatrix_x4(uint32_t& r0, uint32_t& r1, uint32_t& r2,
                                            uint32_t& r3, uint32_t addr) {
    asm volatile("ldmatrix.sync.aligned.m8n8.x4.shared.b16 {%0,%1,%2,%3}, [%4];"
                 : "=r"(r0), "=r"(r1), "=r"(r2), "=r"(r3) : "r"(addr));
}

__device__ __forceinline__ void mma16816(float c[4], const uint32_t a[4], const uint32_t b[2]) {
    asm volatile(
        "mma.sync.aligned.m16n8k16.row.col.f32.bf16.bf16.f32 "
        "{%0,%1,%2,%3}, {%4,%5,%6,%7}, {%8,%9}, {%0,%1,%2,%3};"
        : "+f"(c[0]), "+f"(c[1]), "+f"(c[2]), "+f"(c[3])
        : "r"(a[0]), "r"(a[1]), "r"(a[2]), "r"(a[3]), "r"(b[0]), "r"(b[1]));
}

__device__ __forceinline__ void mma16816h(float c[4], const uint32_t a[4], const uint32_t b[2]) {
    asm volatile(
        "mma.sync.aligned.m16n8k16.row.col.f32.f16.f16.f32 "
        "{%0,%1,%2,%3}, {%4,%5,%6,%7}, {%8,%9}, {%0,%1,%2,%3};"
        : "+f"(c[0]), "+f"(c[1]), "+f"(c[2]), "+f"(c[3])
        : "r"(a[0]), "r"(a[1]), "r"(a[2]), "r"(a[3]), "r"(b[0]), "r"(b[1]));
}

#define CP_ASYNC_CG(smem_addr, gmem_ptr) \
    asm volatile("cp.async.cg.shared.global [%0], [%1], 16;" \
                 :: "r"(smem_addr), "l"(gmem_ptr))
#define CP_ASYNC_COMMIT() asm volatile("cp.async.commit_group;" ::: "memory")
#define CP_ASYNC_WAIT(n)  asm volatile("cp.async.wait_group %0;" :: "n"(n) : "memory")

// ============================ device scratch ============================
__device__ __align__(16) bf16 g_Xh[2048 * 1024];
__device__ __align__(16) bf16 g_Xl[2048 * 1024];
__device__ __align__(16) bf16 g_WTh[5242880];   // q1,k1,q2,k2 (1M each) + v1,v2 (512K each), [N,K]
__device__ __align__(16) bf16 g_WTl[5242880];
__device__ __align__(16) __half g_Qs[2][2048 * 1024];  // Q single fp16 per mat
__device__ __align__(16) __half g_Kh[2][2048 * 1024];  // K fp16 hi
__device__ __align__(16) __half g_Kl[2][2048 * 1024];  // K fp16 lo
__device__ __align__(16) __half g_VTh[1024 * 2048];    // fp16 V hi, rows: mat*512+vcol, cols: token
__device__ __align__(16) __half g_VTl[1024 * 2048];
__device__ __align__(16) float g_S1[NN];   // rows of 2048: fp16 scores then fp16 probs in first half
__device__ __align__(16) float g_S2[NN];
__device__ __align__(16) bf16 g_M1[2048LL * 2048];           // transposed masks, bf16 (exact)
__device__ __align__(16) bf16 g_M2[2048LL * 2048];
__device__ __align__(16) unsigned short g_I1[2048LL * 2048]; // c2n as u16
__device__ __align__(16) unsigned short g_I2[2048LL * 2048]; // n2c as u16

// ============================ conversion kernels ============================
__global__ __launch_bounds__(256) void convx_kernel(const float* __restrict__ x) {
    int i = (blockIdx.x * 256 + threadIdx.x) * 4;
    float4 v = *(const float4*)(x + i);
    float vv[4] = {v.x, v.y, v.z, v.w};
    bf16 h[4], l[4];
#pragma unroll
    for (int j = 0; j < 4; j++) {
        h[j] = __float2bfloat16(vv[j]);
        l[j] = __float2bfloat16(vv[j] - __bfloat162float(h[j]));
    }
    *(uint2*)&g_Xh[i] = *(uint2*)h;
    *(uint2*)&g_Xl[i] = *(uint2*)l;
}

__global__ __launch_bounds__(256)
void convw_kernel(const float* __restrict__ w0, const float* __restrict__ w1,
                  const float* __restrict__ w2, const float* __restrict__ w3,
                  const float* __restrict__ w4, const float* __restrict__ w5) {
    int z = blockIdx.z;
    const float* W;
    int Ncols;
    long long base;
    switch (z) {
        case 0: W = w0; Ncols = 1024; base = 0; break;
        case 1: W = w1; Ncols = 1024; base = 1048576; break;
        case 2: W = w2; Ncols = 1024; base = 2097152; break;
        case 3: W = w3; Ncols = 1024; base = 3145728; break;
        case 4: W = w4; Ncols = 512;  base = 4194304; break;
        default:W = w5; Ncols = 512;  base = 4718592; break;
    }
    int bn = blockIdx.x * 32, bk = blockIdx.y * 32;
    if (bn >= Ncols) return;
    __shared__ float t[32][33];
#pragma unroll
    for (int i = threadIdx.y; i < 32; i += 8)
        t[i][threadIdx.x] = W[(long long)(bk + i) * Ncols + bn + threadIdx.x];
    __syncthreads();
#pragma unroll
    for (int i = threadIdx.y; i < 32; i += 8) {
        float v = t[threadIdx.x][i];
        bf16 hh = __float2bfloat16(v);
        long long o = base + (long long)(bn + i) * 1024 + bk + threadIdx.x;
        g_WTh[o] = hh;
        g_WTl[o] = __float2bfloat16(v - __bfloat162float(hh));
    }
}

// masks transposed -> bf16 (values {0,-1e4} exact)
__global__ void mask_transpose_kernel(const float* __restrict__ G1,
                                      const float* __restrict__ G2) {
    __shared__ float t1[32][33];
    __shared__ float t2[32][33];
    int bx = blockIdx.x * 32;
    int by = blockIdx.y * 32;
    int x = bx + threadIdx.x;
#pragma unroll
    for (int i = threadIdx.y; i < 32; i += 8) {
        t1[i][threadIdx.x] = G1[(long long)(by + i) * N_TOK + x];
        t2[i][threadIdx.x] = G2[(long long)(by + i) * N_TOK + x];
    }
    __syncthreads();
    int ox = by + threadIdx.x;
#pragma unroll
    for (int i = threadIdx.y; i < 32; i += 8) {
        g_M1[(long long)(bx + i) * N_TOK + ox] =
            __float2bfloat16((t1[threadIdx.x][i] - 1.f) * 10000.f);
        g_M2[(long long)(bx + i) * N_TOK + ox] =
            __float2bfloat16((t2[threadIdx.x][i] - 1.f) * 10000.f);
    }
}

// indices int32 -> uint16
__global__ __launch_bounds__(256)
void convidx_kernel(const int* __restrict__ c2n, const int* __restrict__ n2c) {
    long long i = ((long long)blockIdx.x * 256 + threadIdx.x) * 4;
    int4 a = *(const int4*)(c2n + i);
    int4 b = *(const int4*)(n2c + i);
    ushort4 ua = make_ushort4((unsigned short)a.x, (unsigned short)a.y,
                              (unsigned short)a.z, (unsigned short)a.w);
    ushort4 ub = make_ushort4((unsigned short)b.x, (unsigned short)b.y,
                              (unsigned short)b.z, (unsigned short)b.w);
    *(ushort4*)&g_I1[i] = ua;
    *(ushort4*)&g_I2[i] = ub;
}

// ============================ pipelined 3-term bf16 GEMM body (proj) ============================
template <int BN, int WM, int WN>
__device__ __forceinline__ void gemm_mma(
    const bf16* __restrict__ aH, const bf16* __restrict__ aL, int lda,
    const bf16* __restrict__ bH, const bf16* __restrict__ bL, int ldb,
    int K, float acc[128 / (WM * 16)][4][4])
{
    constexpr int MI = 128 / (WM * 16);
    constexpr int OFF_AL = 10240;
    constexpr int OFF_BH = 20480;
    constexpr int OFF_BL = 20480 + BN * 80;
    constexpr int STG = 20480 + BN * 160;
    extern __shared__ __align__(16) char sm[];
    const uint32_t smb = smem_to_u32(sm);
    const int tid = threadIdx.x;
    const int wid = tid >> 5, lane = tid & 31;
    const int wm = (wid / WN) * (MI * 16);
    const int wn = (wid % WN) * 32;
    const int a_row = wm + (lane & 7) + ((lane >> 3) & 1) * 8;
    const int a_cofs = (lane >> 4) * 8;
    const int b_row = wn + (lane & 7) + ((lane >> 4) & 1) * 8;
    const int b_cofs = ((lane >> 3) & 1) * 8;

    const int r_cp = tid >> 2;
    const int c_cp = (tid & 3) * 8;
    const int NC = K >> 5;

    auto issue_stage = [&](int ic) {
        const uint32_t sb = smb + (uint32_t)(ic & 1) * STG;
        const int k0 = ic * 32;
#pragma unroll
        for (int i = 0; i < 2; i++) {
            int r = r_cp + i * 64;
            uint32_t so = (uint32_t)(r * 80 + c_cp * 2);
            CP_ASYNC_CG(sb + so, aH + r * lda + k0 + c_cp);
            CP_ASYNC_CG(sb + OFF_AL + so, aL + r * lda + k0 + c_cp);
        }
#pragma unroll
        for (int i = 0; i < BN / 64; i++) {
            int r = r_cp + i * 64;
            uint32_t so = (uint32_t)(r * 80 + c_cp * 2);
            CP_ASYNC_CG(sb + OFF_BH + so, bH + r * ldb + k0 + c_cp);
            CP_ASYNC_CG(sb + OFF_BL + so, bL + r * ldb + k0 + c_cp);
        }
        CP_ASYNC_COMMIT();
    };

    issue_stage(0);
    for (int ic = 0; ic < NC; ic++) {
        if (ic + 1 < NC) { issue_stage(ic + 1); CP_ASYNC_WAIT(1); }
        else             { CP_ASYNC_WAIT(0); }
        __syncthreads();
        const uint32_t sb = smb + (uint32_t)(ic & 1) * STG;
#pragma unroll
        for (int ks = 0; ks < 32; ks += 16) {
            uint32_t ah[MI][4], al[MI][4], bh[4][2], bl[4][2];
#pragma unroll
            for (int mi = 0; mi < MI; mi++) {
                uint32_t off = (uint32_t)(((a_row + mi * 16) * 40 + ks + a_cofs) * 2);
                ldmatrix_x4(ah[mi][0], ah[mi][1], ah[mi][2], ah[mi][3], sb + off);
                ldmatrix_x4(al[mi][0], al[mi][1], al[mi][2], al[mi][3], sb + OFF_AL + off);
            }
#pragma unroll
            for (int nj = 0; nj < 2; nj++) {
                uint32_t off = (uint32_t)(((b_row + nj * 16) * 40 + ks + b_cofs) * 2);
                ldmatrix_x4(bh[nj * 2][0], bh[nj * 2][1], bh[nj * 2 + 1][0], bh[nj * 2 + 1][1],
                            sb + OFF_BH + off);
                ldmatrix_x4(bl[nj * 2][0], bl[nj * 2][1], bl[nj * 2 + 1][0], bl[nj * 2 + 1][1],
                            sb + OFF_BL + off);
            }
#pragma unroll
            for (int mi = 0; mi < MI; mi++)
#pragma unroll
                for (int ni = 0; ni < 4; ni++) {
                    mma16816(acc[mi][ni], ah[mi], bh[ni]);
                    mma16816(acc[mi][ni], ah[mi], bl[ni]);
                    mma16816(acc[mi][ni], al[mi], bh[ni]);
                }
        }
        __syncthreads();
    }
}

// ============================ 2-term fp16 score GEMM body ============================
// acc[4][4][4] += Q(128,K) * (Kh+Kl)(128,K)^T. Q single fp16, K fp16 hi/lo.
// Warp grid 2x4. Stage: [A 10240 | Bh 10240 | Bl 10240], STG=30720.
__device__ __forceinline__ void gemm_score(
    const __half* __restrict__ aQ, int lda,
    const __half* __restrict__ bH, const __half* __restrict__ bL, int ldb,
    int K, float acc[4][4][4])
{
    constexpr int OFF_BH = 10240;
    constexpr int OFF_BL = 20480;
    constexpr int STG = 30720;
    extern __shared__ __align__(16) char sm[];
    const uint32_t smb = smem_to_u32(sm);
    const int tid = threadIdx.x;
    const int wid = tid >> 5, lane = tid & 31;
    const int wm = (wid >> 2) * 64;
    const int wn = (wid & 3) * 32;
    const int a_row = wm + (lane & 7) + ((lane >> 3) & 1) * 8;
    const int a_cofs = (lane >> 4) * 8;
    const int b_row = wn + (lane & 7) + ((lane >> 4) & 1) * 8;
    const int b_cofs = ((lane >> 3) & 1) * 8;

    const int r_cp = tid >> 2;
    const int c_cp = (tid & 3) * 8;
    const int NC = K >> 5;

    auto issue_stage = [&](int ic) {
        const uint32_t sb = smb + (uint32_t)(ic & 1) * STG;
        const int k0 = ic * 32;
#pragma unroll
        for (int i = 0; i < 2; i++) {
            int r = r_cp + i * 64;
            uint32_t so = (uint32_t)(r * 80 + c_cp * 2);
            CP_ASYNC_CG(sb + so, aQ + (long long)r * lda + k0 + c_cp);
            CP_ASYNC_CG(sb + OFF_BH + so, bH + (long long)r * ldb + k0 + c_cp);
            CP_ASYNC_CG(sb + OFF_BL + so, bL + (long long)r * ldb + k0 + c_cp);
        }
        CP_ASYNC_COMMIT();
    };

    issue_stage(0);
    for (int ic = 0; ic < NC; ic++) {
        if (ic + 1 < NC) { issue_stage(ic + 1); CP_ASYNC_WAIT(1); }
        else             { CP_ASYNC_WAIT(0); }
        __syncthreads();
        const uint32_t sb = smb + (uint32_t)(ic & 1) * STG;
#pragma unroll
        for (int ks = 0; ks < 32; ks += 16) {
            uint32_t aq[4][4], bh[4][2], bl[4][2];
#pragma unroll
            for (int mi = 0; mi < 4; mi++) {
                uint32_t off = (uint32_t)(((a_row + mi * 16) * 40 + ks + a_cofs) * 2);
                ldmatrix_x4(aq[mi][0], aq[mi][1], aq[mi][2], aq[mi][3], sb + off);
            }
#pragma unroll
            for (int nj = 0; nj < 2; nj++) {
                uint32_t off = (uint32_t)(((b_row + nj * 16) * 40 + ks + b_cofs) * 2);
                ldmatrix_x4(bh[nj * 2][0], bh[nj * 2][1], bh[nj * 2 + 1][0], bh[nj * 2 + 1][1],
                            sb + OFF_BH + off);
                ldmatrix_x4(bl[nj * 2][0], bl[nj * 2][1], bl[nj * 2 + 1][0], bl[nj * 2 + 1][1],
                            sb + OFF_BL + off);
            }
#pragma unroll
            for (int mi = 0; mi < 4; mi++)
#pragma unroll
                for (int ni = 0; ni < 4; ni++) {
                    mma16816h(acc[mi][ni], aq[mi], bh[ni]);
                    mma16816h(acc[mi][ni], aq[mi], bl[ni]);
                }
        }
        __syncthreads();
    }
}

// ============================ 2-term fp16 AV GEMM body ============================
__device__ __forceinline__ void gemm_av(
    const __half* __restrict__ aP, int lda,
    const __half* __restrict__ bH, const __half* __restrict__ bL, int ldb,
    int K, float acc[2][4][4])
{
    constexpr int OFF_BH = 10240;
    constexpr int OFF_BL = 15360;
    constexpr int STG = 20480;
    extern __shared__ __align__(16) char sm[];
    const uint32_t smb = smem_to_u32(sm);
    const int tid = threadIdx.x;
    const int wid = tid >> 5, lane = tid & 31;
    const int wm = (wid >> 1) * 32;
    const int wn = (wid & 1) * 32;
    const int a_row = wm + (lane & 7) + ((lane >> 3) & 1) * 8;
    const int a_cofs = (lane >> 4) * 8;
    const int b_row = wn + (lane & 7) + ((lane >> 4) & 1) * 8;
    const int b_cofs = ((lane >> 3) & 1) * 8;

    const int r_cp = tid >> 2;
    const int c_cp = (tid & 3) * 8;
    const int NC = K >> 5;

    auto issue_stage = [&](int ic) {
        const uint32_t sb = smb + (uint32_t)(ic & 1) * STG;
        const int k0 = ic * 32;
#pragma unroll
        for (int i = 0; i < 2; i++) {
            int r = r_cp + i * 64;
            uint32_t so = (uint32_t)(r * 80 + c_cp * 2);
            CP_ASYNC_CG(sb + so, aP + (long long)r * lda + k0 + c_cp);
        }
        {
            int r = r_cp;
            uint32_t so = (uint32_t)(r * 80 + c_cp * 2);
            CP_ASYNC_CG(sb + OFF_BH + so, bH + (long long)r * ldb + k0 + c_cp);
            CP_ASYNC_CG(sb + OFF_BL + so, bL + (long long)r * ldb + k0 + c_cp);
        }
        CP_ASYNC_COMMIT();
    };

    issue_stage(0);
    for (int ic = 0; ic < NC; ic++) {
        if (ic + 1 < NC) { issue_stage(ic + 1); CP_ASYNC_WAIT(1); }
        else             { CP_ASYNC_WAIT(0); }
        __syncthreads();
        const uint32_t sb = smb + (uint32_t)(ic & 1) * STG;
#pragma unroll
        for (int ks = 0; ks < 32; ks += 16) {
            uint32_t ap[2][4], bh[4][2], bl[4][2];
#pragma unroll
            for (int mi = 0; mi < 2; mi++) {
                uint32_t off = (uint32_t)(((a_row + mi * 16) * 40 + ks + a_cofs) * 2);
                ldmatrix_x4(ap[mi][0], ap[mi][1], ap[mi][2], ap[mi][3], sb + off);
            }
#pragma unroll
            for (int nj = 0; nj < 2; nj++) {
                uint32_t off = (uint32_t)(((b_row + nj * 16) * 40 + ks + b_cofs) * 2);
                ldmatrix_x4(bh[nj * 2][0], bh[nj * 2][1], bh[nj * 2 + 1][0], bh[nj * 2 + 1][1],
                            sb + OFF_BH + off);
                ldmatrix_x4(bl[nj * 2][0], bl[nj * 2][1], bl[nj * 2 + 1][0], bl[nj * 2 + 1][1],
                            sb + OFF_BL + off);
            }
#pragma unroll
            for (int mi = 0; mi < 2; mi++)
#pragma unroll
                for (int ni = 0; ni < 4; ni++) {
                    mma16816h(acc[mi][ni], ap[mi], bh[ni]);
                    mma16816h(acc[mi][ni], ap[mi], bl[ni]);
                }
        }
        __syncthreads();
    }
}

// ============================ stage 1: projections ============================
__global__ __launch_bounds__(256, 2)
void proj_mma_kernel(const float* __restrict__ bq1, const float* __restrict__ bk1,
                     const float* __restrict__ bv1, const float* __restrict__ bq2,
                     const float* __restrict__ bk2, const float* __restrict__ bv2)
{
    const int cb = blockIdx.x;
    const int bm = blockIdx.y * 128;
    const bf16 *bH, *bL;
    const float* bias;
    int r, bnl;
    if (cb < 32) {
        r = cb >> 3; bnl = (cb & 7) * 128;
        long long wo = (long long)r * 1048576 + (long long)bnl * 1024;
        bH = g_WTh + wo; bL = g_WTl + wo;
        bias = (r == 0) ? bq1 : (r == 1) ? bk1 : (r == 2) ? bq2 : bk2;
    } else {
        r = (cb - 32) >> 2; bnl = ((cb - 32) & 3) * 128;
        long long wo = 4194304LL + (long long)r * 524288 + (long long)bnl * 1024;
        bH = g_WTh + wo; bL = g_WTl + wo;
        bias = r ? bv2 : bv1;
    }
    float acc[4][4][4];
#pragma unroll
    for (int a = 0; a < 4; a++)
#pragma unroll
        for (int b = 0; b < 4; b++)
#pragma unroll
            for (int c = 0; c < 4; c++) acc[a][b][c] = 0.f;

    gemm_mma<128, 2, 4>(g_Xh + (long long)bm * 1024, g_Xl + (long long)bm * 1024, 1024,
                        bH, bL, 1024, 1024, acc);

    const int wid = threadIdx.x >> 5, lane = threadIdx.x & 31;
    const int g = lane >> 2, t = lane & 3;
    const int wm = (wid >> 2) * 64, wn = (wid & 3) * 32;
#pragma unroll
    for (int mi = 0; mi < 4; mi++) {
        int m0 = bm + wm + mi * 16 + g;
#pragma unroll
        for (int ni = 0; ni < 4; ni++) {
            int col = bnl + wn + ni * 8 + 2 * t;
            float b0 = bias[col], b1 = bias[col + 1];
            float v00 = acc[mi][ni][0] + b0, v01 = acc[mi][ni][1] + b1;
            float v10 = acc[mi][ni][2] + b0, v11 = acc[mi][ni][3] + b1;
            if (cb < 32) {
                int mat = r >> 1;
                long long o0 = (long long)m0 * 1024 + col;
                long long o1 = (long long)(m0 + 8) * 1024 + col;
                if ((r & 1) == 0) {
                    // Q: single fp16
                    *(__half2*)&g_Qs[mat][o0] =
                        __halves2half2(__float2half_rn(v00), __float2half_rn(v01));
                    *(__half2*)&g_Qs[mat][o1] =
                        __halves2half2(__float2half_rn(v10), __float2half_rn(v11));
                } else {
                    // K: fp16 hi/lo
                    __half h00 = __float2half_rn(v00), h01 = __float2half_rn(v01);
                    __half h10 = __float2half_rn(v10), h11 = __float2half_rn(v11);
                    __half l00 = __float2half_rn(v00 - __half2float(h00));
                    __half l01 = __float2half_rn(v01 - __half2float(h01));
                    __half l10 = __float2half_rn(v10 - __half2float(h10));
                    __half l11 = __float2half_rn(v11 - __half2float(h11));
                    *(__half2*)&g_Kh[mat][o0] = __halves2half2(h00, h01);
                    *(__half2*)&g_Kl[mat][o0] = __halves2half2(l00, l01);
                    *(__half2*)&g_Kh[mat][o1] = __halves2half2(h10, h11);
                    *(__half2*)&g_Kl[mat][o1] = __halves2half2(l10, l11);
                }
            } else {
                __half h00 = __float2half_rn(v00), h01 = __float2half_rn(v01);
                __half h10 = __float2half_rn(v10), h11 = __float2half_rn(v11);
                __half l00 = __float2half_rn(v00 - __half2float(h00));
                __half l01 = __float2half_rn(v01 - __half2float(h01));
                __half l10 = __float2half_rn(v10 - __half2float(h10));
                __half l11 = __float2half_rn(v11 - __half2float(h11));
                int c0 = r * 512 + col, c1 = c0 + 1;
                g_VTh[(long long)c0 * 2048 + m0] = h00;
                g_VTh[(long long)c1 * 2048 + m0] = h01;
                g_VTh[(long long)c0 * 2048 + m0 + 8] = h10;
                g_VTh[(long long)c1 * 2048 + m0 + 8] = h11;
                g_VTl[(long long)c0 * 2048 + m0] = l00;
                g_VTl[(long long)c1 * 2048 + m0] = l01;
                g_VTl[(long long)c0 * 2048 + m0 + 8] = l10;
                g_VTl[(long long)c1 * 2048 + m0 + 8] = l11;
            }
        }
    }
}

// ============================ stage 2: scores (2-term fp16, fp16 output) ============================
__global__ __launch_bounds__(256, 2)
void score_mma_kernel(float scale)
{
    const int z = blockIdx.z, mat = z >> 3, h = z & 7;
    const int bm = blockIdx.y * 128, bn = blockIdx.x * 128;
    const __half* q = g_Qs[mat] + (long long)bm * 1024 + h * 128;
    const __half* kh = g_Kh[mat] + (long long)bn * 1024 + h * 128;
    const __half* kl = g_Kl[mat] + (long long)bn * 1024 + h * 128;

    float acc[4][4][4];
#pragma unroll
    for (int a = 0; a < 4; a++)
#pragma unroll
        for (int b = 0; b < 4; b++)
#pragma unroll
            for (int c = 0; c < 4; c++) acc[a][b][c] = 0.f;

    gemm_score(q, 1024, kh, kl, 1024, 128, acc);

    __half* S = reinterpret_cast<__half*>((mat ? g_S2 : g_S1)) ;
    const int wid = threadIdx.x >> 5, lane = threadIdx.x & 31;
    const int g = lane >> 2, t = lane & 3;
    const int wm = (wid >> 2) * 64, wn = (wid & 3) * 32;
    const long long hbase = (long long)h * N_TOK * 4096;  // half-granularity row stride 4096
#pragma unroll
    for (int mi = 0; mi < 4; mi++) {
        int m0 = bm + wm + mi * 16 + g;
#pragma unroll
        for (int ni = 0; ni < 4; ni++) {
            int n0 = bn + wn + ni * 8 + 2 * t;
            *(__half2*)&S[hbase + (long long)m0 * 4096 + n0] =
                __halves2half2(__float2half_rn(acc[mi][ni][0] * scale),
                               __float2half_rn(acc[mi][ni][1] * scale));
            *(__half2*)&S[hbase + (long long)(m0 + 8) * 4096 + n0] =
                __halves2half2(__float2half_rn(acc[mi][ni][2] * scale),
                               __float2half_rn(acc[mi][ni][3] * scale));
        }
    }
}

// ============================ stage 3: dual gathered softmax ============================
__device__ __forceinline__ float warpRedMax(float v) {
#pragma unroll
    for (int o = 16; o > 0; o >>= 1) v = fmaxf(v, __shfl_xor_sync(0xffffffffu, v, o));
    return v;
}
__device__ __forceinline__ float warpRedSum(float v) {
#pragma unroll
    for (int o = 16; o > 0; o >>= 1) v += __shfl_xor_sync(0xffffffffu, v, o);
    return v;
}

__global__ __launch_bounds__(256)
void softmax_gather_kernel()
{
    const int n = blockIdx.x;
    const int h = blockIdx.y;
    __half* s1row = reinterpret_cast<__half*>(g_S1) + ((long long)h * N_TOK + n) * 4096;
    __half* s2row = reinterpret_cast<__half*>(g_S2) + ((long long)h * N_TOK + n) * 4096;
    __shared__ float sh1[N_TOK];
    __shared__ float sh2[N_TOK];
    __shared__ float red[32];
    const int tid = threadIdx.x;
    const int lane = tid & 31, wid = tid >> 5;

    // load fp16 score rows into fp32 smem (one uint4 = 8 halfs per thread)
    {
        uint4 v1 = *(const uint4*)(s1row + tid * 8);
        uint4 v2 = *(const uint4*)(s2row + tid * 8);
        const __half2* p1 = (const __half2*)&v1;
        const __half2* p2 = (const __half2*)&v2;
#pragma unroll
        for (int j = 0; j < 4; j++) {
            float2 f1 = __half22float2(p1[j]);
            float2 f2 = __half22float2(p2[j]);
            sh1[tid * 8 + 2 * j] = f1.x;
            sh1[tid * 8 + 2 * j + 1] = f1.y;
            sh2[tid * 8 + 2 * j] = f2.x;
            sh2[tid * 8 + 2 * j + 1] = f2.y;
        }
    }
    __syncthreads();

    const unsigned short* c2nrow = g_I1 + (long long)n * N_TOK;
    const unsigned short* n2crow = g_I2 + (long long)n * N_TOK;
    const bf16* m1row = g_M1 + (long long)n * N_TOK;
    const bf16* m2row = g_M2 + (long long)n * N_TOK;

    float z1[8], z2[8];
    float mx1 = -1e30f, mx2 = -1e30f;
#pragma unroll
    for (int i = 0; i < 8; i++) {
        int m = tid + i * 256;
        z1[i] = sh1[m] + sh2[c2nrow[m]] + __bfloat162float(m1row[m]);
        z2[i] = sh2[m] + sh1[n2crow[m]] + __bfloat162float(m2row[m]);
        mx1 = fmaxf(mx1, z1[i]);
        mx2 = fmaxf(mx2, z2[i]);
    }
    mx1 = warpRedMax(mx1);
    mx2 = warpRedMax(mx2);
    if (lane == 0) { red[wid] = mx1; red[wid + 8] = mx2; }
    __syncthreads();
    if (wid == 0) {
        float a = (lane < 8) ? red[lane] : -1e30f;
        float b = (lane < 8) ? red[lane + 8] : -1e30f;
        a = warpRedMax(a);
        b = warpRedMax(b);
        if (lane == 0) { red[16] = a; red[17] = b; }
    }
    __syncthreads();
    mx1 = red[16];
    mx2 = red[17];

    float sum1 = 0.f, sum2 = 0.f;
#pragma unroll
    for (int i = 0; i < 8; i++) {
        z1[i] = __expf(z1[i] - mx1);
        z2[i] = __expf(z2[i] - mx2);
        sum1 += z1[i];
        sum2 += z2[i];
    }
    sum1 = warpRedSum(sum1);
    sum2 = warpRedSum(sum2);
    __syncthreads();
    if (lane == 0) { red[wid] = sum1; red[wid + 8] = sum2; }
    __syncthreads();
    if (wid == 0) {
        float a = (lane < 8) ? red[lane] : 0.f;
        float b = (lane < 8) ? red[lane + 8] : 0.f;
        a = warpRedSum(a);
        b = warpRedSum(b);
        if (lane == 0) { red[16] = a; red[17] = b; }
    }
    __syncthreads();
    float inv1 = 1.f / red[16];
    float inv2 = 1.f / red[17];
#pragma unroll
    for (int i = 0; i < 8; i++) {
        int m = tid + i * 256;
        s1row[m] = __float2half_rn(z1[i] * inv1);
        s2row[m] = __float2half_rn(z2[i] * inv2);
    }
}

// ============================ stage 4: AV + concat (2-term fp16) ============================
__global__ __launch_bounds__(256, 2)
void av_mma_kernel(float* __restrict__ out)
{
    const int z = blockIdx.z, mat = z >> 3, h = z & 7;
    const int bm = blockIdx.y * 128;
    const __half* Ab = reinterpret_cast<const __half*>(mat ? g_S2 : g_S1);
    const __half* aP = Ab + ((long long)h * N_TOK + bm) * 4096;
    const __half* bH = g_VTh + (long long)(mat * 512 + h * 64) * 2048;
    const __half* bL = g_VTl + (long long)(mat * 512 + h * 64) * 2048;

    float acc[2][4][4];
#pragma unroll
    for (int a = 0; a < 2; a++)
#pragma unroll
        for (int b = 0; b < 4; b++)
#pragma unroll
            for (int c = 0; c < 4; c++) acc[a][b][c] = 0.f;

    gemm_av(aP, 4096, bH, bL, 2048, 2048, acc);

    const int wid = threadIdx.x >> 5, lane = threadIdx.x & 31;
    const int g = lane >> 2, t = lane & 3;
    const int wm = (wid >> 1) * 32, wn = (wid & 1) * 32;
    const int cbase = mat * 512 + h * 64;
#pragma unroll
    for (int mi = 0; mi < 2; mi++) {
        int m0 = bm + wm + mi * 16 + g;
#pragma unroll
        for (int ni = 0; ni < 4; ni++) {
            int col = cbase + wn + ni * 8 + 2 * t;
            *(float2*)(out + (long long)m0 * 1024 + col) =
                make_float2(acc[mi][ni][0], acc[mi][ni][1]);
            *(float2*)(out + (long long)(m0 + 8) * 1024 + col) =
                make_float2(acc[mi][ni][2], acc[mi][ni][3]);
        }
    }
}

// ============================ launch ============================
extern "C" void kernel_launch(void* const* d_in, const int* in_sizes, int n_in,
                              void* d_out, int out_size)
{
    const float* x   = (const float*)d_in[0];
    const float* fst = (const float*)d_in[1];
    const float* sec = (const float*)d_in[2];
    const int*   n2c = (const int*)d_in[3];
    const int*   c2n = (const int*)d_in[4];
    const float* Wq1 = (const float*)d_in[5];
    const float* bq1 = (const float*)d_in[6];
    const float* Wk1 = (const float*)d_in[7];
    const float* bk1 = (const float*)d_in[8];
    const float* Wv1 = (const float*)d_in[9];
    const float* bv1 = (const float*)d_in[10];
    const float* Wq2 = (const float*)d_in[11];
    const float* bq2 = (const float*)d_in[12];
    const float* Wk2 = (const float*)d_in[13];
    const float* bk2 = (const float*)d_in[14];
    const float* Wv2 = (const float*)d_in[15];
    const float* bv2 = (const float*)d_in[16];
    float* out = (float*)d_out;

    static bool attr_set = false;
    if (!attr_set) {
        cudaFuncSetAttribute(proj_mma_kernel, cudaFuncAttributeMaxDynamicSharedMemorySize, 81920);
        cudaFuncSetAttribute(score_mma_kernel, cudaFuncAttributeMaxDynamicSharedMemorySize, 61440);
        cudaFuncSetAttribute(av_mma_kernel, cudaFuncAttributeMaxDynamicSharedMemorySize, 40960);
        attr_set = true;
    }

    // stage 0: transposed bf16 masks + u16 indices + bf16 split conversions
    mask_transpose_kernel<<<dim3(64, 64), dim3(32, 8)>>>(fst, sec);
    convidx_kernel<<<4096, 256>>>(c2n, n2c);
    convx_kernel<<<2048, 256>>>(x);
    convw_kernel<<<dim3(32, 32, 6), dim3(32, 8)>>>(Wq1, Wk1, Wq2, Wk2, Wv1, Wv2);

    // stage 1: projections (640 CTAs, 3-term bf16)
    proj_mma_kernel<<<dim3(40, 16), 256, 81920>>>(bq1, bk1, bv1, bq2, bk2, bv2);

    // stage 2: scores (4096 CTAs, 2-term fp16, fp16 output)
    const float scale = 0.08838834764831845f;  // 1/sqrt(128)
    score_mma_kernel<<<dim3(16, 16, 16), 256, 61440>>>(scale);

    // stage 3: gathered dual softmax -> fp16 probs, in place
    softmax_gather_kernel<<<dim3(2048, 8), 256>>>();

    // stage 4: AV + concat (256 CTAs, 2-term fp16)
    av_mma_kernel<<<dim3(1, 16, 16), 256, 40960>>>(out);
}

// round 9
// speedup vs baseline: 2.0625x; 1.1430x over previous
#include <cuda_runtime.h>
#include <cuda_bf16.h>
#include <cuda_fp16.h>
#include <cstdint>

#define N_TOK 2048
#define NN (8LL * 2048 * 2048)

typedef __nv_bfloat16 bf16;

__device__ __forceinline__ uint32_t smem_to_u32(const void* p) {
    uint32_t a;
    asm("{ .reg .u64 t; cvta.to.shared.u64 t, %1; cvt.u32.u64 %0, t; }" : "=r"(a) : "l"(p));
    return a;
}

__device__ __forceinline__ void ldmatrix_x4(uint32_t& r0, uint32_t& r1, uint32_t& r2,
                                            uint32_t& r3, uint32_t addr) {
    asm volatile("ldmatrix.sync.aligned.m8n8.x4.shared.b16 {%0,%1,%2,%3}, [%4];"
                 : "=r"(r0), "=r"(r1), "=r"(r2), "=r"(r3) : "r"(addr));
}

__device__ __forceinline__ void mma16816h(float c[4], const uint32_t a[4], const uint32_t b[2]) {
    asm volatile(
        "mma.sync.aligned.m16n8k16.row.col.f32.f16.f16.f32 "
        "{%0,%1,%2,%3}, {%4,%5,%6,%7}, {%8,%9}, {%0,%1,%2,%3};"
        : "+f"(c[0]), "+f"(c[1]), "+f"(c[2]), "+f"(c[3])
        : "r"(a[0]), "r"(a[1]), "r"(a[2]), "r"(a[3]), "r"(b[0]), "r"(b[1]));
}

#define CP_ASYNC_CG(smem_addr, gmem_ptr) \
    asm volatile("cp.async.cg.shared.global [%0], [%1], 16;" \
                 :: "r"(smem_addr), "l"(gmem_ptr))
#define CP_ASYNC_COMMIT() asm volatile("cp.async.commit_group;" ::: "memory")
#define CP_ASYNC_WAIT(n)  asm volatile("cp.async.wait_group %0;" :: "n"(n) : "memory")

// ============================ device scratch ============================
__device__ __align__(16) __half g_Xs[2048 * 1024];      // X single fp16
__device__ __align__(16) __half g_WTh[5242880];          // Wᵀ fp16 hi: q1,k1,q2,k2 (1M) + v1,v2 (512K), [N,K]
__device__ __align__(16) __half g_WTl[5242880];          // Wᵀ fp16 lo
__device__ __align__(16) __half g_Qs[2][2048 * 1024];    // Q single fp16 per mat
__device__ __align__(16) __half g_Kh[2][2048 * 1024];    // K fp16 hi
__device__ __align__(16) __half g_Kl[2][2048 * 1024];    // K fp16 lo
__device__ __align__(16) __half g_VTh[1024 * 2048];      // V fp16 hi, rows: mat*512+vcol, cols: token
__device__ __align__(16) __half g_VTl[1024 * 2048];
__device__ __align__(16) float g_S1[NN];   // rows of 2048 fp32-slots: fp16 scores then fp16 probs in first half
__device__ __align__(16) float g_S2[NN];
__device__ __align__(16) bf16 g_M1[2048LL * 2048];           // transposed masks, bf16 (exact)
__device__ __align__(16) bf16 g_M2[2048LL * 2048];
__device__ __align__(16) unsigned short g_I1[2048LL * 2048]; // c2n as u16
__device__ __align__(16) unsigned short g_I2[2048LL * 2048]; // n2c as u16

// ============================ conversion kernels ============================
__global__ __launch_bounds__(256) void convx_kernel(const float* __restrict__ x) {
    int i = (blockIdx.x * 256 + threadIdx.x) * 4;
    float4 v = *(const float4*)(x + i);
    __half h[4] = {__float2half_rn(v.x), __float2half_rn(v.y),
                   __float2half_rn(v.z), __float2half_rn(v.w)};
    *(uint2*)&g_Xs[i] = *(uint2*)h;
}

__global__ __launch_bounds__(256)
void convw_kernel(const float* __restrict__ w0, const float* __restrict__ w1,
                  const float* __restrict__ w2, const float* __restrict__ w3,
                  const float* __restrict__ w4, const float* __restrict__ w5) {
    int z = blockIdx.z;
    const float* W;
    int Ncols;
    long long base;
    switch (z) {
        case 0: W = w0; Ncols = 1024; base = 0; break;
        case 1: W = w1; Ncols = 1024; base = 1048576; break;
        case 2: W = w2; Ncols = 1024; base = 2097152; break;
        case 3: W = w3; Ncols = 1024; base = 3145728; break;
        case 4: W = w4; Ncols = 512;  base = 4194304; break;
        default:W = w5; Ncols = 512;  base = 4718592; break;
    }
    int bn = blockIdx.x * 32, bk = blockIdx.y * 32;
    if (bn >= Ncols) return;
    __shared__ float t[32][33];
#pragma unroll
    for (int i = threadIdx.y; i < 32; i += 8)
        t[i][threadIdx.x] = W[(long long)(bk + i) * Ncols + bn + threadIdx.x];
    __syncthreads();
#pragma unroll
    for (int i = threadIdx.y; i < 32; i += 8) {
        float v = t[threadIdx.x][i];
        __half hh = __float2half_rn(v);
        long long o = base + (long long)(bn + i) * 1024 + bk + threadIdx.x;
        g_WTh[o] = hh;
        g_WTl[o] = __float2half_rn(v - __half2float(hh));
    }
}

// masks transposed -> bf16 (values {0,-1e4} exact)
__global__ void mask_transpose_kernel(const float* __restrict__ G1,
                                      const float* __restrict__ G2) {
    __shared__ float t1[32][33];
    __shared__ float t2[32][33];
    int bx = blockIdx.x * 32;
    int by = blockIdx.y * 32;
    int x = bx + threadIdx.x;
#pragma unroll
    for (int i = threadIdx.y; i < 32; i += 8) {
        t1[i][threadIdx.x] = G1[(long long)(by + i) * N_TOK + x];
        t2[i][threadIdx.x] = G2[(long long)(by + i) * N_TOK + x];
    }
    __syncthreads();
    int ox = by + threadIdx.x;
#pragma unroll
    for (int i = threadIdx.y; i < 32; i += 8) {
        g_M1[(long long)(bx + i) * N_TOK + ox] =
            __float2bfloat16((t1[threadIdx.x][i] - 1.f) * 10000.f);
        g_M2[(long long)(bx + i) * N_TOK + ox] =
            __float2bfloat16((t2[threadIdx.x][i] - 1.f) * 10000.f);
    }
}

// indices int32 -> uint16
__global__ __launch_bounds__(256)
void convidx_kernel(const int* __restrict__ c2n, const int* __restrict__ n2c) {
    long long i = ((long long)blockIdx.x * 256 + threadIdx.x) * 4;
    int4 a = *(const int4*)(c2n + i);
    int4 b = *(const int4*)(n2c + i);
    ushort4 ua = make_ushort4((unsigned short)a.x, (unsigned short)a.y,
                              (unsigned short)a.z, (unsigned short)a.w);
    ushort4 ub = make_ushort4((unsigned short)b.x, (unsigned short)b.y,
                              (unsigned short)b.z, (unsigned short)b.w);
    *(ushort4*)&g_I1[i] = ua;
    *(ushort4*)&g_I2[i] = ub;
}

// ============================ 2-term fp16 GEMM body (proj & score) ============================
// acc[4][4][4] += A(128,K) * (Bh+Bl)(128,K)^T. A single fp16, B fp16 hi/lo.
// Warp grid 2x4. Stage: [A 10240 | Bh 10240 | Bl 10240], STG=30720. Double-buffered.
__device__ __forceinline__ void gemm_2t(
    const __half* __restrict__ aS, int lda,
    const __half* __restrict__ bH, const __half* __restrict__ bL, int ldb,
    int K, float acc[4][4][4])
{
    constexpr int OFF_BH = 10240;
    constexpr int OFF_BL = 20480;
    constexpr int STG = 30720;
    extern __shared__ __align__(16) char sm[];
    const uint32_t smb = smem_to_u32(sm);
    const int tid = threadIdx.x;
    const int wid = tid >> 5, lane = tid & 31;
    const int wm = (wid >> 2) * 64;
    const int wn = (wid & 3) * 32;
    const int a_row = wm + (lane & 7) + ((lane >> 3) & 1) * 8;
    const int a_cofs = (lane >> 4) * 8;
    const int b_row = wn + (lane & 7) + ((lane >> 4) & 1) * 8;
    const int b_cofs = ((lane >> 3) & 1) * 8;

    const int r_cp = tid >> 2;
    const int c_cp = (tid & 3) * 8;
    const int NC = K >> 5;

    auto issue_stage = [&](int ic) {
        const uint32_t sb = smb + (uint32_t)(ic & 1) * STG;
        const int k0 = ic * 32;
#pragma unroll
        for (int i = 0; i < 2; i++) {
            int r = r_cp + i * 64;
            uint32_t so = (uint32_t)(r * 80 + c_cp * 2);
            CP_ASYNC_CG(sb + so, aS + (long long)r * lda + k0 + c_cp);
            CP_ASYNC_CG(sb + OFF_BH + so, bH + (long long)r * ldb + k0 + c_cp);
            CP_ASYNC_CG(sb + OFF_BL + so, bL + (long long)r * ldb + k0 + c_cp);
        }
        CP_ASYNC_COMMIT();
    };

    issue_stage(0);
    for (int ic = 0; ic < NC; ic++) {
        if (ic + 1 < NC) { issue_stage(ic + 1); CP_ASYNC_WAIT(1); }
        else             { CP_ASYNC_WAIT(0); }
        __syncthreads();
        const uint32_t sb = smb + (uint32_t)(ic & 1) * STG;
#pragma unroll
        for (int ks = 0; ks < 32; ks += 16) {
            uint32_t aq[4][4], bh[4][2], bl[4][2];
#pragma unroll
            for (int mi = 0; mi < 4; mi++) {
                uint32_t off = (uint32_t)(((a_row + mi * 16) * 40 + ks + a_cofs) * 2);
                ldmatrix_x4(aq[mi][0], aq[mi][1], aq[mi][2], aq[mi][3], sb + off);
            }
#pragma unroll
            for (int nj = 0; nj < 2; nj++) {
                uint32_t off = (uint32_t)(((b_row + nj * 16) * 40 + ks + b_cofs) * 2);
                ldmatrix_x4(bh[nj * 2][0], bh[nj * 2][1], bh[nj * 2 + 1][0], bh[nj * 2 + 1][1],
                            sb + OFF_BH + off);
                ldmatrix_x4(bl[nj * 2][0], bl[nj * 2][1], bl[nj * 2 + 1][0], bl[nj * 2 + 1][1],
                            sb + OFF_BL + off);
            }
#pragma unroll
            for (int mi = 0; mi < 4; mi++)
#pragma unroll
                for (int ni = 0; ni < 4; ni++) {
                    mma16816h(acc[mi][ni], aq[mi], bh[ni]);
                    mma16816h(acc[mi][ni], aq[mi], bl[ni]);
                }
        }
        __syncthreads();
    }
}

// ============================ 2-term fp16 AV GEMM body ============================
__device__ __forceinline__ void gemm_av(
    const __half* __restrict__ aP, int lda,
    const __half* __restrict__ bH, const __half* __restrict__ bL, int ldb,
    int K, float acc[2][4][4])
{
    constexpr int OFF_BH = 10240;
    constexpr int OFF_BL = 15360;
    constexpr int STG = 20480;
    extern __shared__ __align__(16) char sm[];
    const uint32_t smb = smem_to_u32(sm);
    const int tid = threadIdx.x;
    const int wid = tid >> 5, lane = tid & 31;
    const int wm = (wid >> 1) * 32;
    const int wn = (wid & 1) * 32;
    const int a_row = wm + (lane & 7) + ((lane >> 3) & 1) * 8;
    const int a_cofs = (lane >> 4) * 8;
    const int b_row = wn + (lane & 7) + ((lane >> 4) & 1) * 8;
    const int b_cofs = ((lane >> 3) & 1) * 8;

    const int r_cp = tid >> 2;
    const int c_cp = (tid & 3) * 8;
    const int NC = K >> 5;

    auto issue_stage = [&](int ic) {
        const uint32_t sb = smb + (uint32_t)(ic & 1) * STG;
        const int k0 = ic * 32;
#pragma unroll
        for (int i = 0; i < 2; i++) {
            int r = r_cp + i * 64;
            uint32_t so = (uint32_t)(r * 80 + c_cp * 2);
            CP_ASYNC_CG(sb + so, aP + (long long)r * lda + k0 + c_cp);
        }
        {
            int r = r_cp;
            uint32_t so = (uint32_t)(r * 80 + c_cp * 2);
            CP_ASYNC_CG(sb + OFF_BH + so, bH + (long long)r * ldb + k0 + c_cp);
            CP_ASYNC_CG(sb + OFF_BL + so, bL + (long long)r * ldb + k0 + c_cp);
        }
        CP_ASYNC_COMMIT();
    };

    issue_stage(0);
    for (int ic = 0; ic < NC; ic++) {
        if (ic + 1 < NC) { issue_stage(ic + 1); CP_ASYNC_WAIT(1); }
        else             { CP_ASYNC_WAIT(0); }
        __syncthreads();
        const uint32_t sb = smb + (uint32_t)(ic & 1) * STG;
#pragma unroll
        for (int ks = 0; ks < 32; ks += 16) {
            uint32_t ap[2][4], bh[4][2], bl[4][2];
#pragma unroll
            for (int mi = 0; mi < 2; mi++) {
                uint32_t off = (uint32_t)(((a_row + mi * 16) * 40 + ks + a_cofs) * 2);
                ldmatrix_x4(ap[mi][0], ap[mi][1], ap[mi][2], ap[mi][3], sb + off);
            }
#pragma unroll
            for (int nj = 0; nj < 2; nj++) {
                uint32_t off = (uint32_t)(((b_row + nj * 16) * 40 + ks + b_cofs) * 2);
                ldmatrix_x4(bh[nj * 2][0], bh[nj * 2][1], bh[nj * 2 + 1][0], bh[nj * 2 + 1][1],
                            sb + OFF_BH + off);
                ldmatrix_x4(bl[nj * 2][0], bl[nj * 2][1], bl[nj * 2 + 1][0], bl[nj * 2 + 1][1],
                            sb + OFF_BL + off);
            }
#pragma unroll
            for (int mi = 0; mi < 2; mi++)
#pragma unroll
                for (int ni = 0; ni < 4; ni++) {
                    mma16816h(acc[mi][ni], ap[mi], bh[ni]);
                    mma16816h(acc[mi][ni], ap[mi], bl[ni]);
                }
        }
        __syncthreads();
    }
}

// ============================ stage 1: projections (2-term fp16) ============================
__global__ __launch_bounds__(256, 2)
void proj_mma_kernel(const float* __restrict__ bq1, const float* __restrict__ bk1,
                     const float* __restrict__ bv1, const float* __restrict__ bq2,
                     const float* __restrict__ bk2, const float* __restrict__ bv2)
{
    const int cb = blockIdx.x;
    const int bm = blockIdx.y * 128;
    const __half *bH, *bL;
    const float* bias;
    int r, bnl;
    if (cb < 32) {
        r = cb >> 3; bnl = (cb & 7) * 128;
        long long wo = (long long)r * 1048576 + (long long)bnl * 1024;
        bH = g_WTh + wo; bL = g_WTl + wo;
        bias = (r == 0) ? bq1 : (r == 1) ? bk1 : (r == 2) ? bq2 : bk2;
    } else {
        r = (cb - 32) >> 2; bnl = ((cb - 32) & 3) * 128;
        long long wo = 4194304LL + (long long)r * 524288 + (long long)bnl * 1024;
        bH = g_WTh + wo; bL = g_WTl + wo;
        bias = r ? bv2 : bv1;
    }
    float acc[4][4][4];
#pragma unroll
    for (int a = 0; a < 4; a++)
#pragma unroll
        for (int b = 0; b < 4; b++)
#pragma unroll
            for (int c = 0; c < 4; c++) acc[a][b][c] = 0.f;

    gemm_2t(g_Xs + (long long)bm * 1024, 1024, bH, bL, 1024, 1024, acc);

    const int wid = threadIdx.x >> 5, lane = threadIdx.x & 31;
    const int g = lane >> 2, t = lane & 3;
    const int wm = (wid >> 2) * 64, wn = (wid & 3) * 32;
#pragma unroll
    for (int mi = 0; mi < 4; mi++) {
        int m0 = bm + wm + mi * 16 + g;
#pragma unroll
        for (int ni = 0; ni < 4; ni++) {
            int col = bnl + wn + ni * 8 + 2 * t;
            float b0 = bias[col], b1 = bias[col + 1];
            float v00 = acc[mi][ni][0] + b0, v01 = acc[mi][ni][1] + b1;
            float v10 = acc[mi][ni][2] + b0, v11 = acc[mi][ni][3] + b1;
            if (cb < 32) {
                int mat = r >> 1;
                long long o0 = (long long)m0 * 1024 + col;
                long long o1 = (long long)(m0 + 8) * 1024 + col;
                if ((r & 1) == 0) {
                    *(__half2*)&g_Qs[mat][o0] =
                        __halves2half2(__float2half_rn(v00), __float2half_rn(v01));
                    *(__half2*)&g_Qs[mat][o1] =
                        __halves2half2(__float2half_rn(v10), __float2half_rn(v11));
                } else {
                    __half h00 = __float2half_rn(v00), h01 = __float2half_rn(v01);
                    __half h10 = __float2half_rn(v10), h11 = __float2half_rn(v11);
                    __half l00 = __float2half_rn(v00 - __half2float(h00));
                    __half l01 = __float2half_rn(v01 - __half2float(h01));
                    __half l10 = __float2half_rn(v10 - __half2float(h10));
                    __half l11 = __float2half_rn(v11 - __half2float(h11));
                    *(__half2*)&g_Kh[mat][o0] = __halves2half2(h00, h01);
                    *(__half2*)&g_Kl[mat][o0] = __halves2half2(l00, l01);
                    *(__half2*)&g_Kh[mat][o1] = __halves2half2(h10, h11);
                    *(__half2*)&g_Kl[mat][o1] = __halves2half2(l10, l11);
                }
            } else {
                __half h00 = __float2half_rn(v00), h01 = __float2half_rn(v01);
                __half h10 = __float2half_rn(v10), h11 = __float2half_rn(v11);
                __half l00 = __float2half_rn(v00 - __half2float(h00));
                __half l01 = __float2half_rn(v01 - __half2float(h01));
                __half l10 = __float2half_rn(v10 - __half2float(h10));
                __half l11 = __float2half_rn(v11 - __half2float(h11));
                int c0 = r * 512 + col, c1 = c0 + 1;
                g_VTh[(long long)c0 * 2048 + m0] = h00;
                g_VTh[(long long)c1 * 2048 + m0] = h01;
                g_VTh[(long long)c0 * 2048 + m0 + 8] = h10;
                g_VTh[(long long)c1 * 2048 + m0 + 8] = h11;
                g_VTl[(long long)c0 * 2048 + m0] = l00;
                g_VTl[(long long)c1 * 2048 + m0] = l01;
                g_VTl[(long long)c0 * 2048 + m0 + 8] = l10;
                g_VTl[(long long)c1 * 2048 + m0 + 8] = l11;
            }
        }
    }
}

// ============================ stage 2: scores (2-term fp16, fp16 output) ============================
__global__ __launch_bounds__(256, 2)
void score_mma_kernel(float scale)
{
    const int z = blockIdx.z, mat = z >> 3, h = z & 7;
    const int bm = blockIdx.y * 128, bn = blockIdx.x * 128;
    const __half* q = g_Qs[mat] + (long long)bm * 1024 + h * 128;
    const __half* kh = g_Kh[mat] + (long long)bn * 1024 + h * 128;
    const __half* kl = g_Kl[mat] + (long long)bn * 1024 + h * 128;

    float acc[4][4][4];
#pragma unroll
    for (int a = 0; a < 4; a++)
#pragma unroll
        for (int b = 0; b < 4; b++)
#pragma unroll
            for (int c = 0; c < 4; c++) acc[a][b][c] = 0.f;

    gemm_2t(q, 1024, kh, kl, 1024, 128, acc);

    __half* S = reinterpret_cast<__half*>((mat ? g_S2 : g_S1));
    const int wid = threadIdx.x >> 5, lane = threadIdx.x & 31;
    const int g = lane >> 2, t = lane & 3;
    const int wm = (wid >> 2) * 64, wn = (wid & 3) * 32;
    const long long hbase = (long long)h * N_TOK * 4096;
#pragma unroll
    for (int mi = 0; mi < 4; mi++) {
        int m0 = bm + wm + mi * 16 + g;
#pragma unroll
        for (int ni = 0; ni < 4; ni++) {
            int n0 = bn + wn + ni * 8 + 2 * t;
            *(__half2*)&S[hbase + (long long)m0 * 4096 + n0] =
                __halves2half2(__float2half_rn(acc[mi][ni][0] * scale),
                               __float2half_rn(acc[mi][ni][1] * scale));
            *(__half2*)&S[hbase + (long long)(m0 + 8) * 4096 + n0] =
                __halves2half2(__float2half_rn(acc[mi][ni][2] * scale),
                               __float2half_rn(acc[mi][ni][3] * scale));
        }
    }
}

// ============================ stage 3: dual gathered softmax ============================
__device__ __forceinline__ float warpRedMax(float v) {
#pragma unroll
    for (int o = 16; o > 0; o >>= 1) v = fmaxf(v, __shfl_xor_sync(0xffffffffu, v, o));
    return v;
}
__device__ __forceinline__ float warpRedSum(float v) {
#pragma unroll
    for (int o = 16; o > 0; o >>= 1) v += __shfl_xor_sync(0xffffffffu, v, o);
    return v;
}

__global__ __launch_bounds__(256)
void softmax_gather_kernel()
{
    const int n = blockIdx.x;
    const int h = blockIdx.y;
    __half* s1row = reinterpret_cast<__half*>(g_S1) + ((long long)h * N_TOK + n) * 4096;
    __half* s2row = reinterpret_cast<__half*>(g_S2) + ((long long)h * N_TOK + n) * 4096;
    __shared__ float sh1[N_TOK];
    __shared__ float sh2[N_TOK];
    __shared__ float red[32];
    const int tid = threadIdx.x;
    const int lane = tid & 31, wid = tid >> 5;

    {
        uint4 v1 = *(const uint4*)(s1row + tid * 8);
        uint4 v2 = *(const uint4*)(s2row + tid * 8);
        const __half2* p1 = (const __half2*)&v1;
        const __half2* p2 = (const __half2*)&v2;
#pragma unroll
        for (int j = 0; j < 4; j++) {
            float2 f1 = __half22float2(p1[j]);
            float2 f2 = __half22float2(p2[j]);
            sh1[tid * 8 + 2 * j] = f1.x;
            sh1[tid * 8 + 2 * j + 1] = f1.y;
            sh2[tid * 8 + 2 * j] = f2.x;
            sh2[tid * 8 + 2 * j + 1] = f2.y;
        }
    }
    __syncthreads();

    const unsigned short* c2nrow = g_I1 + (long long)n * N_TOK;
    const unsigned short* n2crow = g_I2 + (long long)n * N_TOK;
    const bf16* m1row = g_M1 + (long long)n * N_TOK;
    const bf16* m2row = g_M2 + (long long)n * N_TOK;

    float z1[8], z2[8];
    float mx1 = -1e30f, mx2 = -1e30f;
#pragma unroll
    for (int i = 0; i < 8; i++) {
        int m = tid + i * 256;
        z1[i] = sh1[m] + sh2[c2nrow[m]] + __bfloat162float(m1row[m]);
        z2[i] = sh2[m] + sh1[n2crow[m]] + __bfloat162float(m2row[m]);
        mx1 = fmaxf(mx1, z1[i]);
        mx2 = fmaxf(mx2, z2[i]);
    }
    mx1 = warpRedMax(mx1);
    mx2 = warpRedMax(mx2);
    if (lane == 0) { red[wid] = mx1; red[wid + 8] = mx2; }
    __syncthreads();
    if (wid == 0) {
        float a = (lane < 8) ? red[lane] : -1e30f;
        float b = (lane < 8) ? red[lane + 8] : -1e30f;
        a = warpRedMax(a);
        b = warpRedMax(b);
        if (lane == 0) { red[16] = a; red[17] = b; }
    }
    __syncthreads();
    mx1 = red[16];
    mx2 = red[17];

    float sum1 = 0.f, sum2 = 0.f;
#pragma unroll
    for (int i = 0; i < 8; i++) {
        z1[i] = __expf(z1[i] - mx1);
        z2[i] = __expf(z2[i] - mx2);
        sum1 += z1[i];
        sum2 += z2[i];
    }
    sum1 = warpRedSum(sum1);
    sum2 = warpRedSum(sum2);
    __syncthreads();
    if (lane == 0) { red[wid] = sum1; red[wid + 8] = sum2; }
    __syncthreads();
    if (wid == 0) {
        float a = (lane < 8) ? red[lane] : 0.f;
        float b = (lane < 8) ? red[lane + 8] : 0.f;
        a = warpRedSum(a);
        b = warpRedSum(b);
        if (lane == 0) { red[16] = a; red[17] = b; }
    }
    __syncthreads();
    float inv1 = 1.f / red[16];
    float inv2 = 1.f / red[17];
#pragma unroll
    for (int i = 0; i < 8; i++) {
        int m = tid + i * 256;
        s1row[m] = __float2half_rn(z1[i] * inv1);
        s2row[m] = __float2half_rn(z2[i] * inv2);
    }
}

// ============================ stage 4: AV + concat (2-term fp16) ============================
__global__ __launch_bounds__(256, 2)
void av_mma_kernel(float* __restrict__ out)
{
    const int z = blockIdx.z, mat = z >> 3, h = z & 7;
    const int bm = blockIdx.y * 128;
    const __half* Ab = reinterpret_cast<const __half*>(mat ? g_S2 : g_S1);
    const __half* aP = Ab + ((long long)h * N_TOK + bm) * 4096;
    const __half* bH = g_VTh + (long long)(mat * 512 + h * 64) * 2048;
    const __half* bL = g_VTl + (long long)(mat * 512 + h * 64) * 2048;

    float acc[2][4][4];
#pragma unroll
    for (int a = 0; a < 2; a++)
#pragma unroll
        for (int b = 0; b < 4; b++)
#pragma unroll
            for (int c = 0; c < 4; c++) acc[a][b][c] = 0.f;

    gemm_av(aP, 4096, bH, bL, 2048, 2048, acc);

    const int wid = threadIdx.x >> 5, lane = threadIdx.x & 31;
    const int g = lane >> 2, t = lane & 3;
    const int wm = (wid >> 1) * 32, wn = (wid & 1) * 32;
    const int cbase = mat * 512 + h * 64;
#pragma unroll
    for (int mi = 0; mi < 2; mi++) {
        int m0 = bm + wm + mi * 16 + g;
#pragma unroll
        for (int ni = 0; ni < 4; ni++) {
            int col = cbase + wn + ni * 8 + 2 * t;
            *(float2*)(out + (long long)m0 * 1024 + col) =
                make_float2(acc[mi][ni][0], acc[mi][ni][1]);
            *(float2*)(out + (long long)(m0 + 8) * 1024 + col) =
                make_float2(acc[mi][ni][2], acc[mi][ni][3]);
        }
    }
}

// ============================ launch ============================
extern "C" void kernel_launch(void* const* d_in, const int* in_sizes, int n_in,
                              void* d_out, int out_size)
{
    const float* x   = (const float*)d_in[0];
    const float* fst = (const float*)d_in[1];
    const float* sec = (const float*)d_in[2];
    const int*   n2c = (const int*)d_in[3];
    const int*   c2n = (const int*)d_in[4];
    const float* Wq1 = (const float*)d_in[5];
    const float* bq1 = (const float*)d_in[6];
    const float* Wk1 = (const float*)d_in[7];
    const float* bk1 = (const float*)d_in[8];
    const float* Wv1 = (const float*)d_in[9];
    const float* bv1 = (const float*)d_in[10];
    const float* Wq2 = (const float*)d_in[11];
    const float* bq2 = (const float*)d_in[12];
    const float* Wk2 = (const float*)d_in[13];
    const float* bk2 = (const float*)d_in[14];
    const float* Wv2 = (const float*)d_in[15];
    const float* bv2 = (const float*)d_in[16];
    float* out = (float*)d_out;

    static bool attr_set = false;
    if (!attr_set) {
        cudaFuncSetAttribute(proj_mma_kernel, cudaFuncAttributeMaxDynamicSharedMemorySize, 61440);
        cudaFuncSetAttribute(score_mma_kernel, cudaFuncAttributeMaxDynamicSharedMemorySize, 61440);
        cudaFuncSetAttribute(av_mma_kernel, cudaFuncAttributeMaxDynamicSharedMemorySize, 40960);
        attr_set = true;
    }

    // stage 0: transposed bf16 masks + u16 indices + fp16 conversions
    mask_transpose_kernel<<<dim3(64, 64), dim3(32, 8)>>>(fst, sec);
    convidx_kernel<<<4096, 256>>>(c2n, n2c);
    convx_kernel<<<2048, 256>>>(x);
    convw_kernel<<<dim3(32, 32, 6), dim3(32, 8)>>>(Wq1, Wk1, Wq2, Wk2, Wv1, Wv2);

    // stage 1: projections (640 CTAs, 2-term fp16)
    proj_mma_kernel<<<dim3(40, 16), 256, 61440>>>(bq1, bk1, bv1, bq2, bk2, bv2);

    // stage 2: scores (4096 CTAs, 2-term fp16, fp16 output)
    const float scale = 0.08838834764831845f;  // 1/sqrt(128)
    score_mma_kernel<<<dim3(16, 16, 16), 256, 61440>>>(scale);

    // stage 3: gathered dual softmax -> fp16 probs, in place
    softmax_gather_kernel<<<dim3(2048, 8), 256>>>();

    // stage 4: AV + concat (256 CTAs, 2-term fp16)
    av_mma_kernel<<<dim3(1, 16, 16), 256, 40960>>>(out);
}

// round 10
// speedup vs baseline: 2.7057x; 1.3118x over previous
#include <cuda_runtime.h>
#include <cuda_bf16.h>
#include <cuda_fp16.h>
#include <cstdint>

#define N_TOK 2048
#define NN (8LL * 2048 * 2048)

typedef __nv_bfloat16 bf16;

__device__ __forceinline__ uint32_t smem_to_u32(const void* p) {
    uint32_t a;
    asm("{ .reg .u64 t; cvta.to.shared.u64 t, %1; cvt.u32.u64 %0, t; }" : "=r"(a) : "l"(p));
    return a;
}

__device__ __forceinline__ void ldmatrix_x4(uint32_t& r0, uint32_t& r1, uint32_t& r2,
                                            uint32_t& r3, uint32_t addr) {
    asm volatile("ldmatrix.sync.aligned.m8n8.x4.shared.b16 {%0,%1,%2,%3}, [%4];"
                 : "=r"(r0), "=r"(r1), "=r"(r2), "=r"(r3) : "r"(addr));
}

__device__ __forceinline__ void mma16816h(float c[4], const uint32_t a[4], const uint32_t b[2]) {
    asm volatile(
        "mma.sync.aligned.m16n8k16.row.col.f32.f16.f16.f32 "
        "{%0,%1,%2,%3}, {%4,%5,%6,%7}, {%8,%9}, {%0,%1,%2,%3};"
        : "+f"(c[0]), "+f"(c[1]), "+f"(c[2]), "+f"(c[3])
        : "r"(a[0]), "r"(a[1]), "r"(a[2]), "r"(a[3]), "r"(b[0]), "r"(b[1]));
}

#define CP_ASYNC_CG(smem_addr, gmem_ptr) \
    asm volatile("cp.async.cg.shared.global [%0], [%1], 16;" \
                 :: "r"(smem_addr), "l"(gmem_ptr))
#define CP_ASYNC_COMMIT() asm volatile("cp.async.commit_group;" ::: "memory")
#define CP_ASYNC_WAIT(n)  asm volatile("cp.async.wait_group %0;" :: "n"(n) : "memory")

// ============================ device scratch ============================
__device__ __align__(16) __half g_Xs[2048 * 1024];       // X single fp16
__device__ __align__(16) __half g_WT[5242880];           // Wᵀ single fp16: q1,k1,q2,k2 (1M) + v1,v2 (512K), [N,K]
__device__ __align__(16) __half g_Qs[2][2048 * 1024];    // Q single fp16 per mat
__device__ __align__(16) __half g_Ks[2][2048 * 1024];    // K single fp16 per mat
__device__ __align__(16) __half g_VT[1024 * 2048];       // V single fp16, rows: mat*512+vcol, cols: token
__device__ __align__(16) float g_S1[NN];   // rows of 2048 fp32-slots: fp16 scores then fp16 probs in first half
__device__ __align__(16) float g_S2[NN];
__device__ __align__(16) bf16 g_M1[2048LL * 2048];           // transposed masks, bf16 (exact)
__device__ __align__(16) bf16 g_M2[2048LL * 2048];
__device__ __align__(16) unsigned short g_I1[2048LL * 2048]; // c2n as u16
__device__ __align__(16) unsigned short g_I2[2048LL * 2048]; // n2c as u16

// ============================ conversion kernels ============================
__global__ __launch_bounds__(256) void convx_kernel(const float* __restrict__ x) {
    int i = (blockIdx.x * 256 + threadIdx.x) * 4;
    float4 v = *(const float4*)(x + i);
    __half h[4] = {__float2half_rn(v.x), __float2half_rn(v.y),
                   __float2half_rn(v.z), __float2half_rn(v.w)};
    *(uint2*)&g_Xs[i] = *(uint2*)h;
}

__global__ __launch_bounds__(256)
void convw_kernel(const float* __restrict__ w0, const float* __restrict__ w1,
                  const float* __restrict__ w2, const float* __restrict__ w3,
                  const float* __restrict__ w4, const float* __restrict__ w5) {
    int z = blockIdx.z;
    const float* W;
    int Ncols;
    long long base;
    switch (z) {
        case 0: W = w0; Ncols = 1024; base = 0; break;
        case 1: W = w1; Ncols = 1024; base = 1048576; break;
        case 2: W = w2; Ncols = 1024; base = 2097152; break;
        case 3: W = w3; Ncols = 1024; base = 3145728; break;
        case 4: W = w4; Ncols = 512;  base = 4194304; break;
        default:W = w5; Ncols = 512;  base = 4718592; break;
    }
    int bn = blockIdx.x * 32, bk = blockIdx.y * 32;
    if (bn >= Ncols) return;
    __shared__ float t[32][33];
#pragma unroll
    for (int i = threadIdx.y; i < 32; i += 8)
        t[i][threadIdx.x] = W[(long long)(bk + i) * Ncols + bn + threadIdx.x];
    __syncthreads();
#pragma unroll
    for (int i = threadIdx.y; i < 32; i += 8) {
        long long o = base + (long long)(bn + i) * 1024 + bk + threadIdx.x;
        g_WT[o] = __float2half_rn(t[threadIdx.x][i]);
    }
}

// masks transposed -> bf16 (values {0,-1e4} exact)
__global__ void mask_transpose_kernel(const float* __restrict__ G1,
                                      const float* __restrict__ G2) {
    __shared__ float t1[32][33];
    __shared__ float t2[32][33];
    int bx = blockIdx.x * 32;
    int by = blockIdx.y * 32;
    int x = bx + threadIdx.x;
#pragma unroll
    for (int i = threadIdx.y; i < 32; i += 8) {
        t1[i][threadIdx.x] = G1[(long long)(by + i) * N_TOK + x];
        t2[i][threadIdx.x] = G2[(long long)(by + i) * N_TOK + x];
    }
    __syncthreads();
    int ox = by + threadIdx.x;
#pragma unroll
    for (int i = threadIdx.y; i < 32; i += 8) {
        g_M1[(long long)(bx + i) * N_TOK + ox] =
            __float2bfloat16((t1[threadIdx.x][i] - 1.f) * 10000.f);
        g_M2[(long long)(bx + i) * N_TOK + ox] =
            __float2bfloat16((t2[threadIdx.x][i] - 1.f) * 10000.f);
    }
}

// indices int32 -> uint16
__global__ __launch_bounds__(256)
void convidx_kernel(const int* __restrict__ c2n, const int* __restrict__ n2c) {
    long long i = ((long long)blockIdx.x * 256 + threadIdx.x) * 4;
    int4 a = *(const int4*)(c2n + i);
    int4 b = *(const int4*)(n2c + i);
    ushort4 ua = make_ushort4((unsigned short)a.x, (unsigned short)a.y,
                              (unsigned short)a.z, (unsigned short)a.w);
    ushort4 ub = make_ushort4((unsigned short)b.x, (unsigned short)b.y,
                              (unsigned short)b.z, (unsigned short)b.w);
    *(ushort4*)&g_I1[i] = ua;
    *(ushort4*)&g_I2[i] = ub;
}

// ============================ 1-term fp16 GEMM body (proj & score) ============================
// acc[4][4][4] += A(128,K) * B(128,K)^T, both single fp16.
// Warp grid 2x4. Stage: [A 10240 | B 10240], STG=20480. Double-buffered (40960).
__device__ __forceinline__ void gemm_1t(
    const __half* __restrict__ aS, int lda,
    const __half* __restrict__ bS, int ldb,
    int K, float acc[4][4][4])
{
    constexpr int OFF_B = 10240;
    constexpr int STG = 20480;
    extern __shared__ __align__(16) char sm[];
    const uint32_t smb = smem_to_u32(sm);
    const int tid = threadIdx.x;
    const int wid = tid >> 5, lane = tid & 31;
    const int wm = (wid >> 2) * 64;
    const int wn = (wid & 3) * 32;
    const int a_row = wm + (lane & 7) + ((lane >> 3) & 1) * 8;
    const int a_cofs = (lane >> 4) * 8;
    const int b_row = wn + (lane & 7) + ((lane >> 4) & 1) * 8;
    const int b_cofs = ((lane >> 3) & 1) * 8;

    const int r_cp = tid >> 2;
    const int c_cp = (tid & 3) * 8;
    const int NC = K >> 5;

    auto issue_stage = [&](int ic) {
        const uint32_t sb = smb + (uint32_t)(ic & 1) * STG;
        const int k0 = ic * 32;
#pragma unroll
        for (int i = 0; i < 2; i++) {
            int r = r_cp + i * 64;
            uint32_t so = (uint32_t)(r * 80 + c_cp * 2);
            CP_ASYNC_CG(sb + so, aS + (long long)r * lda + k0 + c_cp);
            CP_ASYNC_CG(sb + OFF_B + so, bS + (long long)r * ldb + k0 + c_cp);
        }
        CP_ASYNC_COMMIT();
    };

    issue_stage(0);
    for (int ic = 0; ic < NC; ic++) {
        if (ic + 1 < NC) { issue_stage(ic + 1); CP_ASYNC_WAIT(1); }
        else             { CP_ASYNC_WAIT(0); }
        __syncthreads();
        const uint32_t sb = smb + (uint32_t)(ic & 1) * STG;
#pragma unroll
        for (int ks = 0; ks < 32; ks += 16) {
            uint32_t aq[4][4], bb[4][2];
#pragma unroll
            for (int mi = 0; mi < 4; mi++) {
                uint32_t off = (uint32_t)(((a_row + mi * 16) * 40 + ks + a_cofs) * 2);
                ldmatrix_x4(aq[mi][0], aq[mi][1], aq[mi][2], aq[mi][3], sb + off);
            }
#pragma unroll
            for (int nj = 0; nj < 2; nj++) {
                uint32_t off = (uint32_t)(((b_row + nj * 16) * 40 + ks + b_cofs) * 2);
                ldmatrix_x4(bb[nj * 2][0], bb[nj * 2][1], bb[nj * 2 + 1][0], bb[nj * 2 + 1][1],
                            sb + OFF_B + off);
            }
#pragma unroll
            for (int mi = 0; mi < 4; mi++)
#pragma unroll
                for (int ni = 0; ni < 4; ni++)
                    mma16816h(acc[mi][ni], aq[mi], bb[ni]);
        }
        __syncthreads();
    }
}

// ============================ 1-term fp16 AV GEMM body ============================
// acc[2][4][4] += P(128,K) * V(64,K)^T, both single fp16.
// Warp grid 4x2. Stage: [A 10240 | B 5120], STG=15360. Double-buffered (30720).
__device__ __forceinline__ void gemm_av(
    const __half* __restrict__ aP, int lda,
    const __half* __restrict__ bS, int ldb,
    int K, float acc[2][4][4])
{
    constexpr int OFF_B = 10240;
    constexpr int STG = 15360;
    extern __shared__ __align__(16) char sm[];
    const uint32_t smb = smem_to_u32(sm);
    const int tid = threadIdx.x;
    const int wid = tid >> 5, lane = tid & 31;
    const int wm = (wid >> 1) * 32;
    const int wn = (wid & 1) * 32;
    const int a_row = wm + (lane & 7) + ((lane >> 3) & 1) * 8;
    const int a_cofs = (lane >> 4) * 8;
    const int b_row = wn + (lane & 7) + ((lane >> 4) & 1) * 8;
    const int b_cofs = ((lane >> 3) & 1) * 8;

    const int r_cp = tid >> 2;
    const int c_cp = (tid & 3) * 8;
    const int NC = K >> 5;

    auto issue_stage = [&](int ic) {
        const uint32_t sb = smb + (uint32_t)(ic & 1) * STG;
        const int k0 = ic * 32;
#pragma unroll
        for (int i = 0; i < 2; i++) {
            int r = r_cp + i * 64;
            uint32_t so = (uint32_t)(r * 80 + c_cp * 2);
            CP_ASYNC_CG(sb + so, aP + (long long)r * lda + k0 + c_cp);
        }
        {
            int r = r_cp;
            uint32_t so = (uint32_t)(r * 80 + c_cp * 2);
            CP_ASYNC_CG(sb + OFF_B + so, bS + (long long)r * ldb + k0 + c_cp);
        }
        CP_ASYNC_COMMIT();
    };

    issue_stage(0);
    for (int ic = 0; ic < NC; ic++) {
        if (ic + 1 < NC) { issue_stage(ic + 1); CP_ASYNC_WAIT(1); }
        else             { CP_ASYNC_WAIT(0); }
        __syncthreads();
        const uint32_t sb = smb + (uint32_t)(ic & 1) * STG;
#pragma unroll
        for (int ks = 0; ks < 32; ks += 16) {
            uint32_t ap[2][4], bb[4][2];
#pragma unroll
            for (int mi = 0; mi < 2; mi++) {
                uint32_t off = (uint32_t)(((a_row + mi * 16) * 40 + ks + a_cofs) * 2);
                ldmatrix_x4(ap[mi][0], ap[mi][1], ap[mi][2], ap[mi][3], sb + off);
            }
#pragma unroll
            for (int nj = 0; nj < 2; nj++) {
                uint32_t off = (uint32_t)(((b_row + nj * 16) * 40 + ks + b_cofs) * 2);
                ldmatrix_x4(bb[nj * 2][0], bb[nj * 2][1], bb[nj * 2 + 1][0], bb[nj * 2 + 1][1],
                            sb + OFF_B + off);
            }
#pragma unroll
            for (int mi = 0; mi < 2; mi++)
#pragma unroll
                for (int ni = 0; ni < 4; ni++)
                    mma16816h(acc[mi][ni], ap[mi], bb[ni]);
        }
        __syncthreads();
    }
}

// ============================ stage 1: projections (1-term fp16) ============================
__global__ __launch_bounds__(256, 2)
void proj_mma_kernel(const float* __restrict__ bq1, const float* __restrict__ bk1,
                     const float* __restrict__ bv1, const float* __restrict__ bq2,
                     const float* __restrict__ bk2, const float* __restrict__ bv2)
{
    const int cb = blockIdx.x;
    const int bm = blockIdx.y * 128;
    const __half* bW;
    const float* bias;
    int r, bnl;
    if (cb < 32) {
        r = cb >> 3; bnl = (cb & 7) * 128;
        bW = g_WT + (long long)r * 1048576 + (long long)bnl * 1024;
        bias = (r == 0) ? bq1 : (r == 1) ? bk1 : (r == 2) ? bq2 : bk2;
    } else {
        r = (cb - 32) >> 2; bnl = ((cb - 32) & 3) * 128;
        bW = g_WT + 4194304LL + (long long)r * 524288 + (long long)bnl * 1024;
        bias = r ? bv2 : bv1;
    }
    float acc[4][4][4];
#pragma unroll
    for (int a = 0; a < 4; a++)
#pragma unroll
        for (int b = 0; b < 4; b++)
#pragma unroll
            for (int c = 0; c < 4; c++) acc[a][b][c] = 0.f;

    gemm_1t(g_Xs + (long long)bm * 1024, 1024, bW, 1024, 1024, acc);

    const int wid = threadIdx.x >> 5, lane = threadIdx.x & 31;
    const int g = lane >> 2, t = lane & 3;
    const int wm = (wid >> 2) * 64, wn = (wid & 3) * 32;
#pragma unroll
    for (int mi = 0; mi < 4; mi++) {
        int m0 = bm + wm + mi * 16 + g;
#pragma unroll
        for (int ni = 0; ni < 4; ni++) {
            int col = bnl + wn + ni * 8 + 2 * t;
            float b0 = bias[col], b1 = bias[col + 1];
            float v00 = acc[mi][ni][0] + b0, v01 = acc[mi][ni][1] + b1;
            float v10 = acc[mi][ni][2] + b0, v11 = acc[mi][ni][3] + b1;
            __half h00 = __float2half_rn(v00), h01 = __float2half_rn(v01);
            __half h10 = __float2half_rn(v10), h11 = __float2half_rn(v11);
            if (cb < 32) {
                int mat = r >> 1;
                __half* dst = (r & 1) ? g_Ks[mat] : g_Qs[mat];
                long long o0 = (long long)m0 * 1024 + col;
                long long o1 = (long long)(m0 + 8) * 1024 + col;
                *(__half2*)&dst[o0] = __halves2half2(h00, h01);
                *(__half2*)&dst[o1] = __halves2half2(h10, h11);
            } else {
                int c0 = r * 512 + col, c1 = c0 + 1;
                g_VT[(long long)c0 * 2048 + m0] = h00;
                g_VT[(long long)c1 * 2048 + m0] = h01;
                g_VT[(long long)c0 * 2048 + m0 + 8] = h10;
                g_VT[(long long)c1 * 2048 + m0 + 8] = h11;
            }
        }
    }
}

// ============================ stage 2: scores (1-term fp16, fp16 output) ============================
__global__ __launch_bounds__(256, 2)
void score_mma_kernel(float scale)
{
    const int z = blockIdx.z, mat = z >> 3, h = z & 7;
    const int bm = blockIdx.y * 128, bn = blockIdx.x * 128;
    const __half* q = g_Qs[mat] + (long long)bm * 1024 + h * 128;
    const __half* k = g_Ks[mat] + (long long)bn * 1024 + h * 128;

    float acc[4][4][4];
#pragma unroll
    for (int a = 0; a < 4; a++)
#pragma unroll
        for (int b = 0; b < 4; b++)
#pragma unroll
            for (int c = 0; c < 4; c++) acc[a][b][c] = 0.f;

    gemm_1t(q, 1024, k, 1024, 128, acc);

    __half* S = reinterpret_cast<__half*>((mat ? g_S2 : g_S1));
    const int wid = threadIdx.x >> 5, lane = threadIdx.x & 31;
    const int g = lane >> 2, t = lane & 3;
    const int wm = (wid >> 2) * 64, wn = (wid & 3) * 32;
    const long long hbase = (long long)h * N_TOK * 4096;
#pragma unroll
    for (int mi = 0; mi < 4; mi++) {
        int m0 = bm + wm + mi * 16 + g;
#pragma unroll
        for (int ni = 0; ni < 4; ni++) {
            int n0 = bn + wn + ni * 8 + 2 * t;
            *(__half2*)&S[hbase + (long long)m0 * 4096 + n0] =
                __halves2half2(__float2half_rn(acc[mi][ni][0] * scale),
                               __float2half_rn(acc[mi][ni][1] * scale));
            *(__half2*)&S[hbase + (long long)(m0 + 8) * 4096 + n0] =
                __halves2half2(__float2half_rn(acc[mi][ni][2] * scale),
                               __float2half_rn(acc[mi][ni][3] * scale));
        }
    }
}

// ============================ stage 3: dual gathered softmax ============================
__device__ __forceinline__ float warpRedMax(float v) {
#pragma unroll
    for (int o = 16; o > 0; o >>= 1) v = fmaxf(v, __shfl_xor_sync(0xffffffffu, v, o));
    return v;
}
__device__ __forceinline__ float warpRedSum(float v) {
#pragma unroll
    for (int o = 16; o > 0; o >>= 1) v += __shfl_xor_sync(0xffffffffu, v, o);
    return v;
}

__global__ __launch_bounds__(256)
void softmax_gather_kernel()
{
    const int n = blockIdx.x;
    const int h = blockIdx.y;
    __half* s1row = reinterpret_cast<__half*>(g_S1) + ((long long)h * N_TOK + n) * 4096;
    __half* s2row = reinterpret_cast<__half*>(g_S2) + ((long long)h * N_TOK + n) * 4096;
    __shared__ float sh1[N_TOK];
    __shared__ float sh2[N_TOK];
    __shared__ float red[32];
    const int tid = threadIdx.x;
    const int lane = tid & 31, wid = tid >> 5;

    {
        uint4 v1 = *(const uint4*)(s1row + tid * 8);
        uint4 v2 = *(const uint4*)(s2row + tid * 8);
        const __half2* p1 = (const __half2*)&v1;
        const __half2* p2 = (const __half2*)&v2;
#pragma unroll
        for (int j = 0; j < 4; j++) {
            float2 f1 = __half22float2(p1[j]);
            float2 f2 = __half22float2(p2[j]);
            sh1[tid * 8 + 2 * j] = f1.x;
            sh1[tid * 8 + 2 * j + 1] = f1.y;
            sh2[tid * 8 + 2 * j] = f2.x;
            sh2[tid * 8 + 2 * j + 1] = f2.y;
        }
    }
    __syncthreads();

    const unsigned short* c2nrow = g_I1 + (long long)n * N_TOK;
    const unsigned short* n2crow = g_I2 + (long long)n * N_TOK;
    const bf16* m1row = g_M1 + (long long)n * N_TOK;
    const bf16* m2row = g_M2 + (long long)n * N_TOK;

    float z1[8], z2[8];
    float mx1 = -1e30f, mx2 = -1e30f;
#pragma unroll
    for (int i = 0; i < 8; i++) {
        int m = tid + i * 256;
        z1[i] = sh1[m] + sh2[c2nrow[m]] + __bfloat162float(m1row[m]);
        z2[i] = sh2[m] + sh1[n2crow[m]] + __bfloat162float(m2row[m]);
        mx1 = fmaxf(mx1, z1[i]);
        mx2 = fmaxf(mx2, z2[i]);
    }
    mx1 = warpRedMax(mx1);
    mx2 = warpRedMax(mx2);
    if (lane == 0) { red[wid] = mx1; red[wid + 8] = mx2; }
    __syncthreads();
    if (wid == 0) {
        float a = (lane < 8) ? red[lane] : -1e30f;
        float b = (lane < 8) ? red[lane + 8] : -1e30f;
        a = warpRedMax(a);
        b = warpRedMax(b);
        if (lane == 0) { red[16] = a; red[17] = b; }
    }
    __syncthreads();
    mx1 = red[16];
    mx2 = red[17];

    float sum1 = 0.f, sum2 = 0.f;
#pragma unroll
    for (int i = 0; i < 8; i++) {
        z1[i] = __expf(z1[i] - mx1);
        z2[i] = __expf(z2[i] - mx2);
        sum1 += z1[i];
        sum2 += z2[i];
    }
    sum1 = warpRedSum(sum1);
    sum2 = warpRedSum(sum2);
    __syncthreads();
    if (lane == 0) { red[wid] = sum1; red[wid + 8] = sum2; }
    __syncthreads();
    if (wid == 0) {
        float a = (lane < 8) ? red[lane] : 0.f;
        float b = (lane < 8) ? red[lane + 8] : 0.f;
        a = warpRedSum(a);
        b = warpRedSum(b);
        if (lane == 0) { red[16] = a; red[17] = b; }
    }
    __syncthreads();
    float inv1 = 1.f / red[16];
    float inv2 = 1.f / red[17];
#pragma unroll
    for (int i = 0; i < 8; i++) {
        int m = tid + i * 256;
        s1row[m] = __float2half_rn(z1[i] * inv1);
        s2row[m] = __float2half_rn(z2[i] * inv2);
    }
}

// ============================ stage 4: AV + concat (1-term fp16) ============================
__global__ __launch_bounds__(256, 2)
void av_mma_kernel(float* __restrict__ out)
{
    const int z = blockIdx.z, mat = z >> 3, h = z & 7;
    const int bm = blockIdx.y * 128;
    const __half* Ab = reinterpret_cast<const __half*>(mat ? g_S2 : g_S1);
    const __half* aP = Ab + ((long long)h * N_TOK + bm) * 4096;
    const __half* bV = g_VT + (long long)(mat * 512 + h * 64) * 2048;

    float acc[2][4][4];
#pragma unroll
    for (int a = 0; a < 2; a++)
#pragma unroll
        for (int b = 0; b < 4; b++)
#pragma unroll
            for (int c = 0; c < 4; c++) acc[a][b][c] = 0.f;

    gemm_av(aP, 4096, bV, 2048, 2048, acc);

    const int wid = threadIdx.x >> 5, lane = threadIdx.x & 31;
    const int g = lane >> 2, t = lane & 3;
    const int wm = (wid >> 1) * 32, wn = (wid & 1) * 32;
    const int cbase = mat * 512 + h * 64;
#pragma unroll
    for (int mi = 0; mi < 2; mi++) {
        int m0 = bm + wm + mi * 16 + g;
#pragma unroll
        for (int ni = 0; ni < 4; ni++) {
            int col = cbase + wn + ni * 8 + 2 * t;
            *(float2*)(out + (long long)m0 * 1024 + col) =
                make_float2(acc[mi][ni][0], acc[mi][ni][1]);
            *(float2*)(out + (long long)(m0 + 8) * 1024 + col) =
                make_float2(acc[mi][ni][2], acc[mi][ni][3]);
        }
    }
}

// ============================ launch ============================
extern "C" void kernel_launch(void* const* d_in, const int* in_sizes, int n_in,
                              void* d_out, int out_size)
{
    const float* x   = (const float*)d_in[0];
    const float* fst = (const float*)d_in[1];
    const float* sec = (const float*)d_in[2];
    const int*   n2c = (const int*)d_in[3];
    const int*   c2n = (const int*)d_in[4];
    const float* Wq1 = (const float*)d_in[5];
    const float* bq1 = (const float*)d_in[6];
    const float* Wk1 = (const float*)d_in[7];
    const float* bk1 = (const float*)d_in[8];
    const float* Wv1 = (const float*)d_in[9];
    const float* bv1 = (const float*)d_in[10];
    const float* Wq2 = (const float*)d_in[11];
    const float* bq2 = (const float*)d_in[12];
    const float* Wk2 = (const float*)d_in[13];
    const float* bk2 = (const float*)d_in[14];
    const float* Wv2 = (const float*)d_in[15];
    const float* bv2 = (const float*)d_in[16];
    float* out = (float*)d_out;

    static bool attr_set = false;
    if (!attr_set) {
        cudaFuncSetAttribute(proj_mma_kernel, cudaFuncAttributeMaxDynamicSharedMemorySize, 40960);
        cudaFuncSetAttribute(score_mma_kernel, cudaFuncAttributeMaxDynamicSharedMemorySize, 40960);
        cudaFuncSetAttribute(av_mma_kernel, cudaFuncAttributeMaxDynamicSharedMemorySize, 30720);
        attr_set = true;
    }

    // stage 0: transposed bf16 masks + u16 indices + fp16 conversions
    mask_transpose_kernel<<<dim3(64, 64), dim3(32, 8)>>>(fst, sec);
    convidx_kernel<<<4096, 256>>>(c2n, n2c);
    convx_kernel<<<2048, 256>>>(x);
    convw_kernel<<<dim3(32, 32, 6), dim3(32, 8)>>>(Wq1, Wk1, Wq2, Wk2, Wv1, Wv2);

    // stage 1: projections (640 CTAs, 1-term fp16)
    proj_mma_kernel<<<dim3(40, 16), 256, 40960>>>(bq1, bk1, bv1, bq2, bk2, bv2);

    // stage 2: scores (4096 CTAs, 1-term fp16, fp16 output)
    const float scale = 0.08838834764831845f;  // 1/sqrt(128)
    score_mma_kernel<<<dim3(16, 16, 16), 256, 40960>>>(scale);

    // stage 3: gathered dual softmax -> fp16 probs, in place
    softmax_gather_kernel<<<dim3(2048, 8), 256>>>();

    // stage 4: AV + concat (256 CTAs, 1-term fp16)
    av_mma_kernel<<<dim3(1, 16, 16), 256, 30720>>>(out);
}

// round 11
// speedup vs baseline: 2.7807x; 1.0277x over previous
#include <cuda_runtime.h>
#include <cuda_bf16.h>
#include <cuda_fp16.h>
#include <cstdint>

#define N_TOK 2048
#define NN (8LL * 2048 * 2048)

__device__ __forceinline__ uint32_t smem_to_u32(const void* p) {
    uint32_t a;
    asm("{ .reg .u64 t; cvta.to.shared.u64 t, %1; cvt.u32.u64 %0, t; }" : "=r"(a) : "l"(p));
    return a;
}

__device__ __forceinline__ void ldmatrix_x4(uint32_t& r0, uint32_t& r1, uint32_t& r2,
                                            uint32_t& r3, uint32_t addr) {
    asm volatile("ldmatrix.sync.aligned.m8n8.x4.shared.b16 {%0,%1,%2,%3}, [%4];"
                 : "=r"(r0), "=r"(r1), "=r"(r2), "=r"(r3) : "r"(addr));
}

__device__ __forceinline__ void mma16816h(float c[4], const uint32_t a[4], const uint32_t b[2]) {
    asm volatile(
        "mma.sync.aligned.m16n8k16.row.col.f32.f16.f16.f32 "
        "{%0,%1,%2,%3}, {%4,%5,%6,%7}, {%8,%9}, {%0,%1,%2,%3};"
        : "+f"(c[0]), "+f"(c[1]), "+f"(c[2]), "+f"(c[3])
        : "r"(a[0]), "r"(a[1]), "r"(a[2]), "r"(a[3]), "r"(b[0]), "r"(b[1]));
}

#define CP_ASYNC_CG(smem_addr, gmem_ptr) \
    asm volatile("cp.async.cg.shared.global [%0], [%1], 16;" \
                 :: "r"(smem_addr), "l"(gmem_ptr))
#define CP_ASYNC_COMMIT() asm volatile("cp.async.commit_group;" ::: "memory")
#define CP_ASYNC_WAIT(n)  asm volatile("cp.async.wait_group %0;" :: "n"(n) : "memory")

// ============================ device scratch ============================
__device__ __align__(16) __half g_Xs[2048 * 1024];       // X single fp16
__device__ __align__(16) __half g_WT[5242880];           // Wᵀ single fp16: q1,k1,q2,k2 (1M) + v1,v2 (512K), [N,K]
__device__ __align__(16) __half g_Qs[2][2048 * 1024];    // Q (pre-scaled) single fp16 per mat
__device__ __align__(16) __half g_Ks[2][2048 * 1024];    // K single fp16 per mat
__device__ __align__(16) __half g_VT[1024 * 2048];       // V single fp16, rows: mat*512+vcol, cols: token
__device__ __align__(16) float g_S1[NN];   // rows of 2048 fp32-slots: fp16 scores then fp16 probs in first half
__device__ __align__(16) float g_S2[NN];
__device__ __align__(16) unsigned short g_I1[2048LL * 2048]; // c2n u16 | mask1<<15
__device__ __align__(16) unsigned short g_I2[2048LL * 2048]; // n2c u16 | mask2<<15

// ============================ conversion kernels ============================
__global__ __launch_bounds__(256) void convx_kernel(const float* __restrict__ x) {
    int i = (blockIdx.x * 256 + threadIdx.x) * 4;
    float4 v = *(const float4*)(x + i);
    __half h[4] = {__float2half_rn(v.x), __float2half_rn(v.y),
                   __float2half_rn(v.z), __float2half_rn(v.w)};
    *(uint2*)&g_Xs[i] = *(uint2*)h;
}

__global__ __launch_bounds__(256)
void convw_kernel(const float* __restrict__ w0, const float* __restrict__ w1,
                  const float* __restrict__ w2, const float* __restrict__ w3,
                  const float* __restrict__ w4, const float* __restrict__ w5) {
    int z = blockIdx.z;
    const float* W;
    int Ncols;
    long long base;
    switch (z) {
        case 0: W = w0; Ncols = 1024; base = 0; break;
        case 1: W = w1; Ncols = 1024; base = 1048576; break;
        case 2: W = w2; Ncols = 1024; base = 2097152; break;
        case 3: W = w3; Ncols = 1024; base = 3145728; break;
        case 4: W = w4; Ncols = 512;  base = 4194304; break;
        default:W = w5; Ncols = 512;  base = 4718592; break;
    }
    int bn = blockIdx.x * 32, bk = blockIdx.y * 32;
    if (bn >= Ncols) return;
    __shared__ float t[32][33];
#pragma unroll
    for (int i = threadIdx.y; i < 32; i += 8)
        t[i][threadIdx.x] = W[(long long)(bk + i) * Ncols + bn + threadIdx.x];
    __syncthreads();
#pragma unroll
    for (int i = threadIdx.y; i < 32; i += 8) {
        long long o = base + (long long)(bn + i) * 1024 + bk + threadIdx.x;
        g_WT[o] = __float2half_rn(t[threadIdx.x][i]);
    }
}

// pack indices + transposed graph masks: I1[n][m] = c2n[n][m] | (fst[m][n]==0)<<15
__global__ void pack_kernel(const int* __restrict__ c2n, const int* __restrict__ n2c,
                            const float* __restrict__ G1, const float* __restrict__ G2) {
    __shared__ float t1[32][33];
    __shared__ float t2[32][33];
    const int bx = blockIdx.x * 32;   // n-tile
    const int by = blockIdx.y * 32;   // m-tile
    // load graph tiles: g[i][j] = G[(by+i)][bx+j]
#pragma unroll
    for (int i = threadIdx.y; i < 32; i += 8) {
        t1[i][threadIdx.x] = G1[(long long)(by + i) * N_TOK + bx + threadIdx.x];
        t2[i][threadIdx.x] = G2[(long long)(by + i) * N_TOK + bx + threadIdx.x];
    }
    __syncthreads();
#pragma unroll
    for (int i = threadIdx.y; i < 32; i += 8) {
        int n = bx + i;
        int m = by + threadIdx.x;
        long long o = (long long)n * N_TOK + m;
        unsigned short v1 = (unsigned short)c2n[o];
        unsigned short v2 = (unsigned short)n2c[o];
        if (t1[threadIdx.x][i] == 0.f) v1 |= 0x8000;
        if (t2[threadIdx.x][i] == 0.f) v2 |= 0x8000;
        g_I1[o] = v1;
        g_I2[o] = v2;
    }
}

// ============================ 1-term fp16 GEMM body (proj & score) ============================
// acc[4][4][4] += A(128,K) * B(128,K)^T, both single fp16.
// Warp grid 2x4. Stage: [A 10240 | B 10240], STG=20480. Double-buffered (40960).
__device__ __forceinline__ void gemm_1t(
    const __half* __restrict__ aS, int lda,
    const __half* __restrict__ bS, int ldb,
    int K, float acc[4][4][4])
{
    constexpr int OFF_B = 10240;
    constexpr int STG = 20480;
    extern __shared__ __align__(16) char sm[];
    const uint32_t smb = smem_to_u32(sm);
    const int tid = threadIdx.x;
    const int wid = tid >> 5, lane = tid & 31;
    const int wm = (wid >> 2) * 64;
    const int wn = (wid & 3) * 32;
    const int a_row = wm + (lane & 7) + ((lane >> 3) & 1) * 8;
    const int a_cofs = (lane >> 4) * 8;
    const int b_row = wn + (lane & 7) + ((lane >> 4) & 1) * 8;
    const int b_cofs = ((lane >> 3) & 1) * 8;

    const int r_cp = tid >> 2;
    const int c_cp = (tid & 3) * 8;
    const int NC = K >> 5;

    auto issue_stage = [&](int ic) {
        const uint32_t sb = smb + (uint32_t)(ic & 1) * STG;
        const int k0 = ic * 32;
#pragma unroll
        for (int i = 0; i < 2; i++) {
            int r = r_cp + i * 64;
            uint32_t so = (uint32_t)(r * 80 + c_cp * 2);
            CP_ASYNC_CG(sb + so, aS + (long long)r * lda + k0 + c_cp);
            CP_ASYNC_CG(sb + OFF_B + so, bS + (long long)r * ldb + k0 + c_cp);
        }
        CP_ASYNC_COMMIT();
    };

    issue_stage(0);
    for (int ic = 0; ic < NC; ic++) {
        if (ic + 1 < NC) { issue_stage(ic + 1); CP_ASYNC_WAIT(1); }
        else             { CP_ASYNC_WAIT(0); }
        __syncthreads();
        const uint32_t sb = smb + (uint32_t)(ic & 1) * STG;
#pragma unroll
        for (int ks = 0; ks < 32; ks += 16) {
            uint32_t aq[4][4], bb[4][2];
#pragma unroll
            for (int mi = 0; mi < 4; mi++) {
                uint32_t off = (uint32_t)(((a_row + mi * 16) * 40 + ks + a_cofs) * 2);
                ldmatrix_x4(aq[mi][0], aq[mi][1], aq[mi][2], aq[mi][3], sb + off);
            }
#pragma unroll
            for (int nj = 0; nj < 2; nj++) {
                uint32_t off = (uint32_t)(((b_row + nj * 16) * 40 + ks + b_cofs) * 2);
                ldmatrix_x4(bb[nj * 2][0], bb[nj * 2][1], bb[nj * 2 + 1][0], bb[nj * 2 + 1][1],
                            sb + OFF_B + off);
            }
#pragma unroll
            for (int mi = 0; mi < 4; mi++)
#pragma unroll
                for (int ni = 0; ni < 4; ni++)
                    mma16816h(acc[mi][ni], aq[mi], bb[ni]);
        }
        __syncthreads();
    }
}

// ============================ 1-term fp16 AV GEMM body ============================
__device__ __forceinline__ void gemm_av(
    const __half* __restrict__ aP, int lda,
    const __half* __restrict__ bS, int ldb,
    int K, float acc[2][4][4])
{
    constexpr int OFF_B = 10240;
    constexpr int STG = 15360;
    extern __shared__ __align__(16) char sm[];
    const uint32_t smb = smem_to_u32(sm);
    const int tid = threadIdx.x;
    const int wid = tid >> 5, lane = tid & 31;
    const int wm = (wid >> 1) * 32;
    const int wn = (wid & 1) * 32;
    const int a_row = wm + (lane & 7) + ((lane >> 3) & 1) * 8;
    const int a_cofs = (lane >> 4) * 8;
    const int b_row = wn + (lane & 7) + ((lane >> 4) & 1) * 8;
    const int b_cofs = ((lane >> 3) & 1) * 8;

    const int r_cp = tid >> 2;
    const int c_cp = (tid & 3) * 8;
    const int NC = K >> 5;

    auto issue_stage = [&](int ic) {
        const uint32_t sb = smb + (uint32_t)(ic & 1) * STG;
        const int k0 = ic * 32;
#pragma unroll
        for (int i = 0; i < 2; i++) {
            int r = r_cp + i * 64;
            uint32_t so = (uint32_t)(r * 80 + c_cp * 2);
            CP_ASYNC_CG(sb + so, aP + (long long)r * lda + k0 + c_cp);
        }
        {
            int r = r_cp;
            uint32_t so = (uint32_t)(r * 80 + c_cp * 2);
            CP_ASYNC_CG(sb + OFF_B + so, bS + (long long)r * ldb + k0 + c_cp);
        }
        CP_ASYNC_COMMIT();
    };

    issue_stage(0);
    for (int ic = 0; ic < NC; ic++) {
        if (ic + 1 < NC) { issue_stage(ic + 1); CP_ASYNC_WAIT(1); }
        else             { CP_ASYNC_WAIT(0); }
        __syncthreads();
        const uint32_t sb = smb + (uint32_t)(ic & 1) * STG;
#pragma unroll
        for (int ks = 0; ks < 32; ks += 16) {
            uint32_t ap[2][4], bb[4][2];
#pragma unroll
            for (int mi = 0; mi < 2; mi++) {
                uint32_t off = (uint32_t)(((a_row + mi * 16) * 40 + ks + a_cofs) * 2);
                ldmatrix_x4(ap[mi][0], ap[mi][1], ap[mi][2], ap[mi][3], sb + off);
            }
#pragma unroll
            for (int nj = 0; nj < 2; nj++) {
                uint32_t off = (uint32_t)(((b_row + nj * 16) * 40 + ks + b_cofs) * 2);
                ldmatrix_x4(bb[nj * 2][0], bb[nj * 2][1], bb[nj * 2 + 1][0], bb[nj * 2 + 1][1],
                            sb + OFF_B + off);
            }
#pragma unroll
            for (int mi = 0; mi < 2; mi++)
#pragma unroll
                for (int ni = 0; ni < 4; ni++)
                    mma16816h(acc[mi][ni], ap[mi], bb[ni]);
        }
        __syncthreads();
    }
}

// ============================ stage 1: projections (1-term fp16, Q pre-scaled) ============================
__global__ __launch_bounds__(256, 2)
void proj_mma_kernel(const float* __restrict__ bq1, const float* __restrict__ bk1,
                     const float* __restrict__ bv1, const float* __restrict__ bq2,
                     const float* __restrict__ bk2, const float* __restrict__ bv2)
{
    const float scale = 0.08838834764831845f;  // 1/sqrt(128), folded into Q
    const int cb = blockIdx.x;
    const int bm = blockIdx.y * 128;
    const __half* bW;
    const float* bias;
    int r, bnl;
    if (cb < 32) {
        r = cb >> 3; bnl = (cb & 7) * 128;
        bW = g_WT + (long long)r * 1048576 + (long long)bnl * 1024;
        bias = (r == 0) ? bq1 : (r == 1) ? bk1 : (r == 2) ? bq2 : bk2;
    } else {
        r = (cb - 32) >> 2; bnl = ((cb - 32) & 3) * 128;
        bW = g_WT + 4194304LL + (long long)r * 524288 + (long long)bnl * 1024;
        bias = r ? bv2 : bv1;
    }
    float acc[4][4][4];
#pragma unroll
    for (int a = 0; a < 4; a++)
#pragma unroll
        for (int b = 0; b < 4; b++)
#pragma unroll
            for (int c = 0; c < 4; c++) acc[a][b][c] = 0.f;

    gemm_1t(g_Xs + (long long)bm * 1024, 1024, bW, 1024, 1024, acc);

    const int wid = threadIdx.x >> 5, lane = threadIdx.x & 31;
    const int g = lane >> 2, t = lane & 3;
    const int wm = (wid >> 2) * 64, wn = (wid & 3) * 32;
    const bool isQ = (cb < 32) && ((r & 1) == 0);
    const float outscale = isQ ? scale : 1.f;
#pragma unroll
    for (int mi = 0; mi < 4; mi++) {
        int m0 = bm + wm + mi * 16 + g;
#pragma unroll
        for (int ni = 0; ni < 4; ni++) {
            int col = bnl + wn + ni * 8 + 2 * t;
            float b0 = bias[col], b1 = bias[col + 1];
            float v00 = (acc[mi][ni][0] + b0) * outscale, v01 = (acc[mi][ni][1] + b1) * outscale;
            float v10 = (acc[mi][ni][2] + b0) * outscale, v11 = (acc[mi][ni][3] + b1) * outscale;
            __half h00 = __float2half_rn(v00), h01 = __float2half_rn(v01);
            __half h10 = __float2half_rn(v10), h11 = __float2half_rn(v11);
            if (cb < 32) {
                int mat = r >> 1;
                __half* dst = (r & 1) ? g_Ks[mat] : g_Qs[mat];
                long long o0 = (long long)m0 * 1024 + col;
                long long o1 = (long long)(m0 + 8) * 1024 + col;
                *(__half2*)&dst[o0] = __halves2half2(h00, h01);
                *(__half2*)&dst[o1] = __halves2half2(h10, h11);
            } else {
                int c0 = r * 512 + col, c1 = c0 + 1;
                g_VT[(long long)c0 * 2048 + m0] = h00;
                g_VT[(long long)c1 * 2048 + m0] = h01;
                g_VT[(long long)c0 * 2048 + m0 + 8] = h10;
                g_VT[(long long)c1 * 2048 + m0 + 8] = h11;
            }
        }
    }
}

// ============================ stage 2: scores (1-term fp16, fp16 output) ============================
__global__ __launch_bounds__(256, 2)
void score_mma_kernel()
{
    const int z = blockIdx.z, mat = z >> 3, h = z & 7;
    const int bm = blockIdx.y * 128, bn = blockIdx.x * 128;
    const __half* q = g_Qs[mat] + (long long)bm * 1024 + h * 128;
    const __half* k = g_Ks[mat] + (long long)bn * 1024 + h * 128;

    float acc[4][4][4];
#pragma unroll
    for (int a = 0; a < 4; a++)
#pragma unroll
        for (int b = 0; b < 4; b++)
#pragma unroll
            for (int c = 0; c < 4; c++) acc[a][b][c] = 0.f;

    gemm_1t(q, 1024, k, 1024, 128, acc);

    __half* S = reinterpret_cast<__half*>((mat ? g_S2 : g_S1));
    const int wid = threadIdx.x >> 5, lane = threadIdx.x & 31;
    const int g = lane >> 2, t = lane & 3;
    const int wm = (wid >> 2) * 64, wn = (wid & 3) * 32;
    const long long hbase = (long long)h * N_TOK * 4096;
#pragma unroll
    for (int mi = 0; mi < 4; mi++) {
        int m0 = bm + wm + mi * 16 + g;
#pragma unroll
        for (int ni = 0; ni < 4; ni++) {
            int n0 = bn + wn + ni * 8 + 2 * t;
            *(__half2*)&S[hbase + (long long)m0 * 4096 + n0] =
                __halves2half2(__float2half_rn(acc[mi][ni][0]),
                               __float2half_rn(acc[mi][ni][1]));
            *(__half2*)&S[hbase + (long long)(m0 + 8) * 4096 + n0] =
                __halves2half2(__float2half_rn(acc[mi][ni][2]),
                               __float2half_rn(acc[mi][ni][3]));
        }
    }
}

// ============================ stage 3: dual gathered softmax ============================
__device__ __forceinline__ float warpRedMax(float v) {
#pragma unroll
    for (int o = 16; o > 0; o >>= 1) v = fmaxf(v, __shfl_xor_sync(0xffffffffu, v, o));
    return v;
}
__device__ __forceinline__ float warpRedSum(float v) {
#pragma unroll
    for (int o = 16; o > 0; o >>= 1) v += __shfl_xor_sync(0xffffffffu, v, o);
    return v;
}

// grid (8, 2048): h fastest -> packed index rows L2-resident across the 8 head CTAs
__global__ __launch_bounds__(256)
void softmax_gather_kernel()
{
    const int h = blockIdx.x;
    const int n = blockIdx.y;
    __half* s1row = reinterpret_cast<__half*>(g_S1) + ((long long)h * N_TOK + n) * 4096;
    __half* s2row = reinterpret_cast<__half*>(g_S2) + ((long long)h * N_TOK + n) * 4096;
    __shared__ float sh1[N_TOK];
    __shared__ float sh2[N_TOK];
    __shared__ float red[32];
    const int tid = threadIdx.x;
    const int lane = tid & 31, wid = tid >> 5;

    {
        uint4 v1 = *(const uint4*)(s1row + tid * 8);
        uint4 v2 = *(const uint4*)(s2row + tid * 8);
        const __half2* p1 = (const __half2*)&v1;
        const __half2* p2 = (const __half2*)&v2;
#pragma unroll
        for (int j = 0; j < 4; j++) {
            float2 f1 = __half22float2(p1[j]);
            float2 f2 = __half22float2(p2[j]);
            sh1[tid * 8 + 2 * j] = f1.x;
            sh1[tid * 8 + 2 * j + 1] = f1.y;
            sh2[tid * 8 + 2 * j] = f2.x;
            sh2[tid * 8 + 2 * j + 1] = f2.y;
        }
    }
    __syncthreads();

    const unsigned short* i1row = g_I1 + (long long)n * N_TOK;
    const unsigned short* i2row = g_I2 + (long long)n * N_TOK;

    float z1[8], z2[8];
    float mx1 = -1e30f, mx2 = -1e30f;
#pragma unroll
    for (int i = 0; i < 8; i++) {
        int m = tid + i * 256;
        unsigned short v1 = i1row[m];
        unsigned short v2 = i2row[m];
        z1[i] = sh1[m] + sh2[v1 & 0x7FF] - 10000.f * (float)(v1 >> 15);
        z2[i] = sh2[m] + sh1[v2 & 0x7FF] - 10000.f * (float)(v2 >> 15);
        mx1 = fmaxf(mx1, z1[i]);
        mx2 = fmaxf(mx2, z2[i]);
    }
    mx1 = warpRedMax(mx1);
    mx2 = warpRedMax(mx2);
    if (lane == 0) { red[wid] = mx1; red[wid + 8] = mx2; }
    __syncthreads();
    if (wid == 0) {
        float a = (lane < 8) ? red[lane] : -1e30f;
        float b = (lane < 8) ? red[lane + 8] : -1e30f;
        a = warpRedMax(a);
        b = warpRedMax(b);
        if (lane == 0) { red[16] = a; red[17] = b; }
    }
    __syncthreads();
    mx1 = red[16];
    mx2 = red[17];

    float sum1 = 0.f, sum2 = 0.f;
#pragma unroll
    for (int i = 0; i < 8; i++) {
        z1[i] = __expf(z1[i] - mx1);
        z2[i] = __expf(z2[i] - mx2);
        sum1 += z1[i];
        sum2 += z2[i];
    }
    sum1 = warpRedSum(sum1);
    sum2 = warpRedSum(sum2);
    __syncthreads();
    if (lane == 0) { red[wid] = sum1; red[wid + 8] = sum2; }
    __syncthreads();
    if (wid == 0) {
        float a = (lane < 8) ? red[lane] : 0.f;
        float b = (lane < 8) ? red[lane + 8] : 0.f;
        a = warpRedSum(a);
        b = warpRedSum(b);
        if (lane == 0) { red[16] = a; red[17] = b; }
    }
    __syncthreads();
    float inv1 = 1.f / red[16];
    float inv2 = 1.f / red[17];
#pragma unroll
    for (int i = 0; i < 8; i++) {
        int m = tid + i * 256;
        s1row[m] = __float2half_rn(z1[i] * inv1);
        s2row[m] = __float2half_rn(z2[i] * inv2);
    }
}

// ============================ stage 4: AV + concat (1-term fp16) ============================
__global__ __launch_bounds__(256, 2)
void av_mma_kernel(float* __restrict__ out)
{
    const int z = blockIdx.z, mat = z >> 3, h = z & 7;
    const int bm = blockIdx.y * 128;
    const __half* Ab = reinterpret_cast<const __half*>(mat ? g_S2 : g_S1);
    const __half* aP = Ab + ((long long)h * N_TOK + bm) * 4096;
    const __half* bV = g_VT + (long long)(mat * 512 + h * 64) * 2048;

    float acc[2][4][4];
#pragma unroll
    for (int a = 0; a < 2; a++)
#pragma unroll
        for (int b = 0; b < 4; b++)
#pragma unroll
            for (int c = 0; c < 4; c++) acc[a][b][c] = 0.f;

    gemm_av(aP, 4096, bV, 2048, 2048, acc);

    const int wid = threadIdx.x >> 5, lane = threadIdx.x & 31;
    const int g = lane >> 2, t = lane & 3;
    const int wm = (wid >> 1) * 32, wn = (wid & 1) * 32;
    const int cbase = mat * 512 + h * 64;
#pragma unroll
    for (int mi = 0; mi < 2; mi++) {
        int m0 = bm + wm + mi * 16 + g;
#pragma unroll
        for (int ni = 0; ni < 4; ni++) {
            int col = cbase + wn + ni * 8 + 2 * t;
            *(float2*)(out + (long long)m0 * 1024 + col) =
                make_float2(acc[mi][ni][0], acc[mi][ni][1]);
            *(float2*)(out + (long long)(m0 + 8) * 1024 + col) =
                make_float2(acc[mi][ni][2], acc[mi][ni][3]);
        }
    }
}

// ============================ launch ============================
extern "C" void kernel_launch(void* const* d_in, const int* in_sizes, int n_in,
                              void* d_out, int out_size)
{
    const float* x   = (const float*)d_in[0];
    const float* fst = (const float*)d_in[1];
    const float* sec = (const float*)d_in[2];
    const int*   n2c = (const int*)d_in[3];
    const int*   c2n = (const int*)d_in[4];
    const float* Wq1 = (const float*)d_in[5];
    const float* bq1 = (const float*)d_in[6];
    const float* Wk1 = (const float*)d_in[7];
    const float* bk1 = (const float*)d_in[8];
    const float* Wv1 = (const float*)d_in[9];
    const float* bv1 = (const float*)d_in[10];
    const float* Wq2 = (const float*)d_in[11];
    const float* bq2 = (const float*)d_in[12];
    const float* Wk2 = (const float*)d_in[13];
    const float* bk2 = (const float*)d_in[14];
    const float* Wv2 = (const float*)d_in[15];
    const float* bv2 = (const float*)d_in[16];
    float* out = (float*)d_out;

    static bool attr_set = false;
    if (!attr_set) {
        cudaFuncSetAttribute(proj_mma_kernel, cudaFuncAttributeMaxDynamicSharedMemorySize, 40960);
        cudaFuncSetAttribute(score_mma_kernel, cudaFuncAttributeMaxDynamicSharedMemorySize, 40960);
        cudaFuncSetAttribute(av_mma_kernel, cudaFuncAttributeMaxDynamicSharedMemorySize, 30720);
        attr_set = true;
    }

    // stage 0: packed masked indices + fp16 conversions
    pack_kernel<<<dim3(64, 64), dim3(32, 8)>>>(c2n, n2c, fst, sec);
    convx_kernel<<<2048, 256>>>(x);
    convw_kernel<<<dim3(32, 32, 6), dim3(32, 8)>>>(Wq1, Wk1, Wq2, Wk2, Wv1, Wv2);

    // stage 1: projections (640 CTAs, 1-term fp16, Q pre-scaled)
    proj_mma_kernel<<<dim3(40, 16), 256, 40960>>>(bq1, bk1, bv1, bq2, bk2, bv2);

    // stage 2: scores (4096 CTAs, 1-term fp16, fp16 output)
    score_mma_kernel<<<dim3(16, 16, 16), 256, 40960>>>();

    // stage 3: gathered dual softmax (h-fastest grid) -> fp16 probs, in place
    softmax_gather_kernel<<<dim3(8, 2048), 256>>>();

    // stage 4: AV + concat (256 CTAs, 1-term fp16)
    av_mma_kernel<<<dim3(1, 16, 16), 256, 30720>>>(out);
}

// round 12
// speedup vs baseline: 2.8322x; 1.0185x over previous
#include <cuda_runtime.h>
#include <cuda_bf16.h>
#include <cuda_fp16.h>
#include <cstdint>

#define N_TOK 2048
#define NN (8LL * 2048 * 2048)

__device__ __forceinline__ uint32_t smem_to_u32(const void* p) {
    uint32_t a;
    asm("{ .reg .u64 t; cvta.to.shared.u64 t, %1; cvt.u32.u64 %0, t; }" : "=r"(a) : "l"(p));
    return a;
}

__device__ __forceinline__ void ldmatrix_x4(uint32_t& r0, uint32_t& r1, uint32_t& r2,
                                            uint32_t& r3, uint32_t addr) {
    asm volatile("ldmatrix.sync.aligned.m8n8.x4.shared.b16 {%0,%1,%2,%3}, [%4];"
                 : "=r"(r0), "=r"(r1), "=r"(r2), "=r"(r3) : "r"(addr));
}

__device__ __forceinline__ void mma16816h(float c[4], const uint32_t a[4], const uint32_t b[2]) {
    asm volatile(
        "mma.sync.aligned.m16n8k16.row.col.f32.f16.f16.f32 "
        "{%0,%1,%2,%3}, {%4,%5,%6,%7}, {%8,%9}, {%0,%1,%2,%3};"
        : "+f"(c[0]), "+f"(c[1]), "+f"(c[2]), "+f"(c[3])
        : "r"(a[0]), "r"(a[1]), "r"(a[2]), "r"(a[3]), "r"(b[0]), "r"(b[1]));
}

#define CP_ASYNC_CG(smem_addr, gmem_ptr) \
    asm volatile("cp.async.cg.shared.global [%0], [%1], 16;" \
                 :: "r"(smem_addr), "l"(gmem_ptr))
#define CP_ASYNC_COMMIT() asm volatile("cp.async.commit_group;" ::: "memory")
#define CP_ASYNC_WAIT(n)  asm volatile("cp.async.wait_group %0;" :: "n"(n) : "memory")

// ============================ device scratch ============================
__device__ __align__(16) __half g_Xs[2048 * 1024];       // X single fp16
__device__ __align__(16) __half g_WT[5242880];           // Wᵀ single fp16: q1,k1,q2,k2 (1M) + v1,v2 (512K), [N,K]
__device__ __align__(16) __half g_Qs[2][2048 * 1024];    // Q (pre-scaled) single fp16 per mat
__device__ __align__(16) __half g_Ks[2][2048 * 1024];    // K single fp16 per mat
__device__ __align__(16) __half g_VT[1024 * 2048];       // V single fp16, rows: mat*512+vcol, cols: token
__device__ __align__(16) float g_S1[NN];   // rows of 2048 fp32-slots: fp16 scores then fp16 probs in first half
__device__ __align__(16) float g_S2[NN];
__device__ __align__(16) unsigned short g_I1[2048LL * 2048]; // c2n u16 | mask1<<15
__device__ __align__(16) unsigned short g_I2[2048LL * 2048]; // n2c u16 | mask2<<15

// ============================ conversion kernels ============================
__global__ __launch_bounds__(256) void convx_kernel(const float* __restrict__ x) {
    int i = (blockIdx.x * 256 + threadIdx.x) * 4;
    float4 v = *(const float4*)(x + i);
    __half h[4] = {__float2half_rn(v.x), __float2half_rn(v.y),
                   __float2half_rn(v.z), __float2half_rn(v.w)};
    *(uint2*)&g_Xs[i] = *(uint2*)h;
}

__global__ __launch_bounds__(256)
void convw_kernel(const float* __restrict__ w0, const float* __restrict__ w1,
                  const float* __restrict__ w2, const float* __restrict__ w3,
                  const float* __restrict__ w4, const float* __restrict__ w5) {
    int z = blockIdx.z;
    const float* W;
    int Ncols;
    long long base;
    switch (z) {
        case 0: W = w0; Ncols = 1024; base = 0; break;
        case 1: W = w1; Ncols = 1024; base = 1048576; break;
        case 2: W = w2; Ncols = 1024; base = 2097152; break;
        case 3: W = w3; Ncols = 1024; base = 3145728; break;
        case 4: W = w4; Ncols = 512;  base = 4194304; break;
        default:W = w5; Ncols = 512;  base = 4718592; break;
    }
    int bn = blockIdx.x * 32, bk = blockIdx.y * 32;
    if (bn >= Ncols) return;
    __shared__ float t[32][33];
#pragma unroll
    for (int i = threadIdx.y; i < 32; i += 8)
        t[i][threadIdx.x] = W[(long long)(bk + i) * Ncols + bn + threadIdx.x];
    __syncthreads();
#pragma unroll
    for (int i = threadIdx.y; i < 32; i += 8) {
        long long o = base + (long long)(bn + i) * 1024 + bk + threadIdx.x;
        g_WT[o] = __float2half_rn(t[threadIdx.x][i]);
    }
}

// pack indices + transposed graph masks: I1[n][m] = c2n[n][m] | (fst[m][n]==0)<<15
__global__ void pack_kernel(const int* __restrict__ c2n, const int* __restrict__ n2c,
                            const float* __restrict__ G1, const float* __restrict__ G2) {
    __shared__ float t1[32][33];
    __shared__ float t2[32][33];
    const int bx = blockIdx.x * 32;   // n-tile
    const int by = blockIdx.y * 32;   // m-tile
#pragma unroll
    for (int i = threadIdx.y; i < 32; i += 8) {
        t1[i][threadIdx.x] = G1[(long long)(by + i) * N_TOK + bx + threadIdx.x];
        t2[i][threadIdx.x] = G2[(long long)(by + i) * N_TOK + bx + threadIdx.x];
    }
    __syncthreads();
#pragma unroll
    for (int i = threadIdx.y; i < 32; i += 8) {
        int n = bx + i;
        int m = by + threadIdx.x;
        long long o = (long long)n * N_TOK + m;
        unsigned short v1 = (unsigned short)c2n[o];
        unsigned short v2 = (unsigned short)n2c[o];
        if (t1[threadIdx.x][i] == 0.f) v1 |= 0x8000;
        if (t2[threadIdx.x][i] == 0.f) v2 |= 0x8000;
        g_I1[o] = v1;
        g_I2[o] = v2;
    }
}

// ============================ 3-stage 1-term fp16 GEMM body (proj & score) ============================
// acc[4][4][4] += A(128,K) * B(128,K)^T, both single fp16.
// Warp grid 2x4. Stage: [A 10240 | B 10240], STG=20480, 3 buffers, 1 sync/chunk.
__device__ __forceinline__ void gemm_1t(
    const __half* __restrict__ aS, int lda,
    const __half* __restrict__ bS, int ldb,
    int K, float acc[4][4][4])
{
    constexpr int OFF_B = 10240;
    constexpr int STG = 20480;
    extern __shared__ __align__(16) char sm[];
    const uint32_t smb = smem_to_u32(sm);
    const int tid = threadIdx.x;
    const int wid = tid >> 5, lane = tid & 31;
    const int wm = (wid >> 2) * 64;
    const int wn = (wid & 3) * 32;
    const int a_row = wm + (lane & 7) + ((lane >> 3) & 1) * 8;
    const int a_cofs = (lane >> 4) * 8;
    const int b_row = wn + (lane & 7) + ((lane >> 4) & 1) * 8;
    const int b_cofs = ((lane >> 3) & 1) * 8;

    const int r_cp = tid >> 2;
    const int c_cp = (tid & 3) * 8;
    const int NC = K >> 5;

    auto issue_stage = [&](int ic) {
        const uint32_t sb = smb + (uint32_t)(ic % 3) * STG;
        const int k0 = ic * 32;
#pragma unroll
        for (int i = 0; i < 2; i++) {
            int r = r_cp + i * 64;
            uint32_t so = (uint32_t)(r * 80 + c_cp * 2);
            CP_ASYNC_CG(sb + so, aS + (long long)r * lda + k0 + c_cp);
            CP_ASYNC_CG(sb + OFF_B + so, bS + (long long)r * ldb + k0 + c_cp);
        }
        CP_ASYNC_COMMIT();
    };

    issue_stage(0);
    if (NC > 1) issue_stage(1);
    for (int ic = 0; ic < NC; ic++) {
        if (ic + 1 < NC) { CP_ASYNC_WAIT(1); }
        else             { CP_ASYNC_WAIT(0); }
        __syncthreads();
        if (ic + 2 < NC) issue_stage(ic + 2);
        const uint32_t sb = smb + (uint32_t)(ic % 3) * STG;
#pragma unroll
        for (int ks = 0; ks < 32; ks += 16) {
            uint32_t aq[4][4], bb[4][2];
#pragma unroll
            for (int mi = 0; mi < 4; mi++) {
                uint32_t off = (uint32_t)(((a_row + mi * 16) * 40 + ks + a_cofs) * 2);
                ldmatrix_x4(aq[mi][0], aq[mi][1], aq[mi][2], aq[mi][3], sb + off);
            }
#pragma unroll
            for (int nj = 0; nj < 2; nj++) {
                uint32_t off = (uint32_t)(((b_row + nj * 16) * 40 + ks + b_cofs) * 2);
                ldmatrix_x4(bb[nj * 2][0], bb[nj * 2][1], bb[nj * 2 + 1][0], bb[nj * 2 + 1][1],
                            sb + OFF_B + off);
            }
#pragma unroll
            for (int mi = 0; mi < 4; mi++)
#pragma unroll
                for (int ni = 0; ni < 4; ni++)
                    mma16816h(acc[mi][ni], aq[mi], bb[ni]);
        }
        __syncthreads();
    }
}

// ============================ 3-stage 1-term fp16 AV GEMM body ============================
__device__ __forceinline__ void gemm_av(
    const __half* __restrict__ aP, int lda,
    const __half* __restrict__ bS, int ldb,
    int K, float acc[2][4][4])
{
    constexpr int OFF_B = 10240;
    constexpr int STG = 15360;
    extern __shared__ __align__(16) char sm[];
    const uint32_t smb = smem_to_u32(sm);
    const int tid = threadIdx.x;
    const int wid = tid >> 5, lane = tid & 31;
    const int wm = (wid >> 1) * 32;
    const int wn = (wid & 1) * 32;
    const int a_row = wm + (lane & 7) + ((lane >> 3) & 1) * 8;
    const int a_cofs = (lane >> 4) * 8;
    const int b_row = wn + (lane & 7) + ((lane >> 4) & 1) * 8;
    const int b_cofs = ((lane >> 3) & 1) * 8;

    const int r_cp = tid >> 2;
    const int c_cp = (tid & 3) * 8;
    const int NC = K >> 5;

    auto issue_stage = [&](int ic) {
        const uint32_t sb = smb + (uint32_t)(ic % 3) * STG;
        const int k0 = ic * 32;
#pragma unroll
        for (int i = 0; i < 2; i++) {
            int r = r_cp + i * 64;
            uint32_t so = (uint32_t)(r * 80 + c_cp * 2);
            CP_ASYNC_CG(sb + so, aP + (long long)r * lda + k0 + c_cp);
        }
        {
            int r = r_cp;
            uint32_t so = (uint32_t)(r * 80 + c_cp * 2);
            CP_ASYNC_CG(sb + OFF_B + so, bS + (long long)r * ldb + k0 + c_cp);
        }
        CP_ASYNC_COMMIT();
    };

    issue_stage(0);
    if (NC > 1) issue_stage(1);
    for (int ic = 0; ic < NC; ic++) {
        if (ic + 1 < NC) { CP_ASYNC_WAIT(1); }
        else             { CP_ASYNC_WAIT(0); }
        __syncthreads();
        if (ic + 2 < NC) issue_stage(ic + 2);
        const uint32_t sb = smb + (uint32_t)(ic % 3) * STG;
#pragma unroll
        for (int ks = 0; ks < 32; ks += 16) {
            uint32_t ap[2][4], bb[4][2];
#pragma unroll
            for (int mi = 0; mi < 2; mi++) {
                uint32_t off = (uint32_t)(((a_row + mi * 16) * 40 + ks + a_cofs) * 2);
                ldmatrix_x4(ap[mi][0], ap[mi][1], ap[mi][2], ap[mi][3], sb + off);
            }
#pragma unroll
            for (int nj = 0; nj < 2; nj++) {
                uint32_t off = (uint32_t)(((b_row + nj * 16) * 40 + ks + b_cofs) * 2);
                ldmatrix_x4(bb[nj * 2][0], bb[nj * 2][1], bb[nj * 2 + 1][0], bb[nj * 2 + 1][1],
                            sb + OFF_B + off);
            }
#pragma unroll
            for (int mi = 0; mi < 2; mi++)
#pragma unroll
                for (int ni = 0; ni < 4; ni++)
                    mma16816h(acc[mi][ni], ap[mi], bb[ni]);
        }
        __syncthreads();
    }
}

// ============================ stage 1: projections (1-term fp16, Q pre-scaled) ============================
__global__ __launch_bounds__(256, 2)
void proj_mma_kernel(const float* __restrict__ bq1, const float* __restrict__ bk1,
                     const float* __restrict__ bv1, const float* __restrict__ bq2,
                     const float* __restrict__ bk2, const float* __restrict__ bv2)
{
    const float scale = 0.08838834764831845f;  // 1/sqrt(128), folded into Q
    const int cb = blockIdx.x;
    const int bm = blockIdx.y * 128;
    const __half* bW;
    const float* bias;
    int r, bnl;
    if (cb < 32) {
        r = cb >> 3; bnl = (cb & 7) * 128;
        bW = g_WT + (long long)r * 1048576 + (long long)bnl * 1024;
        bias = (r == 0) ? bq1 : (r == 1) ? bk1 : (r == 2) ? bq2 : bk2;
    } else {
        r = (cb - 32) >> 2; bnl = ((cb - 32) & 3) * 128;
        bW = g_WT + 4194304LL + (long long)r * 524288 + (long long)bnl * 1024;
        bias = r ? bv2 : bv1;
    }
    float acc[4][4][4];
#pragma unroll
    for (int a = 0; a < 4; a++)
#pragma unroll
        for (int b = 0; b < 4; b++)
#pragma unroll
            for (int c = 0; c < 4; c++) acc[a][b][c] = 0.f;

    gemm_1t(g_Xs + (long long)bm * 1024, 1024, bW, 1024, 1024, acc);

    const int wid = threadIdx.x >> 5, lane = threadIdx.x & 31;
    const int g = lane >> 2, t = lane & 3;
    const int wm = (wid >> 2) * 64, wn = (wid & 3) * 32;
    const bool isQ = (cb < 32) && ((r & 1) == 0);
    const float outscale = isQ ? scale : 1.f;
#pragma unroll
    for (int mi = 0; mi < 4; mi++) {
        int m0 = bm + wm + mi * 16 + g;
#pragma unroll
        for (int ni = 0; ni < 4; ni++) {
            int col = bnl + wn + ni * 8 + 2 * t;
            float b0 = bias[col], b1 = bias[col + 1];
            float v00 = (acc[mi][ni][0] + b0) * outscale, v01 = (acc[mi][ni][1] + b1) * outscale;
            float v10 = (acc[mi][ni][2] + b0) * outscale, v11 = (acc[mi][ni][3] + b1) * outscale;
            __half h00 = __float2half_rn(v00), h01 = __float2half_rn(v01);
            __half h10 = __float2half_rn(v10), h11 = __float2half_rn(v11);
            if (cb < 32) {
                int mat = r >> 1;
                __half* dst = (r & 1) ? g_Ks[mat] : g_Qs[mat];
                long long o0 = (long long)m0 * 1024 + col;
                long long o1 = (long long)(m0 + 8) * 1024 + col;
                *(__half2*)&dst[o0] = __halves2half2(h00, h01);
                *(__half2*)&dst[o1] = __halves2half2(h10, h11);
            } else {
                int c0 = r * 512 + col, c1 = c0 + 1;
                g_VT[(long long)c0 * 2048 + m0] = h00;
                g_VT[(long long)c1 * 2048 + m0] = h01;
                g_VT[(long long)c0 * 2048 + m0 + 8] = h10;
                g_VT[(long long)c1 * 2048 + m0 + 8] = h11;
            }
        }
    }
}

// ============================ stage 2: scores (1-term fp16, fp16 output) ============================
__global__ __launch_bounds__(256, 2)
void score_mma_kernel()
{
    const int z = blockIdx.z, mat = z >> 3, h = z & 7;
    const int bm = blockIdx.y * 128, bn = blockIdx.x * 128;
    const __half* q = g_Qs[mat] + (long long)bm * 1024 + h * 128;
    const __half* k = g_Ks[mat] + (long long)bn * 1024 + h * 128;

    float acc[4][4][4];
#pragma unroll
    for (int a = 0; a < 4; a++)
#pragma unroll
        for (int b = 0; b < 4; b++)
#pragma unroll
            for (int c = 0; c < 4; c++) acc[a][b][c] = 0.f;

    gemm_1t(q, 1024, k, 1024, 128, acc);

    __half* S = reinterpret_cast<__half*>((mat ? g_S2 : g_S1));
    const int wid = threadIdx.x >> 5, lane = threadIdx.x & 31;
    const int g = lane >> 2, t = lane & 3;
    const int wm = (wid >> 2) * 64, wn = (wid & 3) * 32;
    const long long hbase = (long long)h * N_TOK * 4096;
#pragma unroll
    for (int mi = 0; mi < 4; mi++) {
        int m0 = bm + wm + mi * 16 + g;
#pragma unroll
        for (int ni = 0; ni < 4; ni++) {
            int n0 = bn + wn + ni * 8 + 2 * t;
            *(__half2*)&S[hbase + (long long)m0 * 4096 + n0] =
                __halves2half2(__float2half_rn(acc[mi][ni][0]),
                               __float2half_rn(acc[mi][ni][1]));
            *(__half2*)&S[hbase + (long long)(m0 + 8) * 4096 + n0] =
                __halves2half2(__float2half_rn(acc[mi][ni][2]),
                               __float2half_rn(acc[mi][ni][3]));
        }
    }
}

// ============================ stage 3: dual gathered softmax ============================
__device__ __forceinline__ float warpRedMax(float v) {
#pragma unroll
    for (int o = 16; o > 0; o >>= 1) v = fmaxf(v, __shfl_xor_sync(0xffffffffu, v, o));
    return v;
}
__device__ __forceinline__ float warpRedSum(float v) {
#pragma unroll
    for (int o = 16; o > 0; o >>= 1) v += __shfl_xor_sync(0xffffffffu, v, o);
    return v;
}

// grid (8, 2048): h fastest -> packed index rows L2-resident across the 8 head CTAs
__global__ __launch_bounds__(256)
void softmax_gather_kernel()
{
    const int h = blockIdx.x;
    const int n = blockIdx.y;
    __half* s1row = reinterpret_cast<__half*>(g_S1) + ((long long)h * N_TOK + n) * 4096;
    __half* s2row = reinterpret_cast<__half*>(g_S2) + ((long long)h * N_TOK + n) * 4096;
    __shared__ float sh1[N_TOK];
    __shared__ float sh2[N_TOK];
    __shared__ float red[32];
    const int tid = threadIdx.x;
    const int lane = tid & 31, wid = tid >> 5;

    {
        uint4 v1 = *(const uint4*)(s1row + tid * 8);
        uint4 v2 = *(const uint4*)(s2row + tid * 8);
        const __half2* p1 = (const __half2*)&v1;
        const __half2* p2 = (const __half2*)&v2;
#pragma unroll
        for (int j = 0; j < 4; j++) {
            float2 f1 = __half22float2(p1[j]);
            float2 f2 = __half22float2(p2[j]);
            sh1[tid * 8 + 2 * j] = f1.x;
            sh1[tid * 8 + 2 * j + 1] = f1.y;
            sh2[tid * 8 + 2 * j] = f2.x;
            sh2[tid * 8 + 2 * j + 1] = f2.y;
        }
    }
    __syncthreads();

    const unsigned short* i1row = g_I1 + (long long)n * N_TOK;
    const unsigned short* i2row = g_I2 + (long long)n * N_TOK;

    float z1[8], z2[8];
    float mx1 = -1e30f, mx2 = -1e30f;
#pragma unroll
    for (int i = 0; i < 8; i++) {
        int m = tid + i * 256;
        unsigned short v1 = i1row[m];
        unsigned short v2 = i2row[m];
        z1[i] = sh1[m] + sh2[v1 & 0x7FF] - 10000.f * (float)(v1 >> 15);
        z2[i] = sh2[m] + sh1[v2 & 0x7FF] - 10000.f * (float)(v2 >> 15);
        mx1 = fmaxf(mx1, z1[i]);
        mx2 = fmaxf(mx2, z2[i]);
    }
    mx1 = warpRedMax(mx1);
    mx2 = warpRedMax(mx2);
    if (lane == 0) { red[wid] = mx1; red[wid + 8] = mx2; }
    __syncthreads();
    if (wid == 0) {
        float a = (lane < 8) ? red[lane] : -1e30f;
        float b = (lane < 8) ? red[lane + 8] : -1e30f;
        a = warpRedMax(a);
        b = warpRedMax(b);
        if (lane == 0) { red[16] = a; red[17] = b; }
    }
    __syncthreads();
    mx1 = red[16];
    mx2 = red[17];

    float sum1 = 0.f, sum2 = 0.f;
#pragma unroll
    for (int i = 0; i < 8; i++) {
        z1[i] = __expf(z1[i] - mx1);
        z2[i] = __expf(z2[i] - mx2);
        sum1 += z1[i];
        sum2 += z2[i];
    }
    sum1 = warpRedSum(sum1);
    sum2 = warpRedSum(sum2);
    __syncthreads();
    if (lane == 0) { red[wid] = sum1; red[wid + 8] = sum2; }
    __syncthreads();
    if (wid == 0) {
        float a = (lane < 8) ? red[lane] : 0.f;
        float b = (lane < 8) ? red[lane + 8] : 0.f;
        a = warpRedSum(a);
        b = warpRedSum(b);
        if (lane == 0) { red[16] = a; red[17] = b; }
    }
    __syncthreads();
    float inv1 = 1.f / red[16];
    float inv2 = 1.f / red[17];
#pragma unroll
    for (int i = 0; i < 8; i++) {
        int m = tid + i * 256;
        s1row[m] = __float2half_rn(z1[i] * inv1);
        s2row[m] = __float2half_rn(z2[i] * inv2);
    }
}

// ============================ stage 4: AV + concat (1-term fp16) ============================
__global__ __launch_bounds__(256, 2)
void av_mma_kernel(float* __restrict__ out)
{
    const int z = blockIdx.z, mat = z >> 3, h = z & 7;
    const int bm = blockIdx.y * 128;
    const __half* Ab = reinterpret_cast<const __half*>(mat ? g_S2 : g_S1);
    const __half* aP = Ab + ((long long)h * N_TOK + bm) * 4096;
    const __half* bV = g_VT + (long long)(mat * 512 + h * 64) * 2048;

    float acc[2][4][4];
#pragma unroll
    for (int a = 0; a < 2; a++)
#pragma unroll
        for (int b = 0; b < 4; b++)
#pragma unroll
            for (int c = 0; c < 4; c++) acc[a][b][c] = 0.f;

    gemm_av(aP, 4096, bV, 2048, 2048, acc);

    const int wid = threadIdx.x >> 5, lane = threadIdx.x & 31;
    const int g = lane >> 2, t = lane & 3;
    const int wm = (wid >> 1) * 32, wn = (wid & 1) * 32;
    const int cbase = mat * 512 + h * 64;
#pragma unroll
    for (int mi = 0; mi < 2; mi++) {
        int m0 = bm + wm + mi * 16 + g;
#pragma unroll
        for (int ni = 0; ni < 4; ni++) {
            int col = cbase + wn + ni * 8 + 2 * t;
            *(float2*)(out + (long long)m0 * 1024 + col) =
                make_float2(acc[mi][ni][0], acc[mi][ni][1]);
            *(float2*)(out + (long long)(m0 + 8) * 1024 + col) =
                make_float2(acc[mi][ni][2], acc[mi][ni][3]);
        }
    }
}

// ============================ launch ============================
extern "C" void kernel_launch(void* const* d_in, const int* in_sizes, int n_in,
                              void* d_out, int out_size)
{
    const float* x   = (const float*)d_in[0];
    const float* fst = (const float*)d_in[1];
    const float* sec = (const float*)d_in[2];
    const int*   n2c = (const int*)d_in[3];
    const int*   c2n = (const int*)d_in[4];
    const float* Wq1 = (const float*)d_in[5];
    const float* bq1 = (const float*)d_in[6];
    const float* Wk1 = (const float*)d_in[7];
    const float* bk1 = (const float*)d_in[8];
    const float* Wv1 = (const float*)d_in[9];
    const float* bv1 = (const float*)d_in[10];
    const float* Wq2 = (const float*)d_in[11];
    const float* bq2 = (const float*)d_in[12];
    const float* Wk2 = (const float*)d_in[13];
    const float* bk2 = (const float*)d_in[14];
    const float* Wv2 = (const float*)d_in[15];
    const float* bv2 = (const float*)d_in[16];
    float* out = (float*)d_out;

    static bool attr_set = false;
    if (!attr_set) {
        cudaFuncSetAttribute(proj_mma_kernel, cudaFuncAttributeMaxDynamicSharedMemorySize, 61440);
        cudaFuncSetAttribute(score_mma_kernel, cudaFuncAttributeMaxDynamicSharedMemorySize, 61440);
        cudaFuncSetAttribute(av_mma_kernel, cudaFuncAttributeMaxDynamicSharedMemorySize, 46080);
        attr_set = true;
    }

    // stage 0: packed masked indices + fp16 conversions
    pack_kernel<<<dim3(64, 64), dim3(32, 8)>>>(c2n, n2c, fst, sec);
    convx_kernel<<<2048, 256>>>(x);
    convw_kernel<<<dim3(32, 32, 6), dim3(32, 8)>>>(Wq1, Wk1, Wq2, Wk2, Wv1, Wv2);

    // stage 1: projections (640 CTAs, 1-term fp16, 3-stage pipeline)
    proj_mma_kernel<<<dim3(40, 16), 256, 61440>>>(bq1, bk1, bv1, bq2, bk2, bv2);

    // stage 2: scores (4096 CTAs, 1-term fp16, fp16 output)
    score_mma_kernel<<<dim3(16, 16, 16), 256, 61440>>>();

    // stage 3: gathered dual softmax (h-fastest grid) -> fp16 probs, in place
    softmax_gather_kernel<<<dim3(8, 2048), 256>>>();

    // stage 4: AV + concat (256 CTAs, 1-term fp16, 3-stage pipeline)
    av_mma_kernel<<<dim3(1, 16, 16), 256, 46080>>>(out);
}

// round 13
// speedup vs baseline: 2.9789x; 1.0518x over previous
#include <cuda_runtime.h>
#include <cuda_bf16.h>
#include <cuda_fp16.h>
#include <cstdint>

#define N_TOK 2048
#define NN (8LL * 2048 * 2048)

__device__ __forceinline__ uint32_t smem_to_u32(const void* p) {
    uint32_t a;
    asm("{ .reg .u64 t; cvta.to.shared.u64 t, %1; cvt.u32.u64 %0, t; }" : "=r"(a) : "l"(p));
    return a;
}

__device__ __forceinline__ void ldmatrix_x4(uint32_t& r0, uint32_t& r1, uint32_t& r2,
                                            uint32_t& r3, uint32_t addr) {
    asm volatile("ldmatrix.sync.aligned.m8n8.x4.shared.b16 {%0,%1,%2,%3}, [%4];"
                 : "=r"(r0), "=r"(r1), "=r"(r2), "=r"(r3) : "r"(addr));
}

__device__ __forceinline__ void mma16816h(float c[4], const uint32_t a[4], const uint32_t b[2]) {
    asm volatile(
        "mma.sync.aligned.m16n8k16.row.col.f32.f16.f16.f32 "
        "{%0,%1,%2,%3}, {%4,%5,%6,%7}, {%8,%9}, {%0,%1,%2,%3};"
        : "+f"(c[0]), "+f"(c[1]), "+f"(c[2]), "+f"(c[3])
        : "r"(a[0]), "r"(a[1]), "r"(a[2]), "r"(a[3]), "r"(b[0]), "r"(b[1]));
}

#define CP_ASYNC_CG(smem_addr, gmem_ptr) \
    asm volatile("cp.async.cg.shared.global [%0], [%1], 16;" \
                 :: "r"(smem_addr), "l"(gmem_ptr))
#define CP_ASYNC_COMMIT() asm volatile("cp.async.commit_group;" ::: "memory")
#define CP_ASYNC_WAIT(n)  asm volatile("cp.async.wait_group %0;" :: "n"(n) : "memory")

// ============================ device scratch ============================
__device__ __align__(16) __half g_Xs[2048 * 1024];       // X single fp16
__device__ __align__(16) __half g_WT[5242880];           // Wᵀ single fp16: q1,k1,q2,k2 (1M) + v1,v2 (512K), [N,K]
__device__ __align__(16) __half g_Qs[2][2048 * 1024];    // Q (pre-scaled) single fp16 per mat
__device__ __align__(16) __half g_Ks[2][2048 * 1024];    // K single fp16 per mat
__device__ __align__(16) __half g_VT[1024 * 2048];       // V single fp16, rows: mat*512+vcol, cols: token
__device__ __align__(16) float g_S1[NN];   // rows of 2048 fp32-slots: fp16 scores then fp16 probs in first half
__device__ __align__(16) float g_S2[NN];
__device__ __align__(16) unsigned short g_I1[2048LL * 2048]; // c2n u16 | mask1<<15
__device__ __align__(16) unsigned short g_I2[2048LL * 2048]; // n2c u16 | mask2<<15

// ============================ conversion kernels ============================
__global__ __launch_bounds__(256) void convx_kernel(const float* __restrict__ x) {
    int i = (blockIdx.x * 256 + threadIdx.x) * 4;
    float4 v = *(const float4*)(x + i);
    __half h[4] = {__float2half_rn(v.x), __float2half_rn(v.y),
                   __float2half_rn(v.z), __float2half_rn(v.w)};
    *(uint2*)&g_Xs[i] = *(uint2*)h;
}

__global__ __launch_bounds__(256)
void convw_kernel(const float* __restrict__ w0, const float* __restrict__ w1,
                  const float* __restrict__ w2, const float* __restrict__ w3,
                  const float* __restrict__ w4, const float* __restrict__ w5) {
    int z = blockIdx.z;
    const float* W;
    int Ncols;
    long long base;
    switch (z) {
        case 0: W = w0; Ncols = 1024; base = 0; break;
        case 1: W = w1; Ncols = 1024; base = 1048576; break;
        case 2: W = w2; Ncols = 1024; base = 2097152; break;
        case 3: W = w3; Ncols = 1024; base = 3145728; break;
        case 4: W = w4; Ncols = 512;  base = 4194304; break;
        default:W = w5; Ncols = 512;  base = 4718592; break;
    }
    int bn = blockIdx.x * 32, bk = blockIdx.y * 32;
    if (bn >= Ncols) return;
    __shared__ float t[32][33];
#pragma unroll
    for (int i = threadIdx.y; i < 32; i += 8)
        t[i][threadIdx.x] = W[(long long)(bk + i) * Ncols + bn + threadIdx.x];
    __syncthreads();
#pragma unroll
    for (int i = threadIdx.y; i < 32; i += 8) {
        long long o = base + (long long)(bn + i) * 1024 + bk + threadIdx.x;
        g_WT[o] = __float2half_rn(t[threadIdx.x][i]);
    }
}

// pack indices + transposed graph masks: I1[n][m] = c2n[n][m] | (fst[m][n]==0)<<15
__global__ void pack_kernel(const int* __restrict__ c2n, const int* __restrict__ n2c,
                            const float* __restrict__ G1, const float* __restrict__ G2) {
    __shared__ float t1[32][33];
    __shared__ float t2[32][33];
    const int bx = blockIdx.x * 32;   // n-tile
    const int by = blockIdx.y * 32;   // m-tile
#pragma unroll
    for (int i = threadIdx.y; i < 32; i += 8) {
        t1[i][threadIdx.x] = G1[(long long)(by + i) * N_TOK + bx + threadIdx.x];
        t2[i][threadIdx.x] = G2[(long long)(by + i) * N_TOK + bx + threadIdx.x];
    }
    __syncthreads();
#pragma unroll
    for (int i = threadIdx.y; i < 32; i += 8) {
        int n = bx + i;
        int m = by + threadIdx.x;
        long long o = (long long)n * N_TOK + m;
        unsigned short v1 = (unsigned short)c2n[o];
        unsigned short v2 = (unsigned short)n2c[o];
        if (t1[threadIdx.x][i] == 0.f) v1 |= 0x8000;
        if (t2[threadIdx.x][i] == 0.f) v2 |= 0x8000;
        g_I1[o] = v1;
        g_I2[o] = v2;
    }
}

// ============================ 3-stage chunk-64 GEMM body (proj) ============================
// acc[4][4][4] += A(128,K) * B(128,K)^T, single fp16. Row pad: 72 halfs (144B).
// Stage: [A 18432 | B 18432] = 36864 B, 3 buffers.
__device__ __forceinline__ void gemm_c64(
    const __half* __restrict__ aS, int lda,
    const __half* __restrict__ bS, int ldb,
    int K, float acc[4][4][4])
{
    constexpr int OFF_B = 18432;
    constexpr int STG = 36864;
    extern __shared__ __align__(16) char sm[];
    const uint32_t smb = smem_to_u32(sm);
    const int tid = threadIdx.x;
    const int wid = tid >> 5, lane = tid & 31;
    const int wm = (wid >> 2) * 64;
    const int wn = (wid & 3) * 32;
    const int a_row = wm + (lane & 7) + ((lane >> 3) & 1) * 8;
    const int a_cofs = (lane >> 4) * 8;
    const int b_row = wn + (lane & 7) + ((lane >> 4) & 1) * 8;
    const int b_cofs = ((lane >> 3) & 1) * 8;

    const int r_cp = tid >> 3;          // 0..31 (x8 iters covers 128 rows? no: idx scheme below)
    const int NC = K >> 6;

    auto issue_stage = [&](int ic) {
        const uint32_t sb = smb + (uint32_t)(ic % 3) * STG;
        const int k0 = ic * 64;
#pragma unroll
        for (int i = 0; i < 4; i++) {
            int idx = i * 256 + tid;
            int r = idx >> 3, c8 = idx & 7;
            uint32_t so = (uint32_t)(r * 144 + c8 * 16);
            CP_ASYNC_CG(sb + so, aS + (long long)r * lda + k0 + c8 * 8);
            CP_ASYNC_CG(sb + OFF_B + so, bS + (long long)r * ldb + k0 + c8 * 8);
        }
        CP_ASYNC_COMMIT();
    };

    issue_stage(0);
    if (NC > 1) issue_stage(1);
    for (int ic = 0; ic < NC; ic++) {
        if (ic + 1 < NC) { CP_ASYNC_WAIT(1); }
        else             { CP_ASYNC_WAIT(0); }
        __syncthreads();
        if (ic + 2 < NC) issue_stage(ic + 2);
        const uint32_t sb = smb + (uint32_t)(ic % 3) * STG;
#pragma unroll
        for (int ks = 0; ks < 64; ks += 16) {
            uint32_t aq[4][4], bb[4][2];
#pragma unroll
            for (int mi = 0; mi < 4; mi++) {
                uint32_t off = (uint32_t)(((a_row + mi * 16) * 72 + ks + a_cofs) * 2);
                ldmatrix_x4(aq[mi][0], aq[mi][1], aq[mi][2], aq[mi][3], sb + off);
            }
#pragma unroll
            for (int nj = 0; nj < 2; nj++) {
                uint32_t off = (uint32_t)(((b_row + nj * 16) * 72 + ks + b_cofs) * 2);
                ldmatrix_x4(bb[nj * 2][0], bb[nj * 2][1], bb[nj * 2 + 1][0], bb[nj * 2 + 1][1],
                            sb + OFF_B + off);
            }
#pragma unroll
            for (int mi = 0; mi < 4; mi++)
#pragma unroll
                for (int ni = 0; ni < 4; ni++)
                    mma16816h(acc[mi][ni], aq[mi], bb[ni]);
        }
        __syncthreads();
    }
}

// ============================ 3-stage chunk-64 AV GEMM body ============================
// acc[2][4][4] += P(128,K) * V(64,K)^T. Stage: [A 18432 | B 9216] = 27648 B.
__device__ __forceinline__ void gemm_av(
    const __half* __restrict__ aP, int lda,
    const __half* __restrict__ bS, int ldb,
    int K, float acc[2][4][4])
{
    constexpr int OFF_B = 18432;
    constexpr int STG = 27648;
    extern __shared__ __align__(16) char sm[];
    const uint32_t smb = smem_to_u32(sm);
    const int tid = threadIdx.x;
    const int wid = tid >> 5, lane = tid & 31;
    const int wm = (wid >> 1) * 32;
    const int wn = (wid & 1) * 32;
    const int a_row = wm + (lane & 7) + ((lane >> 3) & 1) * 8;
    const int a_cofs = (lane >> 4) * 8;
    const int b_row = wn + (lane & 7) + ((lane >> 4) & 1) * 8;
    const int b_cofs = ((lane >> 3) & 1) * 8;

    const int NC = K >> 6;

    auto issue_stage = [&](int ic) {
        const uint32_t sb = smb + (uint32_t)(ic % 3) * STG;
        const int k0 = ic * 64;
#pragma unroll
        for (int i = 0; i < 4; i++) {
            int idx = i * 256 + tid;
            int r = idx >> 3, c8 = idx & 7;
            uint32_t so = (uint32_t)(r * 144 + c8 * 16);
            CP_ASYNC_CG(sb + so, aP + (long long)r * lda + k0 + c8 * 8);
        }
#pragma unroll
        for (int i = 0; i < 2; i++) {
            int idx = i * 256 + tid;
            int r = idx >> 3, c8 = idx & 7;
            uint32_t so = (uint32_t)(r * 144 + c8 * 16);
            CP_ASYNC_CG(sb + OFF_B + so, bS + (long long)r * ldb + k0 + c8 * 8);
        }
        CP_ASYNC_COMMIT();
    };

    issue_stage(0);
    if (NC > 1) issue_stage(1);
    for (int ic = 0; ic < NC; ic++) {
        if (ic + 1 < NC) { CP_ASYNC_WAIT(1); }
        else             { CP_ASYNC_WAIT(0); }
        __syncthreads();
        if (ic + 2 < NC) issue_stage(ic + 2);
        const uint32_t sb = smb + (uint32_t)(ic % 3) * STG;
#pragma unroll
        for (int ks = 0; ks < 64; ks += 16) {
            uint32_t ap[2][4], bb[4][2];
#pragma unroll
            for (int mi = 0; mi < 2; mi++) {
                uint32_t off = (uint32_t)(((a_row + mi * 16) * 72 + ks + a_cofs) * 2);
                ldmatrix_x4(ap[mi][0], ap[mi][1], ap[mi][2], ap[mi][3], sb + off);
            }
#pragma unroll
            for (int nj = 0; nj < 2; nj++) {
                uint32_t off = (uint32_t)(((b_row + nj * 16) * 72 + ks + b_cofs) * 2);
                ldmatrix_x4(bb[nj * 2][0], bb[nj * 2][1], bb[nj * 2 + 1][0], bb[nj * 2 + 1][1],
                            sb + OFF_B + off);
            }
#pragma unroll
            for (int mi = 0; mi < 2; mi++)
#pragma unroll
                for (int ni = 0; ni < 4; ni++)
                    mma16816h(acc[mi][ni], ap[mi], bb[ni]);
        }
        __syncthreads();
    }
}

// ============================ stage 1: projections (chunk-64 pipeline) ============================
__global__ __launch_bounds__(256, 2)
void proj_mma_kernel(const float* __restrict__ bq1, const float* __restrict__ bk1,
                     const float* __restrict__ bv1, const float* __restrict__ bq2,
                     const float* __restrict__ bk2, const float* __restrict__ bv2)
{
    const float scale = 0.08838834764831845f;  // 1/sqrt(128), folded into Q
    const int cb = blockIdx.x;
    const int bm = blockIdx.y * 128;
    const __half* bW;
    const float* bias;
    int r, bnl;
    if (cb < 32) {
        r = cb >> 3; bnl = (cb & 7) * 128;
        bW = g_WT + (long long)r * 1048576 + (long long)bnl * 1024;
        bias = (r == 0) ? bq1 : (r == 1) ? bk1 : (r == 2) ? bq2 : bk2;
    } else {
        r = (cb - 32) >> 2; bnl = ((cb - 32) & 3) * 128;
        bW = g_WT + 4194304LL + (long long)r * 524288 + (long long)bnl * 1024;
        bias = r ? bv2 : bv1;
    }
    float acc[4][4][4];
#pragma unroll
    for (int a = 0; a < 4; a++)
#pragma unroll
        for (int b = 0; b < 4; b++)
#pragma unroll
            for (int c = 0; c < 4; c++) acc[a][b][c] = 0.f;

    gemm_c64(g_Xs + (long long)bm * 1024, 1024, bW, 1024, 1024, acc);

    const int wid = threadIdx.x >> 5, lane = threadIdx.x & 31;
    const int g = lane >> 2, t = lane & 3;
    const int wm = (wid >> 2) * 64, wn = (wid & 3) * 32;
    const bool isQ = (cb < 32) && ((r & 1) == 0);
    const float outscale = isQ ? scale : 1.f;
#pragma unroll
    for (int mi = 0; mi < 4; mi++) {
        int m0 = bm + wm + mi * 16 + g;
#pragma unroll
        for (int ni = 0; ni < 4; ni++) {
            int col = bnl + wn + ni * 8 + 2 * t;
            float b0 = bias[col], b1 = bias[col + 1];
            float v00 = (acc[mi][ni][0] + b0) * outscale, v01 = (acc[mi][ni][1] + b1) * outscale;
            float v10 = (acc[mi][ni][2] + b0) * outscale, v11 = (acc[mi][ni][3] + b1) * outscale;
            __half h00 = __float2half_rn(v00), h01 = __float2half_rn(v01);
            __half h10 = __float2half_rn(v10), h11 = __float2half_rn(v11);
            if (cb < 32) {
                int mat = r >> 1;
                __half* dst = (r & 1) ? g_Ks[mat] : g_Qs[mat];
                long long o0 = (long long)m0 * 1024 + col;
                long long o1 = (long long)(m0 + 8) * 1024 + col;
                *(__half2*)&dst[o0] = __halves2half2(h00, h01);
                *(__half2*)&dst[o1] = __halves2half2(h10, h11);
            } else {
                int c0 = r * 512 + col, c1 = c0 + 1;
                g_VT[(long long)c0 * 2048 + m0] = h00;
                g_VT[(long long)c1 * 2048 + m0] = h01;
                g_VT[(long long)c0 * 2048 + m0 + 8] = h10;
                g_VT[(long long)c1 * 2048 + m0 + 8] = h11;
            }
        }
    }
}

// ============================ stage 2: scores (single-shot K=128) ============================
// smem: A (q tile) at 0, B (k tile) at 34816; rows padded to 136 halfs (272B).
__global__ __launch_bounds__(256, 2)
void score_mma_kernel()
{
    constexpr int OFF_B = 34816;
    extern __shared__ __align__(16) char sm[];
    const uint32_t smb = smem_to_u32(sm);
    const int z = blockIdx.z, mat = z >> 3, h = z & 7;
    const int bm = blockIdx.y * 128, bn = blockIdx.x * 128;
    const __half* q = g_Qs[mat] + (long long)bm * 1024 + h * 128;
    const __half* k = g_Ks[mat] + (long long)bn * 1024 + h * 128;
    const int tid = threadIdx.x;

    // one-shot load of both 128x128 tiles
#pragma unroll
    for (int i = 0; i < 8; i++) {
        int idx = i * 256 + tid;
        int r = idx >> 4, c16 = idx & 15;
        uint32_t so = (uint32_t)(r * 272 + c16 * 16);
        CP_ASYNC_CG(smb + so, q + (long long)r * 1024 + c16 * 8);
        CP_ASYNC_CG(smb + OFF_B + so, k + (long long)r * 1024 + c16 * 8);
    }
    CP_ASYNC_COMMIT();

    float acc[4][4][4];
#pragma unroll
    for (int a = 0; a < 4; a++)
#pragma unroll
        for (int b = 0; b < 4; b++)
#pragma unroll
            for (int c = 0; c < 4; c++) acc[a][b][c] = 0.f;

    const int wid = tid >> 5, lane = tid & 31;
    const int wm = (wid >> 2) * 64;
    const int wn = (wid & 3) * 32;
    const int a_row = wm + (lane & 7) + ((lane >> 3) & 1) * 8;
    const int a_cofs = (lane >> 4) * 8;
    const int b_row = wn + (lane & 7) + ((lane >> 4) & 1) * 8;
    const int b_cofs = ((lane >> 3) & 1) * 8;

    CP_ASYNC_WAIT(0);
    __syncthreads();

#pragma unroll
    for (int ks = 0; ks < 128; ks += 16) {
        uint32_t aq[4][4], bb[4][2];
#pragma unroll
        for (int mi = 0; mi < 4; mi++) {
            uint32_t off = (uint32_t)(((a_row + mi * 16) * 136 + ks + a_cofs) * 2);
            ldmatrix_x4(aq[mi][0], aq[mi][1], aq[mi][2], aq[mi][3], smb + off);
        }
#pragma unroll
        for (int nj = 0; nj < 2; nj++) {
            uint32_t off = (uint32_t)(((b_row + nj * 16) * 136 + ks + b_cofs) * 2);
            ldmatrix_x4(bb[nj * 2][0], bb[nj * 2][1], bb[nj * 2 + 1][0], bb[nj * 2 + 1][1],
                        smb + OFF_B + off);
        }
#pragma unroll
        for (int mi = 0; mi < 4; mi++)
#pragma unroll
            for (int ni = 0; ni < 4; ni++)
                mma16816h(acc[mi][ni], aq[mi], bb[ni]);
    }

    __half* S = reinterpret_cast<__half*>((mat ? g_S2 : g_S1));
    const int g = lane >> 2, t = lane & 3;
    const long long hbase = (long long)h * N_TOK * 4096;
#pragma unroll
    for (int mi = 0; mi < 4; mi++) {
        int m0 = bm + wm + mi * 16 + g;
#pragma unroll
        for (int ni = 0; ni < 4; ni++) {
            int n0 = bn + wn + ni * 8 + 2 * t;
            *(__half2*)&S[hbase + (long long)m0 * 4096 + n0] =
                __halves2half2(__float2half_rn(acc[mi][ni][0]),
                               __float2half_rn(acc[mi][ni][1]));
            *(__half2*)&S[hbase + (long long)(m0 + 8) * 4096 + n0] =
                __halves2half2(__float2half_rn(acc[mi][ni][2]),
                               __float2half_rn(acc[mi][ni][3]));
        }
    }
}

// ============================ stage 3: dual gathered softmax ============================
__device__ __forceinline__ float warpRedMax(float v) {
#pragma unroll
    for (int o = 16; o > 0; o >>= 1) v = fmaxf(v, __shfl_xor_sync(0xffffffffu, v, o));
    return v;
}
__device__ __forceinline__ float warpRedSum(float v) {
#pragma unroll
    for (int o = 16; o > 0; o >>= 1) v += __shfl_xor_sync(0xffffffffu, v, o);
    return v;
}

// grid (8, 2048): h fastest -> packed index rows L2-resident across the 8 head CTAs
__global__ __launch_bounds__(256)
void softmax_gather_kernel()
{
    const int h = blockIdx.x;
    const int n = blockIdx.y;
    __half* s1row = reinterpret_cast<__half*>(g_S1) + ((long long)h * N_TOK + n) * 4096;
    __half* s2row = reinterpret_cast<__half*>(g_S2) + ((long long)h * N_TOK + n) * 4096;
    __shared__ float sh1[N_TOK];
    __shared__ float sh2[N_TOK];
    __shared__ float red[32];
    const int tid = threadIdx.x;
    const int lane = tid & 31, wid = tid >> 5;

    {
        uint4 v1 = *(const uint4*)(s1row + tid * 8);
        uint4 v2 = *(const uint4*)(s2row + tid * 8);
        const __half2* p1 = (const __half2*)&v1;
        const __half2* p2 = (const __half2*)&v2;
#pragma unroll
        for (int j = 0; j < 4; j++) {
            float2 f1 = __half22float2(p1[j]);
            float2 f2 = __half22float2(p2[j]);
            sh1[tid * 8 + 2 * j] = f1.x;
            sh1[tid * 8 + 2 * j + 1] = f1.y;
            sh2[tid * 8 + 2 * j] = f2.x;
            sh2[tid * 8 + 2 * j + 1] = f2.y;
        }
    }
    __syncthreads();

    const unsigned short* i1row = g_I1 + (long long)n * N_TOK;
    const unsigned short* i2row = g_I2 + (long long)n * N_TOK;

    float z1[8], z2[8];
    float mx1 = -1e30f, mx2 = -1e30f;
#pragma unroll
    for (int i = 0; i < 8; i++) {
        int m = tid + i * 256;
        unsigned short v1 = i1row[m];
        unsigned short v2 = i2row[m];
        z1[i] = sh1[m] + sh2[v1 & 0x7FF] - 10000.f * (float)(v1 >> 15);
        z2[i] = sh2[m] + sh1[v2 & 0x7FF] - 10000.f * (float)(v2 >> 15);
        mx1 = fmaxf(mx1, z1[i]);
        mx2 = fmaxf(mx2, z2[i]);
    }
    mx1 = warpRedMax(mx1);
    mx2 = warpRedMax(mx2);
    if (lane == 0) { red[wid] = mx1; red[wid + 8] = mx2; }
    __syncthreads();
    if (wid == 0) {
        float a = (lane < 8) ? red[lane] : -1e30f;
        float b = (lane < 8) ? red[lane + 8] : -1e30f;
        a = warpRedMax(a);
        b = warpRedMax(b);
        if (lane == 0) { red[16] = a; red[17] = b; }
    }
    __syncthreads();
    mx1 = red[16];
    mx2 = red[17];

    float sum1 = 0.f, sum2 = 0.f;
#pragma unroll
    for (int i = 0; i < 8; i++) {
        z1[i] = __expf(z1[i] - mx1);
        z2[i] = __expf(z2[i] - mx2);
        sum1 += z1[i];
        sum2 += z2[i];
    }
    sum1 = warpRedSum(sum1);
    sum2 = warpRedSum(sum2);
    __syncthreads();
    if (lane == 0) { red[wid] = sum1; red[wid + 8] = sum2; }
    __syncthreads();
    if (wid == 0) {
        float a = (lane < 8) ? red[lane] : 0.f;
        float b = (lane < 8) ? red[lane + 8] : 0.f;
        a = warpRedSum(a);
        b = warpRedSum(b);
        if (lane == 0) { red[16] = a; red[17] = b; }
    }
    __syncthreads();
    float inv1 = 1.f / red[16];
    float inv2 = 1.f / red[17];
#pragma unroll
    for (int i = 0; i < 8; i++) {
        int m = tid + i * 256;
        s1row[m] = __float2half_rn(z1[i] * inv1);
        s2row[m] = __float2half_rn(z2[i] * inv2);
    }
}

// ============================ stage 4: AV + concat (chunk-64 pipeline) ============================
__global__ __launch_bounds__(256, 2)
void av_mma_kernel(float* __restrict__ out)
{
    const int z = blockIdx.z, mat = z >> 3, h = z & 7;
    const int bm = blockIdx.y * 128;
    const __half* Ab = reinterpret_cast<const __half*>(mat ? g_S2 : g_S1);
    const __half* aP = Ab + ((long long)h * N_TOK + bm) * 4096;
    const __half* bV = g_VT + (long long)(mat * 512 + h * 64) * 2048;

    float acc[2][4][4];
#pragma unroll
    for (int a = 0; a < 2; a++)
#pragma unroll
        for (int b = 0; b < 4; b++)
#pragma unroll
            for (int c = 0; c < 4; c++) acc[a][b][c] = 0.f;

    gemm_av(aP, 4096, bV, 2048, 2048, acc);

    const int wid = threadIdx.x >> 5, lane = threadIdx.x & 31;
    const int g = lane >> 2, t = lane & 3;
    const int wm = (wid >> 1) * 32, wn = (wid & 1) * 32;
    const int cbase = mat * 512 + h * 64;
#pragma unroll
    for (int mi = 0; mi < 2; mi++) {
        int m0 = bm + wm + mi * 16 + g;
#pragma unroll
        for (int ni = 0; ni < 4; ni++) {
            int col = cbase + wn + ni * 8 + 2 * t;
            *(float2*)(out + (long long)m0 * 1024 + col) =
                make_float2(acc[mi][ni][0], acc[mi][ni][1]);
            *(float2*)(out + (long long)(m0 + 8) * 1024 + col) =
                make_float2(acc[mi][ni][2], acc[mi][ni][3]);
        }
    }
}

// ============================ launch ============================
extern "C" void kernel_launch(void* const* d_in, const int* in_sizes, int n_in,
                              void* d_out, int out_size)
{
    const float* x   = (const float*)d_in[0];
    const float* fst = (const float*)d_in[1];
    const float* sec = (const float*)d_in[2];
    const int*   n2c = (const int*)d_in[3];
    const int*   c2n = (const int*)d_in[4];
    const float* Wq1 = (const float*)d_in[5];
    const float* bq1 = (const float*)d_in[6];
    const float* Wk1 = (const float*)d_in[7];
    const float* bk1 = (const float*)d_in[8];
    const float* Wv1 = (const float*)d_in[9];
    const float* bv1 = (const float*)d_in[10];
    const float* Wq2 = (const float*)d_in[11];
    const float* bq2 = (const float*)d_in[12];
    const float* Wk2 = (const float*)d_in[13];
    const float* bk2 = (const float*)d_in[14];
    const float* Wv2 = (const float*)d_in[15];
    const float* bv2 = (const float*)d_in[16];
    float* out = (float*)d_out;

    static bool attr_set = false;
    if (!attr_set) {
        cudaFuncSetAttribute(proj_mma_kernel, cudaFuncAttributeMaxDynamicSharedMemorySize, 110592);
        cudaFuncSetAttribute(score_mma_kernel, cudaFuncAttributeMaxDynamicSharedMemorySize, 69632);
        cudaFuncSetAttribute(av_mma_kernel, cudaFuncAttributeMaxDynamicSharedMemorySize, 82944);
        attr_set = true;
    }

    // stage 0: packed masked indices + fp16 conversions
    pack_kernel<<<dim3(64, 64), dim3(32, 8)>>>(c2n, n2c, fst, sec);
    convx_kernel<<<2048, 256>>>(x);
    convw_kernel<<<dim3(32, 32, 6), dim3(32, 8)>>>(Wq1, Wk1, Wq2, Wk2, Wv1, Wv2);

    // stage 1: projections (640 CTAs, chunk-64 3-stage pipeline)
    proj_mma_kernel<<<dim3(40, 16), 256, 110592>>>(bq1, bk1, bv1, bq2, bk2, bv2);

    // stage 2: scores (4096 CTAs, single-shot K=128, zero compute barriers)
    score_mma_kernel<<<dim3(16, 16, 16), 256, 69632>>>();

    // stage 3: gathered dual softmax (h-fastest grid) -> fp16 probs, in place
    softmax_gather_kernel<<<dim3(8, 2048), 256>>>();

    // stage 4: AV + concat (256 CTAs, chunk-64 3-stage pipeline)
    av_mma_kernel<<<dim3(1, 16, 16), 256, 82944>>>(out);
}

// round 14
// speedup vs baseline: 3.0417x; 1.0211x over previous
#include <cuda_runtime.h>
#include <cuda_bf16.h>
#include <cuda_fp16.h>
#include <cstdint>

#define N_TOK 2048
#define NN (8LL * 2048 * 2048)

__device__ __forceinline__ uint32_t smem_to_u32(const void* p) {
    uint32_t a;
    asm("{ .reg .u64 t; cvta.to.shared.u64 t, %1; cvt.u32.u64 %0, t; }" : "=r"(a) : "l"(p));
    return a;
}

__device__ __forceinline__ void ldmatrix_x4(uint32_t& r0, uint32_t& r1, uint32_t& r2,
                                            uint32_t& r3, uint32_t addr) {
    asm volatile("ldmatrix.sync.aligned.m8n8.x4.shared.b16 {%0,%1,%2,%3}, [%4];"
                 : "=r"(r0), "=r"(r1), "=r"(r2), "=r"(r3) : "r"(addr));
}

__device__ __forceinline__ void mma16816h(float c[4], const uint32_t a[4], const uint32_t b[2]) {
    asm volatile(
        "mma.sync.aligned.m16n8k16.row.col.f32.f16.f16.f32 "
        "{%0,%1,%2,%3}, {%4,%5,%6,%7}, {%8,%9}, {%0,%1,%2,%3};"
        : "+f"(c[0]), "+f"(c[1]), "+f"(c[2]), "+f"(c[3])
        : "r"(a[0]), "r"(a[1]), "r"(a[2]), "r"(a[3]), "r"(b[0]), "r"(b[1]));
}

#define CP_ASYNC_CG(smem_addr, gmem_ptr) \
    asm volatile("cp.async.cg.shared.global [%0], [%1], 16;" \
                 :: "r"(smem_addr), "l"(gmem_ptr))
#define CP_ASYNC_COMMIT() asm volatile("cp.async.commit_group;" ::: "memory")
#define CP_ASYNC_WAIT(n)  asm volatile("cp.async.wait_group %0;" :: "n"(n) : "memory")

// ============================ device scratch ============================
__device__ __align__(16) __half g_Xs[2048 * 1024];       // X single fp16
__device__ __align__(16) __half g_WT[5242880];           // Wᵀ single fp16: q1,k1,q2,k2 (1M) + v1,v2 (512K), [N,K]
__device__ __align__(16) __half g_Qs[2][2048 * 1024];    // Q (pre-scaled) single fp16 per mat
__device__ __align__(16) __half g_Ks[2][2048 * 1024];    // K single fp16 per mat
__device__ __align__(16) __half g_VT[1024 * 2048];       // V single fp16, rows: mat*512+vcol, cols: token
__device__ __align__(16) float g_S1[NN];   // rows of 2048 fp32-slots: fp16 scores then fp16 probs in first half
__device__ __align__(16) float g_S2[NN];
__device__ __align__(16) unsigned short g_I1[2048LL * 2048]; // c2n u16 | mask1<<15
__device__ __align__(16) unsigned short g_I2[2048LL * 2048]; // n2c u16 | mask2<<15

// ============================ fused stage-0 conversion kernel ============================
// grid.x = 12288 CTAs of (32,8):
//   [0,4096)      pack: indices + transposed graph masks
//   [4096,6144)   convx: X fp32 -> fp16
//   [6144,12288)  convw: W fp32 -> Wᵀ fp16
__global__ __launch_bounds__(256)
void stage0_kernel(const int* __restrict__ c2n, const int* __restrict__ n2c,
                   const float* __restrict__ G1, const float* __restrict__ G2,
                   const float* __restrict__ x,
                   const float* __restrict__ w0, const float* __restrict__ w1,
                   const float* __restrict__ w2, const float* __restrict__ w3,
                   const float* __restrict__ w4, const float* __restrict__ w5)
{
    const int bid = blockIdx.x;
    const int tx = threadIdx.x, ty = threadIdx.y;
    const int tid = ty * 32 + tx;

    if (bid < 4096) {
        // ---- pack: I[n][m] = idx | (G[m][n]==0)<<15 ----
        __shared__ float t1[32][33];
        __shared__ float t2[32][33];
        const int bx = (bid & 63) * 32;   // n-tile
        const int by = (bid >> 6) * 32;   // m-tile
#pragma unroll
        for (int i = ty; i < 32; i += 8) {
            t1[i][tx] = G1[(long long)(by + i) * N_TOK + bx + tx];
            t2[i][tx] = G2[(long long)(by + i) * N_TOK + bx + tx];
        }
        __syncthreads();
#pragma unroll
        for (int i = ty; i < 32; i += 8) {
            int n = bx + i;
            int m = by + tx;
            long long o = (long long)n * N_TOK + m;
            unsigned short v1 = (unsigned short)c2n[o];
            unsigned short v2 = (unsigned short)n2c[o];
            if (t1[tx][i] == 0.f) v1 |= 0x8000;
            if (t2[tx][i] == 0.f) v2 |= 0x8000;
            g_I1[o] = v1;
            g_I2[o] = v2;
        }
    } else if (bid < 6144) {
        // ---- convx ----
        int i = ((bid - 4096) * 256 + tid) * 4;
        float4 v = *(const float4*)(x + i);
        __half h[4] = {__float2half_rn(v.x), __float2half_rn(v.y),
                       __float2half_rn(v.z), __float2half_rn(v.w)};
        *(uint2*)&g_Xs[i] = *(uint2*)h;
    } else {
        // ---- convw: transpose W[K,N] -> WT[N,K] fp16 ----
        int idx = bid - 6144;
        int z = idx >> 10;         // 0..5
        int xy = idx & 1023;
        int bn = (xy & 31) * 32, bk = (xy >> 5) * 32;
        const float* W;
        int Ncols;
        long long base;
        switch (z) {
            case 0: W = w0; Ncols = 1024; base = 0; break;
            case 1: W = w1; Ncols = 1024; base = 1048576; break;
            case 2: W = w2; Ncols = 1024; base = 2097152; break;
            case 3: W = w3; Ncols = 1024; base = 3145728; break;
            case 4: W = w4; Ncols = 512;  base = 4194304; break;
            default:W = w5; Ncols = 512;  base = 4718592; break;
        }
        if (bn >= Ncols) return;
        __shared__ float t[32][33];
#pragma unroll
        for (int i = ty; i < 32; i += 8)
            t[i][tx] = W[(long long)(bk + i) * Ncols + bn + tx];
        __syncthreads();
#pragma unroll
        for (int i = ty; i < 32; i += 8) {
            long long o = base + (long long)(bn + i) * 1024 + bk + tx;
            g_WT[o] = __float2half_rn(t[tx][i]);
        }
    }
}

// ============================ 3-stage chunk-64 GEMM body (proj), 1 barrier/chunk ============================
// acc[4][4][4] += A(128,K) * B(128,K)^T, single fp16. Row pad: 72 halfs (144B).
// Stage: [A 18432 | B 18432] = 36864 B, 3 buffers.
__device__ __forceinline__ void gemm_c64(
    const __half* __restrict__ aS, int lda,
    const __half* __restrict__ bS, int ldb,
    int K, float acc[4][4][4])
{
    constexpr int OFF_B = 18432;
    constexpr int STG = 36864;
    extern __shared__ __align__(16) char sm[];
    const uint32_t smb = smem_to_u32(sm);
    const int tid = threadIdx.x;
    const int wid = tid >> 5, lane = tid & 31;
    const int wm = (wid >> 2) * 64;
    const int wn = (wid & 3) * 32;
    const int a_row = wm + (lane & 7) + ((lane >> 3) & 1) * 8;
    const int a_cofs = (lane >> 4) * 8;
    const int b_row = wn + (lane & 7) + ((lane >> 4) & 1) * 8;
    const int b_cofs = ((lane >> 3) & 1) * 8;

    const int NC = K >> 6;

    auto issue_stage = [&](int ic) {
        const uint32_t sb = smb + (uint32_t)(ic % 3) * STG;
        const int k0 = ic * 64;
#pragma unroll
        for (int i = 0; i < 4; i++) {
            int idx = i * 256 + tid;
            int r = idx >> 3, c8 = idx & 7;
            uint32_t so = (uint32_t)(r * 144 + c8 * 16);
            CP_ASYNC_CG(sb + so, aS + (long long)r * lda + k0 + c8 * 8);
            CP_ASYNC_CG(sb + OFF_B + so, bS + (long long)r * ldb + k0 + c8 * 8);
        }
        CP_ASYNC_COMMIT();
    };

    issue_stage(0);
    if (NC > 1) issue_stage(1);
    for (int ic = 0; ic < NC; ic++) {
        if (ic + 1 < NC) { CP_ASYNC_WAIT(1); }
        else             { CP_ASYNC_WAIT(0); }
        __syncthreads();   // single barrier per chunk: separates compute(ic-1) from issue(ic+2)
        if (ic + 2 < NC) issue_stage(ic + 2);
        const uint32_t sb = smb + (uint32_t)(ic % 3) * STG;
#pragma unroll
        for (int ks = 0; ks < 64; ks += 16) {
            uint32_t aq[4][4], bb[4][2];
#pragma unroll
            for (int mi = 0; mi < 4; mi++) {
                uint32_t off = (uint32_t)(((a_row + mi * 16) * 72 + ks + a_cofs) * 2);
                ldmatrix_x4(aq[mi][0], aq[mi][1], aq[mi][2], aq[mi][3], sb + off);
            }
#pragma unroll
            for (int nj = 0; nj < 2; nj++) {
                uint32_t off = (uint32_t)(((b_row + nj * 16) * 72 + ks + b_cofs) * 2);
                ldmatrix_x4(bb[nj * 2][0], bb[nj * 2][1], bb[nj * 2 + 1][0], bb[nj * 2 + 1][1],
                            sb + OFF_B + off);
            }
#pragma unroll
            for (int mi = 0; mi < 4; mi++)
#pragma unroll
                for (int ni = 0; ni < 4; ni++)
                    mma16816h(acc[mi][ni], aq[mi], bb[ni]);
        }
    }
}

// ============================ 3-stage chunk-64 AV GEMM body, 1 barrier/chunk ============================
// acc[2][4][4] += P(128,K) * V(64,K)^T. Stage: [A 18432 | B 9216] = 27648 B.
__device__ __forceinline__ void gemm_av(
    const __half* __restrict__ aP, int lda,
    const __half* __restrict__ bS, int ldb,
    int K, float acc[2][4][4])
{
    constexpr int OFF_B = 18432;
    constexpr int STG = 27648;
    extern __shared__ __align__(16) char sm[];
    const uint32_t smb = smem_to_u32(sm);
    const int tid = threadIdx.x;
    const int wid = tid >> 5, lane = tid & 31;
    const int wm = (wid >> 1) * 32;
    const int wn = (wid & 1) * 32;
    const int a_row = wm + (lane & 7) + ((lane >> 3) & 1) * 8;
    const int a_cofs = (lane >> 4) * 8;
    const int b_row = wn + (lane & 7) + ((lane >> 4) & 1) * 8;
    const int b_cofs = ((lane >> 3) & 1) * 8;

    const int NC = K >> 6;

    auto issue_stage = [&](int ic) {
        const uint32_t sb = smb + (uint32_t)(ic % 3) * STG;
        const int k0 = ic * 64;
#pragma unroll
        for (int i = 0; i < 4; i++) {
            int idx = i * 256 + tid;
            int r = idx >> 3, c8 = idx & 7;
            uint32_t so = (uint32_t)(r * 144 + c8 * 16);
            CP_ASYNC_CG(sb + so, aP + (long long)r * lda + k0 + c8 * 8);
        }
#pragma unroll
        for (int i = 0; i < 2; i++) {
            int idx = i * 256 + tid;
            int r = idx >> 3, c8 = idx & 7;
            uint32_t so = (uint32_t)(r * 144 + c8 * 16);
            CP_ASYNC_CG(sb + OFF_B + so, bS + (long long)r * ldb + k0 + c8 * 8);
        }
        CP_ASYNC_COMMIT();
    };

    issue_stage(0);
    if (NC > 1) issue_stage(1);
    for (int ic = 0; ic < NC; ic++) {
        if (ic + 1 < NC) { CP_ASYNC_WAIT(1); }
        else             { CP_ASYNC_WAIT(0); }
        __syncthreads();
        if (ic + 2 < NC) issue_stage(ic + 2);
        const uint32_t sb = smb + (uint32_t)(ic % 3) * STG;
#pragma unroll
        for (int ks = 0; ks < 64; ks += 16) {
            uint32_t ap[2][4], bb[4][2];
#pragma unroll
            for (int mi = 0; mi < 2; mi++) {
                uint32_t off = (uint32_t)(((a_row + mi * 16) * 72 + ks + a_cofs) * 2);
                ldmatrix_x4(ap[mi][0], ap[mi][1], ap[mi][2], ap[mi][3], sb + off);
            }
#pragma unroll
            for (int nj = 0; nj < 2; nj++) {
                uint32_t off = (uint32_t)(((b_row + nj * 16) * 72 + ks + b_cofs) * 2);
                ldmatrix_x4(bb[nj * 2][0], bb[nj * 2][1], bb[nj * 2 + 1][0], bb[nj * 2 + 1][1],
                            sb + OFF_B + off);
            }
#pragma unroll
            for (int mi = 0; mi < 2; mi++)
#pragma unroll
                for (int ni = 0; ni < 4; ni++)
                    mma16816h(acc[mi][ni], ap[mi], bb[ni]);
        }
    }
}

// ============================ stage 1: projections (chunk-64 pipeline) ============================
__global__ __launch_bounds__(256, 2)
void proj_mma_kernel(const float* __restrict__ bq1, const float* __restrict__ bk1,
                     const float* __restrict__ bv1, const float* __restrict__ bq2,
                     const float* __restrict__ bk2, const float* __restrict__ bv2)
{
    const float scale = 0.08838834764831845f;  // 1/sqrt(128), folded into Q
    const int cb = blockIdx.x;
    const int bm = blockIdx.y * 128;
    const __half* bW;
    const float* bias;
    int r, bnl;
    if (cb < 32) {
        r = cb >> 3; bnl = (cb & 7) * 128;
        bW = g_WT + (long long)r * 1048576 + (long long)bnl * 1024;
        bias = (r == 0) ? bq1 : (r == 1) ? bk1 : (r == 2) ? bq2 : bk2;
    } else {
        r = (cb - 32) >> 2; bnl = ((cb - 32) & 3) * 128;
        bW = g_WT + 4194304LL + (long long)r * 524288 + (long long)bnl * 1024;
        bias = r ? bv2 : bv1;
    }
    float acc[4][4][4];
#pragma unroll
    for (int a = 0; a < 4; a++)
#pragma unroll
        for (int b = 0; b < 4; b++)
#pragma unroll
            for (int c = 0; c < 4; c++) acc[a][b][c] = 0.f;

    gemm_c64(g_Xs + (long long)bm * 1024, 1024, bW, 1024, 1024, acc);

    const int wid = threadIdx.x >> 5, lane = threadIdx.x & 31;
    const int g = lane >> 2, t = lane & 3;
    const int wm = (wid >> 2) * 64, wn = (wid & 3) * 32;
    const bool isQ = (cb < 32) && ((r & 1) == 0);
    const float outscale = isQ ? scale : 1.f;
#pragma unroll
    for (int mi = 0; mi < 4; mi++) {
        int m0 = bm + wm + mi * 16 + g;
#pragma unroll
        for (int ni = 0; ni < 4; ni++) {
            int col = bnl + wn + ni * 8 + 2 * t;
            float b0 = bias[col], b1 = bias[col + 1];
            float v00 = (acc[mi][ni][0] + b0) * outscale, v01 = (acc[mi][ni][1] + b1) * outscale;
            float v10 = (acc[mi][ni][2] + b0) * outscale, v11 = (acc[mi][ni][3] + b1) * outscale;
            __half h00 = __float2half_rn(v00), h01 = __float2half_rn(v01);
            __half h10 = __float2half_rn(v10), h11 = __float2half_rn(v11);
            if (cb < 32) {
                int mat = r >> 1;
                __half* dst = (r & 1) ? g_Ks[mat] : g_Qs[mat];
                long long o0 = (long long)m0 * 1024 + col;
                long long o1 = (long long)(m0 + 8) * 1024 + col;
                *(__half2*)&dst[o0] = __halves2half2(h00, h01);
                *(__half2*)&dst[o1] = __halves2half2(h10, h11);
            } else {
                int c0 = r * 512 + col, c1 = c0 + 1;
                g_VT[(long long)c0 * 2048 + m0] = h00;
                g_VT[(long long)c1 * 2048 + m0] = h01;
                g_VT[(long long)c0 * 2048 + m0 + 8] = h10;
                g_VT[(long long)c1 * 2048 + m0 + 8] = h11;
            }
        }
    }
}

// ============================ stage 2: scores (single-shot K=128) ============================
// smem: A (q tile) at 0, B (k tile) at 34816; rows padded to 136 halfs (272B).
__global__ __launch_bounds__(256, 2)
void score_mma_kernel()
{
    constexpr int OFF_B = 34816;
    extern __shared__ __align__(16) char sm[];
    const uint32_t smb = smem_to_u32(sm);
    const int z = blockIdx.z, mat = z >> 3, h = z & 7;
    const int bm = blockIdx.y * 128, bn = blockIdx.x * 128;
    const __half* q = g_Qs[mat] + (long long)bm * 1024 + h * 128;
    const __half* k = g_Ks[mat] + (long long)bn * 1024 + h * 128;
    const int tid = threadIdx.x;

    // one-shot load of both 128x128 tiles
#pragma unroll
    for (int i = 0; i < 8; i++) {
        int idx = i * 256 + tid;
        int r = idx >> 4, c16 = idx & 15;
        uint32_t so = (uint32_t)(r * 272 + c16 * 16);
        CP_ASYNC_CG(smb + so, q + (long long)r * 1024 + c16 * 8);
        CP_ASYNC_CG(smb + OFF_B + so, k + (long long)r * 1024 + c16 * 8);
    }
    CP_ASYNC_COMMIT();

    float acc[4][4][4];
#pragma unroll
    for (int a = 0; a < 4; a++)
#pragma unroll
        for (int b = 0; b < 4; b++)
#pragma unroll
            for (int c = 0; c < 4; c++) acc[a][b][c] = 0.f;

    const int wid = tid >> 5, lane = tid & 31;
    const int wm = (wid >> 2) * 64;
    const int wn = (wid & 3) * 32;
    const int a_row = wm + (lane & 7) + ((lane >> 3) & 1) * 8;
    const int a_cofs = (lane >> 4) * 8;
    const int b_row = wn + (lane & 7) + ((lane >> 4) & 1) * 8;
    const int b_cofs = ((lane >> 3) & 1) * 8;

    CP_ASYNC_WAIT(0);
    __syncthreads();

#pragma unroll
    for (int ks = 0; ks < 128; ks += 16) {
        uint32_t aq[4][4], bb[4][2];
#pragma unroll
        for (int mi = 0; mi < 4; mi++) {
            uint32_t off = (uint32_t)(((a_row + mi * 16) * 136 + ks + a_cofs) * 2);
            ldmatrix_x4(aq[mi][0], aq[mi][1], aq[mi][2], aq[mi][3], smb + off);
        }
#pragma unroll
        for (int nj = 0; nj < 2; nj++) {
            uint32_t off = (uint32_t)(((b_row + nj * 16) * 136 + ks + b_cofs) * 2);
            ldmatrix_x4(bb[nj * 2][0], bb[nj * 2][1], bb[nj * 2 + 1][0], bb[nj * 2 + 1][1],
                        smb + OFF_B + off);
        }
#pragma unroll
        for (int mi = 0; mi < 4; mi++)
#pragma unroll
            for (int ni = 0; ni < 4; ni++)
                mma16816h(acc[mi][ni], aq[mi], bb[ni]);
    }

    __half* S = reinterpret_cast<__half*>((mat ? g_S2 : g_S1));
    const int g = lane >> 2, t = lane & 3;
    const long long hbase = (long long)h * N_TOK * 4096;
#pragma unroll
    for (int mi = 0; mi < 4; mi++) {
        int m0 = bm + wm + mi * 16 + g;
#pragma unroll
        for (int ni = 0; ni < 4; ni++) {
            int n0 = bn + wn + ni * 8 + 2 * t;
            *(__half2*)&S[hbase + (long long)m0 * 4096 + n0] =
                __halves2half2(__float2half_rn(acc[mi][ni][0]),
                               __float2half_rn(acc[mi][ni][1]));
            *(__half2*)&S[hbase + (long long)(m0 + 8) * 4096 + n0] =
                __halves2half2(__float2half_rn(acc[mi][ni][2]),
                               __float2half_rn(acc[mi][ni][3]));
        }
    }
}

// ============================ stage 3: dual gathered softmax ============================
__device__ __forceinline__ float warpRedMax(float v) {
#pragma unroll
    for (int o = 16; o > 0; o >>= 1) v = fmaxf(v, __shfl_xor_sync(0xffffffffu, v, o));
    return v;
}
__device__ __forceinline__ float warpRedSum(float v) {
#pragma unroll
    for (int o = 16; o > 0; o >>= 1) v += __shfl_xor_sync(0xffffffffu, v, o);
    return v;
}

// grid (8, 2048): h fastest -> packed index rows L2-resident across the 8 head CTAs
__global__ __launch_bounds__(256)
void softmax_gather_kernel()
{
    const int h = blockIdx.x;
    const int n = blockIdx.y;
    __half* s1row = reinterpret_cast<__half*>(g_S1) + ((long long)h * N_TOK + n) * 4096;
    __half* s2row = reinterpret_cast<__half*>(g_S2) + ((long long)h * N_TOK + n) * 4096;
    __shared__ float sh1[N_TOK];
    __shared__ float sh2[N_TOK];
    __shared__ float red[32];
    const int tid = threadIdx.x;
    const int lane = tid & 31, wid = tid >> 5;

    {
        uint4 v1 = *(const uint4*)(s1row + tid * 8);
        uint4 v2 = *(const uint4*)(s2row + tid * 8);
        const __half2* p1 = (const __half2*)&v1;
        const __half2* p2 = (const __half2*)&v2;
#pragma unroll
        for (int j = 0; j < 4; j++) {
            float2 f1 = __half22float2(p1[j]);
            float2 f2 = __half22float2(p2[j]);
            sh1[tid * 8 + 2 * j] = f1.x;
            sh1[tid * 8 + 2 * j + 1] = f1.y;
            sh2[tid * 8 + 2 * j] = f2.x;
            sh2[tid * 8 + 2 * j + 1] = f2.y;
        }
    }
    __syncthreads();

    const unsigned short* i1row = g_I1 + (long long)n * N_TOK;
    const unsigned short* i2row = g_I2 + (long long)n * N_TOK;

    float z1[8], z2[8];
    float mx1 = -1e30f, mx2 = -1e30f;
#pragma unroll
    for (int i = 0; i < 8; i++) {
        int m = tid + i * 256;
        unsigned short v1 = i1row[m];
        unsigned short v2 = i2row[m];
        z1[i] = sh1[m] + sh2[v1 & 0x7FF] - 10000.f * (float)(v1 >> 15);
        z2[i] = sh2[m] + sh1[v2 & 0x7FF] - 10000.f * (float)(v2 >> 15);
        mx1 = fmaxf(mx1, z1[i]);
        mx2 = fmaxf(mx2, z2[i]);
    }
    mx1 = warpRedMax(mx1);
    mx2 = warpRedMax(mx2);
    if (lane == 0) { red[wid] = mx1; red[wid + 8] = mx2; }
    __syncthreads();
    if (wid == 0) {
        float a = (lane < 8) ? red[lane] : -1e30f;
        float b = (lane < 8) ? red[lane + 8] : -1e30f;
        a = warpRedMax(a);
        b = warpRedMax(b);
        if (lane == 0) { red[16] = a; red[17] = b; }
    }
    __syncthreads();
    mx1 = red[16];
    mx2 = red[17];

    float sum1 = 0.f, sum2 = 0.f;
#pragma unroll
    for (int i = 0; i < 8; i++) {
        z1[i] = __expf(z1[i] - mx1);
        z2[i] = __expf(z2[i] - mx2);
        sum1 += z1[i];
        sum2 += z2[i];
    }
    sum1 = warpRedSum(sum1);
    sum2 = warpRedSum(sum2);
    __syncthreads();
    if (lane == 0) { red[wid] = sum1; red[wid + 8] = sum2; }
    __syncthreads();
    if (wid == 0) {
        float a = (lane < 8) ? red[lane] : 0.f;
        float b = (lane < 8) ? red[lane + 8] : 0.f;
        a = warpRedSum(a);
        b = warpRedSum(b);
        if (lane == 0) { red[16] = a; red[17] = b; }
    }
    __syncthreads();
    float inv1 = 1.f / red[16];
    float inv2 = 1.f / red[17];
#pragma unroll
    for (int i = 0; i < 8; i++) {
        int m = tid + i * 256;
        s1row[m] = __float2half_rn(z1[i] * inv1);
        s2row[m] = __float2half_rn(z2[i] * inv2);
    }
}

// ============================ stage 4: AV + concat (chunk-64 pipeline) ============================
__global__ __launch_bounds__(256, 2)
void av_mma_kernel(float* __restrict__ out)
{
    const int z = blockIdx.z, mat = z >> 3, h = z & 7;
    const int bm = blockIdx.y * 128;
    const __half* Ab = reinterpret_cast<const __half*>(mat ? g_S2 : g_S1);
    const __half* aP = Ab + ((long long)h * N_TOK + bm) * 4096;
    const __half* bV = g_VT + (long long)(mat * 512 + h * 64) * 2048;

    float acc[2][4][4];
#pragma unroll
    for (int a = 0; a < 2; a++)
#pragma unroll
        for (int b = 0; b < 4; b++)
#pragma unroll
            for (int c = 0; c < 4; c++) acc[a][b][c] = 0.f;

    gemm_av(aP, 4096, bV, 2048, 2048, acc);

    const int wid = threadIdx.x >> 5, lane = threadIdx.x & 31;
    const int g = lane >> 2, t = lane & 3;
    const int wm = (wid >> 1) * 32, wn = (wid & 1) * 32;
    const int cbase = mat * 512 + h * 64;
#pragma unroll
    for (int mi = 0; mi < 2; mi++) {
        int m0 = bm + wm + mi * 16 + g;
#pragma unroll
        for (int ni = 0; ni < 4; ni++) {
            int col = cbase + wn + ni * 8 + 2 * t;
            *(float2*)(out + (long long)m0 * 1024 + col) =
                make_float2(acc[mi][ni][0], acc[mi][ni][1]);
            *(float2*)(out + (long long)(m0 + 8) * 1024 + col) =
                make_float2(acc[mi][ni][2], acc[mi][ni][3]);
        }
    }
}

// ============================ launch ============================
extern "C" void kernel_launch(void* const* d_in, const int* in_sizes, int n_in,
                              void* d_out, int out_size)
{
    const float* x   = (const float*)d_in[0];
    const float* fst = (const float*)d_in[1];
    const float* sec = (const float*)d_in[2];
    const int*   n2c = (const int*)d_in[3];
    const int*   c2n = (const int*)d_in[4];
    const float* Wq1 = (const float*)d_in[5];
    const float* bq1 = (const float*)d_in[6];
    const float* Wk1 = (const float*)d_in[7];
    const float* bk1 = (const float*)d_in[8];
    const float* Wv1 = (const float*)d_in[9];
    const float* bv1 = (const float*)d_in[10];
    const float* Wq2 = (const float*)d_in[11];
    const float* bq2 = (const float*)d_in[12];
    const float* Wk2 = (const float*)d_in[13];
    const float* bk2 = (const float*)d_in[14];
    const float* Wv2 = (const float*)d_in[15];
    const float* bv2 = (const float*)d_in[16];
    float* out = (float*)d_out;

    static bool attr_set = false;
    if (!attr_set) {
        cudaFuncSetAttribute(proj_mma_kernel, cudaFuncAttributeMaxDynamicSharedMemorySize, 110592);
        cudaFuncSetAttribute(score_mma_kernel, cudaFuncAttributeMaxDynamicSharedMemorySize, 69632);
        cudaFuncSetAttribute(av_mma_kernel, cudaFuncAttributeMaxDynamicSharedMemorySize, 82944);
        attr_set = true;
    }

    // stage 0: fused pack + convx + convw (one launch, overlapped)
    stage0_kernel<<<12288, dim3(32, 8)>>>(c2n, n2c, fst, sec, x,
                                          Wq1, Wk1, Wq2, Wk2, Wv1, Wv2);

    // stage 1: projections (640 CTAs, chunk-64 3-stage pipeline, 1 barrier/chunk)
    proj_mma_kernel<<<dim3(40, 16), 256, 110592>>>(bq1, bk1, bv1, bq2, bk2, bv2);

    // stage 2: scores (4096 CTAs, single-shot K=128, zero compute barriers)
    score_mma_kernel<<<dim3(16, 16, 16), 256, 69632>>>();

    // stage 3: gathered dual softmax (h-fastest grid) -> fp16 probs, in place
    softmax_gather_kernel<<<dim3(8, 2048), 256>>>();

    // stage 4: AV + concat (256 CTAs, chunk-64 3-stage pipeline, 1 barrier/chunk)
    av_mma_kernel<<<dim3(1, 16, 16), 256, 82944>>>(out);
}

// round 15
// speedup vs baseline: 3.2065x; 1.0542x over previous
#include <cuda_runtime.h>
#include <cuda_bf16.h>
#include <cuda_fp16.h>
#include <cstdint>

#define N_TOK 2048
#define NN (8LL * 2048 * 2048)

__device__ __forceinline__ uint32_t smem_to_u32(const void* p) {
    uint32_t a;
    asm("{ .reg .u64 t; cvta.to.shared.u64 t, %1; cvt.u32.u64 %0, t; }" : "=r"(a) : "l"(p));
    return a;
}

__device__ __forceinline__ void ldmatrix_x4(uint32_t& r0, uint32_t& r1, uint32_t& r2,
                                            uint32_t& r3, uint32_t addr) {
    asm volatile("ldmatrix.sync.aligned.m8n8.x4.shared.b16 {%0,%1,%2,%3}, [%4];"
                 : "=r"(r0), "=r"(r1), "=r"(r2), "=r"(r3) : "r"(addr));
}

__device__ __forceinline__ void mma16816h(float c[4], const uint32_t a[4], const uint32_t b[2]) {
    asm volatile(
        "mma.sync.aligned.m16n8k16.row.col.f32.f16.f16.f32 "
        "{%0,%1,%2,%3}, {%4,%5,%6,%7}, {%8,%9}, {%0,%1,%2,%3};"
        : "+f"(c[0]), "+f"(c[1]), "+f"(c[2]), "+f"(c[3])
        : "r"(a[0]), "r"(a[1]), "r"(a[2]), "r"(a[3]), "r"(b[0]), "r"(b[1]));
}

#define CP_ASYNC_CG(smem_addr, gmem_ptr) \
    asm volatile("cp.async.cg.shared.global [%0], [%1], 16;" \
                 :: "r"(smem_addr), "l"(gmem_ptr))
#define CP_ASYNC_COMMIT() asm volatile("cp.async.commit_group;" ::: "memory")
#define CP_ASYNC_WAIT(n)  asm volatile("cp.async.wait_group %0;" :: "n"(n) : "memory")

// ============================ device scratch ============================
__device__ __align__(16) __half g_Xs[2048 * 1024];       // X single fp16
__device__ __align__(16) __half g_WT[5242880];           // Wᵀ single fp16: q1,k1,q2,k2 (1M) + v1,v2 (512K), [N,K]
__device__ __align__(16) __half g_Qs[2][2048 * 1024];    // Q (pre-scaled) single fp16 per mat
__device__ __align__(16) __half g_Ks[2][2048 * 1024];    // K single fp16 per mat
__device__ __align__(16) __half g_VT[1024 * 2048];       // V single fp16, rows: mat*512+vcol, cols: token
__device__ __align__(16) float g_S1[NN];   // rows of 2048 fp32-slots: fp16 scores then fp16 probs in first half
__device__ __align__(16) float g_S2[NN];
__device__ __align__(16) unsigned short g_I1[2048LL * 2048]; // c2n u16 | mask1<<15
__device__ __align__(16) unsigned short g_I2[2048LL * 2048]; // n2c u16 | mask2<<15

// ============================ fused stage-0 conversion kernel ============================
__global__ __launch_bounds__(256)
void stage0_kernel(const int* __restrict__ c2n, const int* __restrict__ n2c,
                   const float* __restrict__ G1, const float* __restrict__ G2,
                   const float* __restrict__ x,
                   const float* __restrict__ w0, const float* __restrict__ w1,
                   const float* __restrict__ w2, const float* __restrict__ w3,
                   const float* __restrict__ w4, const float* __restrict__ w5)
{
    const int bid = blockIdx.x;
    const int tx = threadIdx.x, ty = threadIdx.y;
    const int tid = ty * 32 + tx;

    if (bid < 4096) {
        __shared__ float t1[32][33];
        __shared__ float t2[32][33];
        const int bx = (bid & 63) * 32;   // n-tile
        const int by = (bid >> 6) * 32;   // m-tile
#pragma unroll
        for (int i = ty; i < 32; i += 8) {
            t1[i][tx] = G1[(long long)(by + i) * N_TOK + bx + tx];
            t2[i][tx] = G2[(long long)(by + i) * N_TOK + bx + tx];
        }
        __syncthreads();
#pragma unroll
        for (int i = ty; i < 32; i += 8) {
            int n = bx + i;
            int m = by + tx;
            long long o = (long long)n * N_TOK + m;
            unsigned short v1 = (unsigned short)c2n[o];
            unsigned short v2 = (unsigned short)n2c[o];
            if (t1[tx][i] == 0.f) v1 |= 0x8000;
            if (t2[tx][i] == 0.f) v2 |= 0x8000;
            g_I1[o] = v1;
            g_I2[o] = v2;
        }
    } else if (bid < 6144) {
        int i = ((bid - 4096) * 256 + tid) * 4;
        float4 v = *(const float4*)(x + i);
        __half h[4] = {__float2half_rn(v.x), __float2half_rn(v.y),
                       __float2half_rn(v.z), __float2half_rn(v.w)};
        *(uint2*)&g_Xs[i] = *(uint2*)h;
    } else {
        int idx = bid - 6144;
        int z = idx >> 10;
        int xy = idx & 1023;
        int bn = (xy & 31) * 32, bk = (xy >> 5) * 32;
        const float* W;
        int Ncols;
        long long base;
        switch (z) {
            case 0: W = w0; Ncols = 1024; base = 0; break;
            case 1: W = w1; Ncols = 1024; base = 1048576; break;
            case 2: W = w2; Ncols = 1024; base = 2097152; break;
            case 3: W = w3; Ncols = 1024; base = 3145728; break;
            case 4: W = w4; Ncols = 512;  base = 4194304; break;
            default:W = w5; Ncols = 512;  base = 4718592; break;
        }
        if (bn >= Ncols) return;
        __shared__ float t[32][33];
#pragma unroll
        for (int i = ty; i < 32; i += 8)
            t[i][tx] = W[(long long)(bk + i) * Ncols + bn + tx];
        __syncthreads();
#pragma unroll
        for (int i = ty; i < 32; i += 8) {
            long long o = base + (long long)(bn + i) * 1024 + bk + tx;
            g_WT[o] = __float2half_rn(t[tx][i]);
        }
    }
}

// ============================ 3-stage chunk-64 GEMM body (proj), 1 barrier/chunk ============================
__device__ __forceinline__ void gemm_c64(
    const __half* __restrict__ aS, int lda,
    const __half* __restrict__ bS, int ldb,
    int K, float acc[4][4][4])
{
    constexpr int OFF_B = 18432;
    constexpr int STG = 36864;
    extern __shared__ __align__(16) char sm[];
    const uint32_t smb = smem_to_u32(sm);
    const int tid = threadIdx.x;
    const int wid = tid >> 5, lane = tid & 31;
    const int wm = (wid >> 2) * 64;
    const int wn = (wid & 3) * 32;
    const int a_row = wm + (lane & 7) + ((lane >> 3) & 1) * 8;
    const int a_cofs = (lane >> 4) * 8;
    const int b_row = wn + (lane & 7) + ((lane >> 4) & 1) * 8;
    const int b_cofs = ((lane >> 3) & 1) * 8;

    const int NC = K >> 6;

    auto issue_stage = [&](int ic) {
        const uint32_t sb = smb + (uint32_t)(ic % 3) * STG;
        const int k0 = ic * 64;
#pragma unroll
        for (int i = 0; i < 4; i++) {
            int idx = i * 256 + tid;
            int r = idx >> 3, c8 = idx & 7;
            uint32_t so = (uint32_t)(r * 144 + c8 * 16);
            CP_ASYNC_CG(sb + so, aS + (long long)r * lda + k0 + c8 * 8);
            CP_ASYNC_CG(sb + OFF_B + so, bS + (long long)r * ldb + k0 + c8 * 8);
        }
        CP_ASYNC_COMMIT();
    };

    issue_stage(0);
    if (NC > 1) issue_stage(1);
    for (int ic = 0; ic < NC; ic++) {
        if (ic + 1 < NC) { CP_ASYNC_WAIT(1); }
        else             { CP_ASYNC_WAIT(0); }
        __syncthreads();
        if (ic + 2 < NC) issue_stage(ic + 2);
        const uint32_t sb = smb + (uint32_t)(ic % 3) * STG;
#pragma unroll
        for (int ks = 0; ks < 64; ks += 16) {
            uint32_t aq[4][4], bb[4][2];
#pragma unroll
            for (int mi = 0; mi < 4; mi++) {
                uint32_t off = (uint32_t)(((a_row + mi * 16) * 72 + ks + a_cofs) * 2);
                ldmatrix_x4(aq[mi][0], aq[mi][1], aq[mi][2], aq[mi][3], sb + off);
            }
#pragma unroll
            for (int nj = 0; nj < 2; nj++) {
                uint32_t off = (uint32_t)(((b_row + nj * 16) * 72 + ks + b_cofs) * 2);
                ldmatrix_x4(bb[nj * 2][0], bb[nj * 2][1], bb[nj * 2 + 1][0], bb[nj * 2 + 1][1],
                            sb + OFF_B + off);
            }
#pragma unroll
            for (int mi = 0; mi < 4; mi++)
#pragma unroll
                for (int ni = 0; ni < 4; ni++)
                    mma16816h(acc[mi][ni], aq[mi], bb[ni]);
        }
    }
}

// ============================ 3-stage chunk-64 AV GEMM body, 1 barrier/chunk ============================
__device__ __forceinline__ void gemm_av(
    const __half* __restrict__ aP, int lda,
    const __half* __restrict__ bS, int ldb,
    int K, float acc[2][4][4])
{
    constexpr int OFF_B = 18432;
    constexpr int STG = 27648;
    extern __shared__ __align__(16) char sm[];
    const uint32_t smb = smem_to_u32(sm);
    const int tid = threadIdx.x;
    const int wid = tid >> 5, lane = tid & 31;
    const int wm = (wid >> 1) * 32;
    const int wn = (wid & 1) * 32;
    const int a_row = wm + (lane & 7) + ((lane >> 3) & 1) * 8;
    const int a_cofs = (lane >> 4) * 8;
    const int b_row = wn + (lane & 7) + ((lane >> 4) & 1) * 8;
    const int b_cofs = ((lane >> 3) & 1) * 8;

    const int NC = K >> 6;

    auto issue_stage = [&](int ic) {
        const uint32_t sb = smb + (uint32_t)(ic % 3) * STG;
        const int k0 = ic * 64;
#pragma unroll
        for (int i = 0; i < 4; i++) {
            int idx = i * 256 + tid;
            int r = idx >> 3, c8 = idx & 7;
            uint32_t so = (uint32_t)(r * 144 + c8 * 16);
            CP_ASYNC_CG(sb + so, aP + (long long)r * lda + k0 + c8 * 8);
        }
#pragma unroll
        for (int i = 0; i < 2; i++) {
            int idx = i * 256 + tid;
            int r = idx >> 3, c8 = idx & 7;
            uint32_t so = (uint32_t)(r * 144 + c8 * 16);
            CP_ASYNC_CG(sb + OFF_B + so, bS + (long long)r * ldb + k0 + c8 * 8);
        }
        CP_ASYNC_COMMIT();
    };

    issue_stage(0);
    if (NC > 1) issue_stage(1);
    for (int ic = 0; ic < NC; ic++) {
        if (ic + 1 < NC) { CP_ASYNC_WAIT(1); }
        else             { CP_ASYNC_WAIT(0); }
        __syncthreads();
        if (ic + 2 < NC) issue_stage(ic + 2);
        const uint32_t sb = smb + (uint32_t)(ic % 3) * STG;
#pragma unroll
        for (int ks = 0; ks < 64; ks += 16) {
            uint32_t ap[2][4], bb[4][2];
#pragma unroll
            for (int mi = 0; mi < 2; mi++) {
                uint32_t off = (uint32_t)(((a_row + mi * 16) * 72 + ks + a_cofs) * 2);
                ldmatrix_x4(ap[mi][0], ap[mi][1], ap[mi][2], ap[mi][3], sb + off);
            }
#pragma unroll
            for (int nj = 0; nj < 2; nj++) {
                uint32_t off = (uint32_t)(((b_row + nj * 16) * 72 + ks + b_cofs) * 2);
                ldmatrix_x4(bb[nj * 2][0], bb[nj * 2][1], bb[nj * 2 + 1][0], bb[nj * 2 + 1][1],
                            sb + OFF_B + off);
            }
#pragma unroll
            for (int mi = 0; mi < 2; mi++)
#pragma unroll
                for (int ni = 0; ni < 4; ni++)
                    mma16816h(acc[mi][ni], ap[mi], bb[ni]);
        }
    }
}

// ============================ stage 1: projections (chunk-64 pipeline) ============================
__global__ __launch_bounds__(256, 2)
void proj_mma_kernel(const float* __restrict__ bq1, const float* __restrict__ bk1,
                     const float* __restrict__ bv1, const float* __restrict__ bq2,
                     const float* __restrict__ bk2, const float* __restrict__ bv2)
{
    const float scale = 0.08838834764831845f;  // 1/sqrt(128), folded into Q
    const int cb = blockIdx.x;
    const int bm = blockIdx.y * 128;
    const __half* bW;
    const float* bias;
    int r, bnl;
    if (cb < 32) {
        r = cb >> 3; bnl = (cb & 7) * 128;
        bW = g_WT + (long long)r * 1048576 + (long long)bnl * 1024;
        bias = (r == 0) ? bq1 : (r == 1) ? bk1 : (r == 2) ? bq2 : bk2;
    } else {
        r = (cb - 32) >> 2; bnl = ((cb - 32) & 3) * 128;
        bW = g_WT + 4194304LL + (long long)r * 524288 + (long long)bnl * 1024;
        bias = r ? bv2 : bv1;
    }
    float acc[4][4][4];
#pragma unroll
    for (int a = 0; a < 4; a++)
#pragma unroll
        for (int b = 0; b < 4; b++)
#pragma unroll
            for (int c = 0; c < 4; c++) acc[a][b][c] = 0.f;

    gemm_c64(g_Xs + (long long)bm * 1024, 1024, bW, 1024, 1024, acc);

    const int wid = threadIdx.x >> 5, lane = threadIdx.x & 31;
    const int g = lane >> 2, t = lane & 3;
    const int wm = (wid >> 2) * 64, wn = (wid & 3) * 32;
    const bool isQ = (cb < 32) && ((r & 1) == 0);
    const float outscale = isQ ? scale : 1.f;
#pragma unroll
    for (int mi = 0; mi < 4; mi++) {
        int m0 = bm + wm + mi * 16 + g;
#pragma unroll
        for (int ni = 0; ni < 4; ni++) {
            int col = bnl + wn + ni * 8 + 2 * t;
            float b0 = bias[col], b1 = bias[col + 1];
            float v00 = (acc[mi][ni][0] + b0) * outscale, v01 = (acc[mi][ni][1] + b1) * outscale;
            float v10 = (acc[mi][ni][2] + b0) * outscale, v11 = (acc[mi][ni][3] + b1) * outscale;
            __half h00 = __float2half_rn(v00), h01 = __float2half_rn(v01);
            __half h10 = __float2half_rn(v10), h11 = __float2half_rn(v11);
            if (cb < 32) {
                int mat = r >> 1;
                __half* dst = (r & 1) ? g_Ks[mat] : g_Qs[mat];
                long long o0 = (long long)m0 * 1024 + col;
                long long o1 = (long long)(m0 + 8) * 1024 + col;
                *(__half2*)&dst[o0] = __halves2half2(h00, h01);
                *(__half2*)&dst[o1] = __halves2half2(h10, h11);
            } else {
                int c0 = r * 512 + col, c1 = c0 + 1;
                g_VT[(long long)c0 * 2048 + m0] = h00;
                g_VT[(long long)c1 * 2048 + m0] = h01;
                g_VT[(long long)c0 * 2048 + m0 + 8] = h10;
                g_VT[(long long)c1 * 2048 + m0 + 8] = h11;
            }
        }
    }
}

// ============================ stage 2: scores (single-shot K=128) ============================
__global__ __launch_bounds__(256, 2)
void score_mma_kernel()
{
    constexpr int OFF_B = 34816;
    extern __shared__ __align__(16) char sm[];
    const uint32_t smb = smem_to_u32(sm);
    const int z = blockIdx.z, mat = z >> 3, h = z & 7;
    const int bm = blockIdx.y * 128, bn = blockIdx.x * 128;
    const __half* q = g_Qs[mat] + (long long)bm * 1024 + h * 128;
    const __half* k = g_Ks[mat] + (long long)bn * 1024 + h * 128;
    const int tid = threadIdx.x;

#pragma unroll
    for (int i = 0; i < 8; i++) {
        int idx = i * 256 + tid;
        int r = idx >> 4, c16 = idx & 15;
        uint32_t so = (uint32_t)(r * 272 + c16 * 16);
        CP_ASYNC_CG(smb + so, q + (long long)r * 1024 + c16 * 8);
        CP_ASYNC_CG(smb + OFF_B + so, k + (long long)r * 1024 + c16 * 8);
    }
    CP_ASYNC_COMMIT();

    float acc[4][4][4];
#pragma unroll
    for (int a = 0; a < 4; a++)
#pragma unroll
        for (int b = 0; b < 4; b++)
#pragma unroll
            for (int c = 0; c < 4; c++) acc[a][b][c] = 0.f;

    const int wid = tid >> 5, lane = tid & 31;
    const int wm = (wid >> 2) * 64;
    const int wn = (wid & 3) * 32;
    const int a_row = wm + (lane & 7) + ((lane >> 3) & 1) * 8;
    const int a_cofs = (lane >> 4) * 8;
    const int b_row = wn + (lane & 7) + ((lane >> 4) & 1) * 8;
    const int b_cofs = ((lane >> 3) & 1) * 8;

    CP_ASYNC_WAIT(0);
    __syncthreads();

#pragma unroll
    for (int ks = 0; ks < 128; ks += 16) {
        uint32_t aq[4][4], bb[4][2];
#pragma unroll
        for (int mi = 0; mi < 4; mi++) {
            uint32_t off = (uint32_t)(((a_row + mi * 16) * 136 + ks + a_cofs) * 2);
            ldmatrix_x4(aq[mi][0], aq[mi][1], aq[mi][2], aq[mi][3], smb + off);
        }
#pragma unroll
        for (int nj = 0; nj < 2; nj++) {
            uint32_t off = (uint32_t)(((b_row + nj * 16) * 136 + ks + b_cofs) * 2);
            ldmatrix_x4(bb[nj * 2][0], bb[nj * 2][1], bb[nj * 2 + 1][0], bb[nj * 2 + 1][1],
                        smb + OFF_B + off);
        }
#pragma unroll
        for (int mi = 0; mi < 4; mi++)
#pragma unroll
            for (int ni = 0; ni < 4; ni++)
                mma16816h(acc[mi][ni], aq[mi], bb[ni]);
    }

    __half* S = reinterpret_cast<__half*>((mat ? g_S2 : g_S1));
    const int g = lane >> 2, t = lane & 3;
    const long long hbase = (long long)h * N_TOK * 4096;
#pragma unroll
    for (int mi = 0; mi < 4; mi++) {
        int m0 = bm + wm + mi * 16 + g;
#pragma unroll
        for (int ni = 0; ni < 4; ni++) {
            int n0 = bn + wn + ni * 8 + 2 * t;
            *(__half2*)&S[hbase + (long long)m0 * 4096 + n0] =
                __halves2half2(__float2half_rn(acc[mi][ni][0]),
                               __float2half_rn(acc[mi][ni][1]));
            *(__half2*)&S[hbase + (long long)(m0 + 8) * 4096 + n0] =
                __halves2half2(__float2half_rn(acc[mi][ni][2]),
                               __float2half_rn(acc[mi][ni][3]));
        }
    }
}

// ============================ stage 3: dual gathered softmax (register-direct) ============================
__device__ __forceinline__ float warpRedMax(float v) {
#pragma unroll
    for (int o = 16; o > 0; o >>= 1) v = fmaxf(v, __shfl_xor_sync(0xffffffffu, v, o));
    return v;
}
__device__ __forceinline__ float warpRedSum(float v) {
#pragma unroll
    for (int o = 16; o > 0; o >>= 1) v += __shfl_xor_sync(0xffffffffu, v, o);
    return v;
}

// grid (8, 2048). Each thread owns contiguous elements [tid*8, tid*8+8):
// direct terms live in registers; smem used only for the cross-row gathers.
__global__ __launch_bounds__(256)
void softmax_gather_kernel()
{
    const int h = blockIdx.x;
    const int n = blockIdx.y;
    __half* s1row = reinterpret_cast<__half*>(g_S1) + ((long long)h * N_TOK + n) * 4096;
    __half* s2row = reinterpret_cast<__half*>(g_S2) + ((long long)h * N_TOK + n) * 4096;
    __shared__ float sh1[N_TOK];
    __shared__ float sh2[N_TOK];
    __shared__ float red[32];
    const int tid = threadIdx.x;
    const int lane = tid & 31, wid = tid >> 5;
    const int mb = tid * 8;

    float f1[8], f2[8];
    {
        uint4 v1 = *(const uint4*)(s1row + mb);
        uint4 v2 = *(const uint4*)(s2row + mb);
        const __half2* p1 = (const __half2*)&v1;
        const __half2* p2 = (const __half2*)&v2;
#pragma unroll
        for (int j = 0; j < 4; j++) {
            float2 a = __half22float2(p1[j]);
            float2 b = __half22float2(p2[j]);
            f1[2 * j] = a.x; f1[2 * j + 1] = a.y;
            f2[2 * j] = b.x; f2[2 * j + 1] = b.y;
        }
#pragma unroll
        for (int j = 0; j < 2; j++) {
            *(float4*)&sh1[mb + j * 4] =
                make_float4(f1[4 * j], f1[4 * j + 1], f1[4 * j + 2], f1[4 * j + 3]);
            *(float4*)&sh2[mb + j * 4] =
                make_float4(f2[4 * j], f2[4 * j + 1], f2[4 * j + 2], f2[4 * j + 3]);
        }
    }
    __syncthreads();

    unsigned short i1[8], i2[8];
    *(uint4*)i1 = *(const uint4*)(g_I1 + (long long)n * N_TOK + mb);
    *(uint4*)i2 = *(const uint4*)(g_I2 + (long long)n * N_TOK + mb);

    float z1[8], z2[8];
    float mx1 = -1e30f, mx2 = -1e30f;
#pragma unroll
    for (int i = 0; i < 8; i++) {
        z1[i] = f1[i] + sh2[i1[i] & 0x7FF] - 10000.f * (float)(i1[i] >> 15);
        z2[i] = f2[i] + sh1[i2[i] & 0x7FF] - 10000.f * (float)(i2[i] >> 15);
        mx1 = fmaxf(mx1, z1[i]);
        mx2 = fmaxf(mx2, z2[i]);
    }
    mx1 = warpRedMax(mx1);
    mx2 = warpRedMax(mx2);
    if (lane == 0) { red[wid] = mx1; red[wid + 8] = mx2; }
    __syncthreads();
    if (wid == 0) {
        float a = (lane < 8) ? red[lane] : -1e30f;
        float b = (lane < 8) ? red[lane + 8] : -1e30f;
        a = warpRedMax(a);
        b = warpRedMax(b);
        if (lane == 0) { red[16] = a; red[17] = b; }
    }
    __syncthreads();
    mx1 = red[16];
    mx2 = red[17];

    float sum1 = 0.f, sum2 = 0.f;
#pragma unroll
    for (int i = 0; i < 8; i++) {
        z1[i] = __expf(z1[i] - mx1);
        z2[i] = __expf(z2[i] - mx2);
        sum1 += z1[i];
        sum2 += z2[i];
    }
    sum1 = warpRedSum(sum1);
    sum2 = warpRedSum(sum2);
    __syncthreads();
    if (lane == 0) { red[wid] = sum1; red[wid + 8] = sum2; }
    __syncthreads();
    if (wid == 0) {
        float a = (lane < 8) ? red[lane] : 0.f;
        float b = (lane < 8) ? red[lane + 8] : 0.f;
        a = warpRedSum(a);
        b = warpRedSum(b);
        if (lane == 0) { red[16] = a; red[17] = b; }
    }
    __syncthreads();
    const float inv1 = 1.f / red[16];
    const float inv2 = 1.f / red[17];

    __half o1[8], o2[8];
#pragma unroll
    for (int i = 0; i < 8; i++) {
        o1[i] = __float2half_rn(z1[i] * inv1);
        o2[i] = __float2half_rn(z2[i] * inv2);
    }
    *(uint4*)(s1row + mb) = *(uint4*)o1;
    *(uint4*)(s2row + mb) = *(uint4*)o2;
}

// ============================ stage 4: AV + concat (chunk-64 pipeline) ============================
__global__ __launch_bounds__(256, 2)
void av_mma_kernel(float* __restrict__ out)
{
    const int z = blockIdx.z, mat = z >> 3, h = z & 7;
    const int bm = blockIdx.y * 128;
    const __half* Ab = reinterpret_cast<const __half*>(mat ? g_S2 : g_S1);
    const __half* aP = Ab + ((long long)h * N_TOK + bm) * 4096;
    const __half* bV = g_VT + (long long)(mat * 512 + h * 64) * 2048;

    float acc[2][4][4];
#pragma unroll
    for (int a = 0; a < 2; a++)
#pragma unroll
        for (int b = 0; b < 4; b++)
#pragma unroll
            for (int c = 0; c < 4; c++) acc[a][b][c] = 0.f;

    gemm_av(aP, 4096, bV, 2048, 2048, acc);

    const int wid = threadIdx.x >> 5, lane = threadIdx.x & 31;
    const int g = lane >> 2, t = lane & 3;
    const int wm = (wid >> 1) * 32, wn = (wid & 1) * 32;
    const int cbase = mat * 512 + h * 64;
#pragma unroll
    for (int mi = 0; mi < 2; mi++) {
        int m0 = bm + wm + mi * 16 + g;
#pragma unroll
        for (int ni = 0; ni < 4; ni++) {
            int col = cbase + wn + ni * 8 + 2 * t;
            *(float2*)(out + (long long)m0 * 1024 + col) =
                make_float2(acc[mi][ni][0], acc[mi][ni][1]);
            *(float2*)(out + (long long)(m0 + 8) * 1024 + col) =
                make_float2(acc[mi][ni][2], acc[mi][ni][3]);
        }
    }
}

// ============================ launch ============================
extern "C" void kernel_launch(void* const* d_in, const int* in_sizes, int n_in,
                              void* d_out, int out_size)
{
    const float* x   = (const float*)d_in[0];
    const float* fst = (const float*)d_in[1];
    const float* sec = (const float*)d_in[2];
    const int*   n2c = (const int*)d_in[3];
    const int*   c2n = (const int*)d_in[4];
    const float* Wq1 = (const float*)d_in[5];
    const float* bq1 = (const float*)d_in[6];
    const float* Wk1 = (const float*)d_in[7];
    const float* bk1 = (const float*)d_in[8];
    const float* Wv1 = (const float*)d_in[9];
    const float* bv1 = (const float*)d_in[10];
    const float* Wq2 = (const float*)d_in[11];
    const float* bq2 = (const float*)d_in[12];
    const float* Wk2 = (const float*)d_in[13];
    const float* bk2 = (const float*)d_in[14];
    const float* Wv2 = (const float*)d_in[15];
    const float* bv2 = (const float*)d_in[16];
    float* out = (float*)d_out;

    static bool attr_set = false;
    if (!attr_set) {
        cudaFuncSetAttribute(proj_mma_kernel, cudaFuncAttributeMaxDynamicSharedMemorySize, 110592);
        cudaFuncSetAttribute(score_mma_kernel, cudaFuncAttributeMaxDynamicSharedMemorySize, 69632);
        cudaFuncSetAttribute(av_mma_kernel, cudaFuncAttributeMaxDynamicSharedMemorySize, 82944);
        attr_set = true;
    }

    // stage 0: fused pack + convx + convw (one launch, overlapped)
    stage0_kernel<<<12288, dim3(32, 8)>>>(c2n, n2c, fst, sec, x,
                                          Wq1, Wk1, Wq2, Wk2, Wv1, Wv2);

    // stage 1: projections (640 CTAs, chunk-64 3-stage pipeline)
    proj_mma_kernel<<<dim3(40, 16), 256, 110592>>>(bq1, bk1, bv1, bq2, bk2, bv2);

    // stage 2: scores (4096 CTAs, single-shot K=128, zero compute barriers)
    score_mma_kernel<<<dim3(16, 16, 16), 256, 69632>>>();

    // stage 3: gathered dual softmax (register-direct, vectorized I/O)
    softmax_gather_kernel<<<dim3(8, 2048), 256>>>();

    // stage 4: AV + concat (256 CTAs, chunk-64 3-stage pipeline)
    av_mma_kernel<<<dim3(1, 16, 16), 256, 82944>>>(out);
}